// round 2
// baseline (speedup 1.0000x reference)
#include <cuda_runtime.h>
#include <math.h>

// ---------------- problem constants ----------------
#define TT 2048
#define BB 8
#define DD 128
#define HH 4
#define NTOK (BB*TT)          // 16384
#define SCALE 0.17677669529663687f   // 1/sqrt(32)
#define LAMBDA_INIT 0.8f
#define LN_EPS 1e-5f

// banded attention config
#define W_MAX 80              // max half-bandwidth (8*sigma_noise = 80)
#define QT 32                 // queries per block
#define QW 2                  // queries per warp
#define KROWS (QT + 2*W_MAX + 1)   // 193 rows of K/V in smem
#define KLD 68                // padded K row stride (floats), float4-aligned

// ---------------- scratch ----------------
__device__ float g_xn[NTOK*DD];        // layernormed tokens   (8 MB)
__device__ float g_y [NTOK*768];       // qkv projections      (48 MB)  [q|k|v] each 256
__device__ float g_ho[NTOK*256];       // per-head outputs     (16 MB)

__device__ __forceinline__ float dot4(float4 a, float4 b) {
    return a.x*b.x + a.y*b.y + a.z*b.z + a.w*b.w;
}
__device__ __forceinline__ float warpmax(float v) {
    #pragma unroll
    for (int o = 16; o; o >>= 1) v = fmaxf(v, __shfl_xor_sync(0xffffffffu, v, o));
    return v;
}
__device__ __forceinline__ float warpsum(float v) {
    #pragma unroll
    for (int o = 16; o; o >>= 1) v += __shfl_xor_sync(0xffffffffu, v, o);
    return v;
}

// ---------------- stage 1: layernorm ----------------
__global__ void ln_kernel(const float* __restrict__ tok,
                          const float* __restrict__ w,
                          const float* __restrict__ b) {
    int t = blockIdx.x * 8 + (threadIdx.x >> 5);
    int lane = threadIdx.x & 31;
    const float4* src = (const float4*)(tok + (size_t)t * DD);
    float4 x = src[lane];
    float s  = x.x + x.y + x.z + x.w;
    float sq = x.x*x.x + x.y*x.y + x.z*x.z + x.w*x.w;
    s  = warpsum(s);
    sq = warpsum(sq);
    float mu  = s * (1.0f/128.0f);
    float var = sq * (1.0f/128.0f) - mu*mu;
    float rs  = rsqrtf(var + LN_EPS);
    float4 w4 = ((const float4*)w)[lane];
    float4 b4 = ((const float4*)b)[lane];
    float4 o;
    o.x = (x.x - mu) * rs * w4.x + b4.x;
    o.y = (x.y - mu) * rs * w4.y + b4.y;
    o.z = (x.z - mu) * rs * w4.z + b4.z;
    o.w = (x.w - mu) * rs * w4.w + b4.w;
    ((float4*)(g_xn + (size_t)t * DD))[lane] = o;
}

// ---------------- stage 2: QKV gemm (16384x128 @ 128x768) ----------------
__global__ void gemm_qkv(const float* __restrict__ wq,
                         const float* __restrict__ wk,
                         const float* __restrict__ wv) {
    __shared__ float As[16][64];
    __shared__ float Bs[16][64];
    int tx = threadIdx.x & 15, ty = threadIdx.x >> 4;
    int m0 = blockIdx.x * 64;
    int n0 = blockIdx.y * 64;
    const float* Bsrc; int nb;
    if (n0 < 256)      { Bsrc = wq; nb = n0; }
    else if (n0 < 512) { Bsrc = wk; nb = n0 - 256; }
    else               { Bsrc = wv; nb = n0 - 512; }

    int la_r = threadIdx.x >> 2;          // 0..63
    int la_c = (threadIdx.x & 3) * 4;     // 0,4,8,12
    int lb_r = threadIdx.x >> 4;          // 0..15
    int lb_c = (threadIdx.x & 15) * 4;    // 0..60

    float acc[4][4];
    #pragma unroll
    for (int i = 0; i < 4; i++)
        #pragma unroll
        for (int j = 0; j < 4; j++) acc[i][j] = 0.0f;

    for (int k0 = 0; k0 < 128; k0 += 16) {
        float4 a4 = *(const float4*)&g_xn[(size_t)(m0 + la_r)*128 + k0 + la_c];
        float4 b4 = *(const float4*)&Bsrc[(size_t)(k0 + lb_r)*256 + nb + lb_c];
        As[la_c+0][la_r] = a4.x;
        As[la_c+1][la_r] = a4.y;
        As[la_c+2][la_r] = a4.z;
        As[la_c+3][la_r] = a4.w;
        *(float4*)&Bs[lb_r][lb_c] = b4;
        __syncthreads();
        #pragma unroll
        for (int k = 0; k < 16; k++) {
            float4 a = *(const float4*)&As[k][ty*4];
            float4 b = *(const float4*)&Bs[k][tx*4];
            acc[0][0] += a.x*b.x; acc[0][1] += a.x*b.y; acc[0][2] += a.x*b.z; acc[0][3] += a.x*b.w;
            acc[1][0] += a.y*b.x; acc[1][1] += a.y*b.y; acc[1][2] += a.y*b.z; acc[1][3] += a.y*b.w;
            acc[2][0] += a.z*b.x; acc[2][1] += a.z*b.y; acc[2][2] += a.z*b.z; acc[2][3] += a.z*b.w;
            acc[3][0] += a.w*b.x; acc[3][1] += a.w*b.y; acc[3][2] += a.w*b.z; acc[3][3] += a.w*b.w;
        }
        __syncthreads();
    }
    #pragma unroll
    for (int i = 0; i < 4; i++) {
        float4 r = make_float4(acc[i][0], acc[i][1], acc[i][2], acc[i][3]);
        *(float4*)&g_y[(size_t)(m0 + ty*4 + i)*768 + n0 + tx*4] = r;
    }
}

// ---------------- stage 3: banded differential attention ----------------
__global__ void __launch_bounds__(512, 1)
attn_kernel(const float* __restrict__ lq1, const float* __restrict__ lk1,
            const float* __restrict__ lq2, const float* __restrict__ lk2,
            const float* __restrict__ sigS, const float* __restrict__ sigN,
            const float* __restrict__ hnw,  const float* __restrict__ hnb) {
    extern __shared__ float sm[];
    float* Ksm = sm;                      // KROWS * KLD
    float* Vsm = Ksm + KROWS*KLD;         // KROWS * 64 (interleaved (d, d+32) pairs)
    float* Qsm = Vsm + KROWS*64;          // QT * 64
    __shared__ float s_lam;

    int tid = threadIdx.x;
    int bh  = blockIdx.y;
    int b   = bh >> 2;      // / HH
    int h   = bh & 3;       // % HH
    int q0  = blockIdx.x * QT;

    float ss = fmaxf(sigS[0], 1.0f), sn = fmaxf(sigN[0], 1.0f);
    float c1 = -0.5f / (ss*ss);
    float c2 = -0.5f / (sn*sn);
    int Wn = (int)ceilf(8.0f * fmaxf(ss, sn));
    if (Wn > W_MAX) Wn = W_MAX;

    int blo = q0 - Wn;          if (blo < 0) blo = 0;
    int bhi = q0 + QT - 1 + Wn; if (bhi > TT-1) bhi = TT-1;
    int nrows = bhi - blo + 1;

    const float* ybase = g_y + (size_t)(b*TT) * 768;

    // cooperative K/V band load
    for (int idx = tid; idx < nrows*64; idx += 512) {
        int r = idx >> 6, d = idx & 63;
        const float* row = ybase + (size_t)(blo + r)*768 + h*64;
        Ksm[r*KLD + d] = row[256 + d];
        float v = row[512 + d];
        int dd = (d < 32) ? (2*d) : (2*(d-32) + 1);
        Vsm[r*64 + dd] = v;
    }
    // Q tile
    for (int idx = tid; idx < QT*64; idx += 512) {
        int r = idx >> 6, d = idx & 63;
        Qsm[idx] = ybase[(size_t)(q0 + r)*768 + h*64 + d];
    }
    if (tid == 0) {
        float d1 = 0.0f, d2 = 0.0f;
        #pragma unroll
        for (int i = 0; i < 32; i++) { d1 += lq1[i]*lk1[i]; d2 += lq2[i]*lk2[i]; }
        s_lam = __expf(d1) - __expf(d2) + LAMBDA_INIT;
    }
    __syncthreads();
    float lam = s_lam;

    int w = tid >> 5, lane = tid & 31;
    int i0 = q0 + w*QW;                          // queries i0, i0+1
    int jlo = i0 - Wn;           if (jlo < blo) jlo = blo;
    int jhi = i0 + QW - 1 + Wn;  if (jhi > bhi) jhi = bhi;

    const float4* Q0 = (const float4*)&Qsm[(w*QW + 0)*64];
    const float4* Q1 = (const float4*)&Qsm[(w*QW + 1)*64];

    float m1a = -1e30f, m1b = -1e30f, m2a = -1e30f, m2b = -1e30f;
    float l1a = 0, l1b = 0, l2a = 0, l2b = 0;
    float2 o1a = {0,0}, o1b = {0,0}, o2a = {0,0}, o2b = {0,0};

    for (int jc = jlo; jc <= jhi; jc += 32) {
        int j = jc + lane;
        bool valid = (j <= jhi);
        float s1A = 0, s1B = 0, s2A = 0, s2B = 0;
        if (valid) {
            const float4* kr = (const float4*)(Ksm + (j - blo)*KLD);
            #pragma unroll
            for (int dc = 0; dc < 8; dc++) {
                float4 k4 = kr[dc];
                s1A += dot4(k4, Q0[dc]);
                s1B += dot4(k4, Q1[dc]);
            }
            #pragma unroll
            for (int dc = 8; dc < 16; dc++) {
                float4 k4 = kr[dc];
                s2A += dot4(k4, Q0[dc]);
                s2B += dot4(k4, Q1[dc]);
            }
        }
        float relA = (float)(j - i0);
        float relB = relA - 1.0f;
        float ra2 = relA*relA, rb2 = relB*relB;
        s1A = valid ? (s1A*SCALE + ra2*c1) : -1e30f;
        s1B = valid ? (s1B*SCALE + rb2*c1) : -1e30f;
        s2A = valid ? (s2A*SCALE + ra2*c2) : -1e30f;
        s2B = valid ? (s2B*SCALE + rb2*c2) : -1e30f;

        float n1a = fmaxf(m1a, warpmax(s1A));
        float n1b = fmaxf(m1b, warpmax(s1B));
        float n2a = fmaxf(m2a, warpmax(s2A));
        float n2b = fmaxf(m2b, warpmax(s2B));
        float r1a = __expf(m1a - n1a), r1b = __expf(m1b - n1b);
        float r2a = __expf(m2a - n2a), r2b = __expf(m2b - n2b);
        m1a = n1a; m1b = n1b; m2a = n2a; m2b = n2b;

        float e1a = __expf(s1A - n1a);
        float e1b = __expf(s1B - n1b);
        float e2a = __expf(s2A - n2a);
        float e2b = __expf(s2B - n2b);

        l1a = l1a*r1a + warpsum(e1a);
        l1b = l1b*r1b + warpsum(e1b);
        l2a = l2a*r2a + warpsum(e2a);
        l2b = l2b*r2b + warpsum(e2b);

        o1a.x *= r1a; o1a.y *= r1a;
        o1b.x *= r1b; o1b.y *= r1b;
        o2a.x *= r2a; o2a.y *= r2a;
        o2b.x *= r2b; o2b.y *= r2b;

        int cnt = jhi - jc + 1; if (cnt > 32) cnt = 32;
        const float2* vb = (const float2*)(Vsm + (jc - blo)*64);
        #pragma unroll 4
        for (int jj = 0; jj < cnt; jj++) {
            float2 v = vb[jj*32 + lane];
            float p1a = __shfl_sync(0xffffffffu, e1a, jj);
            float p1b = __shfl_sync(0xffffffffu, e1b, jj);
            float p2a = __shfl_sync(0xffffffffu, e2a, jj);
            float p2b = __shfl_sync(0xffffffffu, e2b, jj);
            o1a.x += p1a*v.x; o1a.y += p1a*v.y;
            o1b.x += p1b*v.x; o1b.y += p1b*v.y;
            o2a.x += p2a*v.x; o2a.y += p2a*v.y;
            o2b.x += p2b*v.x; o2b.y += p2b*v.y;
        }
    }

    // epilogue: combine, per-head layernorm(64), *(1-lambda_init)
    float hw0 = hnw[lane], hw1 = hnw[lane+32];
    float hb0 = hnb[lane], hb1 = hnb[lane+32];
    float post = 1.0f - LAMBDA_INIT;
    #pragma unroll
    for (int qq = 0; qq < 2; qq++) {
        float il1 = 1.0f / (qq ? l1b : l1a);
        float il2 = lam  / (qq ? l2b : l2a);
        float2 u1 = qq ? o1b : o1a;
        float2 u2 = qq ? o2b : o2a;
        float ox = u1.x*il1 - u2.x*il2;
        float oy = u1.y*il1 - u2.y*il2;
        float s  = warpsum(ox + oy);
        float sq = warpsum(ox*ox + oy*oy);
        float mu  = s * (1.0f/64.0f);
        float var = sq * (1.0f/64.0f) - mu*mu;
        float rs  = rsqrtf(var + LN_EPS);
        float y0 = ((ox - mu)*rs*hw0 + hb0) * post;
        float y1 = ((oy - mu)*rs*hw1 + hb1) * post;
        int i = i0 + qq;
        float* dst = g_ho + (size_t)(b*TT + i)*256 + h*64;
        dst[lane]      = y0;
        dst[lane + 32] = y1;
    }
}

// ---------------- stage 4: output gemm + residual ----------------
__global__ void gemm_out(const float* __restrict__ wo,
                         const float* __restrict__ tok,
                         float* __restrict__ out) {
    __shared__ float As[16][64];
    __shared__ float Bs[16][64];
    int tx = threadIdx.x & 15, ty = threadIdx.x >> 4;
    int m0 = blockIdx.x * 64;
    int n0 = blockIdx.y * 64;

    int la_r = threadIdx.x >> 2;
    int la_c = (threadIdx.x & 3) * 4;
    int lb_r = threadIdx.x >> 4;
    int lb_c = (threadIdx.x & 15) * 4;

    float acc[4][4];
    #pragma unroll
    for (int i = 0; i < 4; i++)
        #pragma unroll
        for (int j = 0; j < 4; j++) acc[i][j] = 0.0f;

    for (int k0 = 0; k0 < 256; k0 += 16) {
        float4 a4 = *(const float4*)&g_ho[(size_t)(m0 + la_r)*256 + k0 + la_c];
        float4 b4 = *(const float4*)&wo[(size_t)(k0 + lb_r)*128 + n0 + lb_c];
        As[la_c+0][la_r] = a4.x;
        As[la_c+1][la_r] = a4.y;
        As[la_c+2][la_r] = a4.z;
        As[la_c+3][la_r] = a4.w;
        *(float4*)&Bs[lb_r][lb_c] = b4;
        __syncthreads();
        #pragma unroll
        for (int k = 0; k < 16; k++) {
            float4 a = *(const float4*)&As[k][ty*4];
            float4 b = *(const float4*)&Bs[k][tx*4];
            acc[0][0] += a.x*b.x; acc[0][1] += a.x*b.y; acc[0][2] += a.x*b.z; acc[0][3] += a.x*b.w;
            acc[1][0] += a.y*b.x; acc[1][1] += a.y*b.y; acc[1][2] += a.y*b.z; acc[1][3] += a.y*b.w;
            acc[2][0] += a.z*b.x; acc[2][1] += a.z*b.y; acc[2][2] += a.z*b.z; acc[2][3] += a.z*b.w;
            acc[3][0] += a.w*b.x; acc[3][1] += a.w*b.y; acc[3][2] += a.w*b.z; acc[3][3] += a.w*b.w;
        }
        __syncthreads();
    }
    #pragma unroll
    for (int i = 0; i < 4; i++) {
        size_t base = (size_t)(m0 + ty*4 + i)*128 + n0 + tx*4;
        float4 t4 = *(const float4*)&tok[base];
        float4 r = make_float4(acc[i][0] + t4.x, acc[i][1] + t4.y,
                               acc[i][2] + t4.z, acc[i][3] + t4.w);
        *(float4*)&out[base] = r;
    }
}

// ---------------- launch ----------------
extern "C" void kernel_launch(void* const* d_in, const int* in_sizes, int n_in,
                              void* d_out, int out_size) {
    const float* tokens = (const float*)d_in[0];
    const float* ln_w   = (const float*)d_in[1];
    const float* ln_b   = (const float*)d_in[2];
    const float* wq     = (const float*)d_in[3];
    const float* wk     = (const float*)d_in[4];
    const float* wv     = (const float*)d_in[5];
    const float* wo     = (const float*)d_in[6];
    const float* lq1    = (const float*)d_in[7];
    const float* lk1    = (const float*)d_in[8];
    const float* lq2    = (const float*)d_in[9];
    const float* lk2    = (const float*)d_in[10];
    const float* sigS   = (const float*)d_in[11];
    const float* sigN   = (const float*)d_in[12];
    const float* hnw    = (const float*)d_in[13];
    const float* hnb    = (const float*)d_in[14];
    float* out = (float*)d_out;

    const size_t attn_smem = (size_t)(KROWS*KLD + KROWS*64 + QT*64) * sizeof(float);
    cudaFuncSetAttribute(attn_kernel, cudaFuncAttributeMaxDynamicSharedMemorySize, (int)attn_smem);

    ln_kernel<<<NTOK/8, 256>>>(tokens, ln_w, ln_b);
    gemm_qkv<<<dim3(NTOK/64, 12), 256>>>(wq, wk, wv);
    attn_kernel<<<dim3(TT/QT, BB*HH), 512, attn_smem>>>(lq1, lk1, lq2, lk2, sigS, sigN, hnw, hnb);
    gemm_out<<<dim3(NTOK/64, 2), 256>>>(wo, tokens, out);
}

// round 4
// speedup vs baseline: 1.3228x; 1.3228x over previous
#include <cuda_runtime.h>
#include <math.h>

// ---------------- problem constants ----------------
#define TT 2048
#define BB 8
#define DD 128
#define HH 4
#define NTOK (BB*TT)          // 16384
#define SCALE 0.17677669529663687f   // 1/sqrt(32)
#define LAMBDA_INIT 0.8f
#define LN_EPS 1e-5f

// banded attention config
#define W_MAX 80              // max half-bandwidth (8*sigma_noise = 80)
#define QT 64                 // queries per block
#define QW 4                  // queries per warp
#define NW 16                 // warps per block
#define KROWS (QT + 2*W_MAX + 1)   // 225 rows of K/V in smem
#define KLD 68                // padded K row stride (floats), float4-aligned

// ---------------- scratch ----------------
__device__ float g_xn[NTOK*DD];        // layernormed tokens   (8 MB)
__device__ float g_y [NTOK*768];       // qkv projections      (48 MB)  [q|k|v] each 256
__device__ float g_ho[NTOK*256];       // per-head outputs     (16 MB)

__device__ __forceinline__ float dot4(float4 a, float4 b) {
    return a.x*b.x + a.y*b.y + a.z*b.z + a.w*b.w;
}
__device__ __forceinline__ float warpsum(float v) {
    #pragma unroll
    for (int o = 16; o; o >>= 1) v += __shfl_xor_sync(0xffffffffu, v, o);
    return v;
}

// ---------------- stage 1: layernorm ----------------
__global__ void ln_kernel(const float* __restrict__ tok,
                          const float* __restrict__ w,
                          const float* __restrict__ b) {
    int t = blockIdx.x * 8 + (threadIdx.x >> 5);
    int lane = threadIdx.x & 31;
    const float4* src = (const float4*)(tok + (size_t)t * DD);
    float4 x = src[lane];
    float s  = x.x + x.y + x.z + x.w;
    float sq = x.x*x.x + x.y*x.y + x.z*x.z + x.w*x.w;
    s  = warpsum(s);
    sq = warpsum(sq);
    float mu  = s * (1.0f/128.0f);
    float var = sq * (1.0f/128.0f) - mu*mu;
    float rs  = rsqrtf(var + LN_EPS);
    float4 w4 = ((const float4*)w)[lane];
    float4 b4 = ((const float4*)b)[lane];
    float4 o;
    o.x = (x.x - mu) * rs * w4.x + b4.x;
    o.y = (x.y - mu) * rs * w4.y + b4.y;
    o.z = (x.z - mu) * rs * w4.z + b4.z;
    o.w = (x.w - mu) * rs * w4.w + b4.w;
    ((float4*)(g_xn + (size_t)t * DD))[lane] = o;
}

// ---------------- stage 2: QKV gemm (16384x128 @ 128x768) ----------------
__global__ void gemm_qkv(const float* __restrict__ wq,
                         const float* __restrict__ wk,
                         const float* __restrict__ wv) {
    __shared__ float As[16][64];
    __shared__ float Bs[16][64];
    int tx = threadIdx.x & 15, ty = threadIdx.x >> 4;
    int m0 = blockIdx.x * 64;
    int n0 = blockIdx.y * 64;
    const float* Bsrc; int nb;
    if (n0 < 256)      { Bsrc = wq; nb = n0; }
    else if (n0 < 512) { Bsrc = wk; nb = n0 - 256; }
    else               { Bsrc = wv; nb = n0 - 512; }

    int la_r = threadIdx.x >> 2;          // 0..63
    int la_c = (threadIdx.x & 3) * 4;     // 0,4,8,12
    int lb_r = threadIdx.x >> 4;          // 0..15
    int lb_c = (threadIdx.x & 15) * 4;    // 0..60

    float acc[4][4];
    #pragma unroll
    for (int i = 0; i < 4; i++)
        #pragma unroll
        for (int j = 0; j < 4; j++) acc[i][j] = 0.0f;

    for (int k0 = 0; k0 < 128; k0 += 16) {
        float4 a4 = *(const float4*)&g_xn[(size_t)(m0 + la_r)*128 + k0 + la_c];
        float4 b4 = *(const float4*)&Bsrc[(size_t)(k0 + lb_r)*256 + nb + lb_c];
        As[la_c+0][la_r] = a4.x;
        As[la_c+1][la_r] = a4.y;
        As[la_c+2][la_r] = a4.z;
        As[la_c+3][la_r] = a4.w;
        *(float4*)&Bs[lb_r][lb_c] = b4;
        __syncthreads();
        #pragma unroll
        for (int k = 0; k < 16; k++) {
            float4 a = *(const float4*)&As[k][ty*4];
            float4 b = *(const float4*)&Bs[k][tx*4];
            acc[0][0] += a.x*b.x; acc[0][1] += a.x*b.y; acc[0][2] += a.x*b.z; acc[0][3] += a.x*b.w;
            acc[1][0] += a.y*b.x; acc[1][1] += a.y*b.y; acc[1][2] += a.y*b.z; acc[1][3] += a.y*b.w;
            acc[2][0] += a.z*b.x; acc[2][1] += a.z*b.y; acc[2][2] += a.z*b.z; acc[2][3] += a.z*b.w;
            acc[3][0] += a.w*b.x; acc[3][1] += a.w*b.y; acc[3][2] += a.w*b.z; acc[3][3] += a.w*b.w;
        }
        __syncthreads();
    }
    #pragma unroll
    for (int i = 0; i < 4; i++) {
        float4 r = make_float4(acc[i][0], acc[i][1], acc[i][2], acc[i][3]);
        *(float4*)&g_y[(size_t)(m0 + ty*4 + i)*768 + n0 + tx*4] = r;
    }
}

// ---------------- stage 3: banded differential attention ----------------
// No online-softmax max tracking: scores are bounded (qk ~ N(0,1), bias <= 0,
// diagonal always present), so raw expf(s) is safe in fp32. Per-query band
// masking is implicit: out-of-band Gaussian bias underflows exp to 0.
__global__ void __launch_bounds__(512, 1)
attn_kernel(const float* __restrict__ lq1, const float* __restrict__ lk1,
            const float* __restrict__ lq2, const float* __restrict__ lk2,
            const float* __restrict__ sigS, const float* __restrict__ sigN,
            const float* __restrict__ hnw,  const float* __restrict__ hnb) {
    extern __shared__ float sm[];
    float*  Ksm  = sm;                       // KROWS * KLD
    float*  Vsm  = Ksm + KROWS*KLD;          // KROWS * 64 (interleaved (d,d+32))
    float*  Qsm  = Vsm + KROWS*64;           // QT * 64
    float4* Pbuf = (float4*)(Qsm + QT*64);   // [NW][2][32] float4
    __shared__ float s_lam;

    int tid = threadIdx.x;
    int bh  = blockIdx.y;
    int b   = bh >> 2;      // / HH
    int h   = bh & 3;       // % HH
    int q0  = blockIdx.x * QT;

    float ss = fmaxf(sigS[0], 1.0f), sn = fmaxf(sigN[0], 1.0f);
    float c1 = -0.5f / (ss*ss);
    float c2 = -0.5f / (sn*sn);
    int Wn = (int)ceilf(8.0f * fmaxf(ss, sn));
    if (Wn > W_MAX) Wn = W_MAX;

    int blo = q0 - Wn;          if (blo < 0) blo = 0;
    int bhi = q0 + QT - 1 + Wn; if (bhi > TT-1) bhi = TT-1;
    int nrows = bhi - blo + 1;

    const float* ybase = g_y + (size_t)(b*TT) * 768;

    // cooperative K/V band load
    for (int idx = tid; idx < nrows*64; idx += 512) {
        int r = idx >> 6, d = idx & 63;
        const float* row = ybase + (size_t)(blo + r)*768 + h*64;
        Ksm[r*KLD + d] = row[256 + d];
        float v = row[512 + d];
        int dd = (d < 32) ? (2*d) : (2*(d-32) + 1);
        Vsm[r*64 + dd] = v;
    }
    // Q tile
    for (int idx = tid; idx < QT*64; idx += 512) {
        int r = idx >> 6, d = idx & 63;
        Qsm[idx] = ybase[(size_t)(q0 + r)*768 + h*64 + d];
    }
    if (tid == 0) {
        float d1 = 0.0f, d2 = 0.0f;
        #pragma unroll
        for (int i = 0; i < 32; i++) { d1 += lq1[i]*lk1[i]; d2 += lq2[i]*lk2[i]; }
        s_lam = __expf(d1) - __expf(d2) + LAMBDA_INIT;
    }
    __syncthreads();
    float lam = s_lam;

    int w = tid >> 5, lane = tid & 31;
    int i0 = q0 + w*QW;                          // queries i0 .. i0+3
    int jlo = i0 - Wn;           if (jlo < blo) jlo = blo;
    int jhi = i0 + QW - 1 + Wn;  if (jhi > bhi) jhi = bhi;

    float4* p1buf = Pbuf + w*64;        // 32 float4 per warp
    float4* p2buf = p1buf + 32;

    float  l1[QW], l2[QW];
    float2 o1[QW], o2[QW];
    #pragma unroll
    for (int q = 0; q < QW; q++) {
        l1[q] = 0.0f; l2[q] = 0.0f;
        o1[q] = make_float2(0.0f, 0.0f);
        o2[q] = make_float2(0.0f, 0.0f);
    }

    for (int jc = jlo; jc <= jhi; jc += 32) {
        int j = jc + lane;
        bool valid = (j <= jhi);
        int r = (valid ? j : jhi) - blo;      // clamp row for safe smem read
        const float4* kr = (const float4*)(Ksm + r*KLD);

        float s1[QW], s2[QW];
        #pragma unroll
        for (int q = 0; q < QW; q++) { s1[q] = 0.0f; s2[q] = 0.0f; }

        #pragma unroll
        for (int dc = 0; dc < 8; dc++) {
            float4 k4 = kr[dc];
            #pragma unroll
            for (int q = 0; q < QW; q++) {
                float4 q4 = *(const float4*)&Qsm[(w*QW + q)*64 + dc*4];
                s1[q] += dot4(k4, q4);
            }
        }
        #pragma unroll
        for (int dc = 8; dc < 16; dc++) {
            float4 k4 = kr[dc];
            #pragma unroll
            for (int q = 0; q < QW; q++) {
                float4 q4 = *(const float4*)&Qsm[(w*QW + q)*64 + dc*4];
                s2[q] += dot4(k4, q4);
            }
        }

        float relb = (float)(j - i0);
        float e1[QW], e2[QW];
        #pragma unroll
        for (int q = 0; q < QW; q++) {
            float rel = relb - (float)q;
            float r2  = rel*rel;
            e1[q] = valid ? __expf(s1[q]*SCALE + r2*c1) : 0.0f;
            e2[q] = valid ? __expf(s2[q]*SCALE + r2*c2) : 0.0f;
            l1[q] += e1[q];
            l2[q] += e2[q];
        }
        p1buf[lane] = make_float4(e1[0], e1[1], e1[2], e1[3]);
        p2buf[lane] = make_float4(e2[0], e2[1], e2[2], e2[3]);
        __syncwarp();

        int cnt = jhi - jc + 1; if (cnt > 32) cnt = 32;
        const float2* vb = (const float2*)(Vsm + (jc - blo)*64);
        #pragma unroll 4
        for (int jj = 0; jj < cnt; jj++) {
            float2 v = vb[jj*32 + lane];
            float4 a = p1buf[jj];   // uniform broadcast
            float4 bq = p2buf[jj];
            o1[0].x += a.x*v.x;  o1[0].y += a.x*v.y;
            o1[1].x += a.y*v.x;  o1[1].y += a.y*v.y;
            o1[2].x += a.z*v.x;  o1[2].y += a.z*v.y;
            o1[3].x += a.w*v.x;  o1[3].y += a.w*v.y;
            o2[0].x += bq.x*v.x; o2[0].y += bq.x*v.y;
            o2[1].x += bq.y*v.x; o2[1].y += bq.y*v.y;
            o2[2].x += bq.z*v.x; o2[2].y += bq.z*v.y;
            o2[3].x += bq.w*v.x; o2[3].y += bq.w*v.y;
        }
        __syncwarp();
    }

    // epilogue: combine, per-head layernorm(64), *(1-lambda_init)
    float hw0 = hnw[lane], hw1 = hnw[lane+32];
    float hb0 = hnb[lane], hb1 = hnb[lane+32];
    float post = 1.0f - LAMBDA_INIT;
    #pragma unroll
    for (int q = 0; q < QW; q++) {
        float L1 = warpsum(l1[q]);
        float L2 = warpsum(l2[q]);
        float il1 = 1.0f / L1;
        float il2 = lam  / L2;
        float ox = o1[q].x*il1 - o2[q].x*il2;
        float oy = o1[q].y*il1 - o2[q].y*il2;
        float s  = warpsum(ox + oy);
        float sq = warpsum(ox*ox + oy*oy);
        float mu  = s * (1.0f/64.0f);
        float var = sq * (1.0f/64.0f) - mu*mu;
        float rs  = rsqrtf(var + LN_EPS);
        float y0 = ((ox - mu)*rs*hw0 + hb0) * post;
        float y1 = ((oy - mu)*rs*hw1 + hb1) * post;
        int i = i0 + q;
        float* dst = g_ho + (size_t)(b*TT + i)*256 + h*64;
        dst[lane]      = y0;
        dst[lane + 32] = y1;
    }
}

// ---------------- stage 4: output gemm + residual ----------------
__global__ void gemm_out(const float* __restrict__ wo,
                         const float* __restrict__ tok,
                         float* __restrict__ out) {
    __shared__ float As[16][64];
    __shared__ float Bs[16][64];
    int tx = threadIdx.x & 15, ty = threadIdx.x >> 4;
    int m0 = blockIdx.x * 64;
    int n0 = blockIdx.y * 64;

    int la_r = threadIdx.x >> 2;
    int la_c = (threadIdx.x & 3) * 4;
    int lb_r = threadIdx.x >> 4;
    int lb_c = (threadIdx.x & 15) * 4;

    float acc[4][4];
    #pragma unroll
    for (int i = 0; i < 4; i++)
        #pragma unroll
        for (int j = 0; j < 4; j++) acc[i][j] = 0.0f;

    for (int k0 = 0; k0 < 256; k0 += 16) {
        float4 a4 = *(const float4*)&g_ho[(size_t)(m0 + la_r)*256 + k0 + la_c];
        float4 b4 = *(const float4*)&wo[(size_t)(k0 + lb_r)*128 + n0 + lb_c];
        As[la_c+0][la_r] = a4.x;
        As[la_c+1][la_r] = a4.y;
        As[la_c+2][la_r] = a4.z;
        As[la_c+3][la_r] = a4.w;
        *(float4*)&Bs[lb_r][lb_c] = b4;
        __syncthreads();
        #pragma unroll
        for (int k = 0; k < 16; k++) {
            float4 a = *(const float4*)&As[k][ty*4];
            float4 b = *(const float4*)&Bs[k][tx*4];
            acc[0][0] += a.x*b.x; acc[0][1] += a.x*b.y; acc[0][2] += a.x*b.z; acc[0][3] += a.x*b.w;
            acc[1][0] += a.y*b.x; acc[1][1] += a.y*b.y; acc[1][2] += a.y*b.z; acc[1][3] += a.y*b.w;
            acc[2][0] += a.z*b.x; acc[2][1] += a.z*b.y; acc[2][2] += a.z*b.z; acc[2][3] += a.z*b.w;
            acc[3][0] += a.w*b.x; acc[3][1] += a.w*b.y; acc[3][2] += a.w*b.z; acc[3][3] += a.w*b.w;
        }
        __syncthreads();
    }
    #pragma unroll
    for (int i = 0; i < 4; i++) {
        size_t base = (size_t)(m0 + ty*4 + i)*128 + n0 + tx*4;
        float4 t4 = *(const float4*)&tok[base];
        float4 r = make_float4(acc[i][0] + t4.x, acc[i][1] + t4.y,
                               acc[i][2] + t4.z, acc[i][3] + t4.w);
        *(float4*)&out[base] = r;
    }
}

// ---------------- launch ----------------
extern "C" void kernel_launch(void* const* d_in, const int* in_sizes, int n_in,
                              void* d_out, int out_size) {
    const float* tokens = (const float*)d_in[0];
    const float* ln_w   = (const float*)d_in[1];
    const float* ln_b   = (const float*)d_in[2];
    const float* wq     = (const float*)d_in[3];
    const float* wk     = (const float*)d_in[4];
    const float* wv     = (const float*)d_in[5];
    const float* wo     = (const float*)d_in[6];
    const float* lq1    = (const float*)d_in[7];
    const float* lk1    = (const float*)d_in[8];
    const float* lq2    = (const float*)d_in[9];
    const float* lk2    = (const float*)d_in[10];
    const float* sigS   = (const float*)d_in[11];
    const float* sigN   = (const float*)d_in[12];
    const float* hnw    = (const float*)d_in[13];
    const float* hnb    = (const float*)d_in[14];
    float* out = (float*)d_out;

    const size_t attn_smem = (size_t)(KROWS*KLD + KROWS*64 + QT*64 + NW*2*32*4) * sizeof(float);
    cudaFuncSetAttribute(attn_kernel, cudaFuncAttributeMaxDynamicSharedMemorySize, (int)attn_smem);

    ln_kernel<<<NTOK/8, 256>>>(tokens, ln_w, ln_b);
    gemm_qkv<<<dim3(NTOK/64, 12), 256>>>(wq, wk, wv);
    attn_kernel<<<dim3(TT/QT, BB*HH), 512, attn_smem>>>(lq1, lk1, lq2, lk2, sigS, sigN, hnw, hnb);
    gemm_out<<<dim3(NTOK/64, 2), 256>>>(wo, tokens, out);
}

// round 5
// speedup vs baseline: 1.3261x; 1.0025x over previous
#include <cuda_runtime.h>
#include <math.h>

// ---------------- problem constants ----------------
#define TT 2048
#define BB 8
#define DD 128
#define HH 4
#define NTOK (BB*TT)          // 16384
#define SCALE 0.17677669529663687f   // 1/sqrt(32)
#define LAMBDA_INIT 0.8f
#define LN_EPS 1e-5f

// banded attention config
#define W_MAX 80              // max half-bandwidth (8*sigma)
#define QT 64                 // queries per block
#define QW 8                  // queries per warp
#define NW 8                  // warps per block
#define KROWS (QT + 2*W_MAX + 1)   // 225 rows of K/V in smem
#define KLD 68                // padded K row stride (floats), 16B-aligned rows

typedef unsigned long long u64;

// ---------------- scratch ----------------
__device__ float g_xn[NTOK*DD];        // layernormed tokens   (8 MB)
__device__ float g_y [NTOK*768];       // qkv projections      (48 MB)  [q|k|v] each 256
__device__ float g_ho[NTOK*256];       // per-head outputs     (16 MB)

// ---------------- f32x2 helpers ----------------
__device__ __forceinline__ u64 pk2(float x, float y) {
    u64 r; asm("mov.b64 %0, {%1, %2};" : "=l"(r) : "f"(x), "f"(y)); return r;
}
__device__ __forceinline__ void up2(u64 v, float& x, float& y) {
    asm("mov.b64 {%0, %1}, %2;" : "=f"(x), "=f"(y) : "l"(v));
}
__device__ __forceinline__ u64 f2fma(u64 a, u64 b, u64 c) {
    u64 d; asm("fma.rn.f32x2 %0, %1, %2, %3;" : "=l"(d) : "l"(a), "l"(b), "l"(c));
    return d;
}
__device__ __forceinline__ float warpsum(float v) {
    #pragma unroll
    for (int o = 16; o; o >>= 1) v += __shfl_xor_sync(0xffffffffu, v, o);
    return v;
}

// ---------------- stage 1: layernorm ----------------
__global__ void ln_kernel(const float* __restrict__ tok,
                          const float* __restrict__ w,
                          const float* __restrict__ b) {
    int t = blockIdx.x * 8 + (threadIdx.x >> 5);
    int lane = threadIdx.x & 31;
    const float4* src = (const float4*)(tok + (size_t)t * DD);
    float4 x = src[lane];
    float s  = x.x + x.y + x.z + x.w;
    float sq = x.x*x.x + x.y*x.y + x.z*x.z + x.w*x.w;
    s  = warpsum(s);
    sq = warpsum(sq);
    float mu  = s * (1.0f/128.0f);
    float var = sq * (1.0f/128.0f) - mu*mu;
    float rs  = rsqrtf(var + LN_EPS);
    float4 w4 = ((const float4*)w)[lane];
    float4 b4 = ((const float4*)b)[lane];
    float4 o;
    o.x = (x.x - mu) * rs * w4.x + b4.x;
    o.y = (x.y - mu) * rs * w4.y + b4.y;
    o.z = (x.z - mu) * rs * w4.z + b4.z;
    o.w = (x.w - mu) * rs * w4.w + b4.w;
    ((float4*)(g_xn + (size_t)t * DD))[lane] = o;
}

// ---------------- stage 2: QKV gemm 16384x128 @ 128x768, 128x128 tile ----------------
__global__ void __launch_bounds__(256, 2)
gemm_qkv(const float* __restrict__ wq,
         const float* __restrict__ wk,
         const float* __restrict__ wv) {
    __shared__ __align__(16) float As[8][132];
    __shared__ __align__(16) float Bs[8][128];
    int tid = threadIdx.x;
    int tx = tid & 15, ty = tid >> 4;
    int m0 = blockIdx.x * 128, n0 = blockIdx.y * 128;
    const float* Bsrc; int nb;
    if (n0 < 256)      { Bsrc = wq; nb = n0; }
    else if (n0 < 512) { Bsrc = wk; nb = n0 - 256; }
    else               { Bsrc = wv; nb = n0 - 512; }

    int ar = tid >> 1, ac = (tid & 1) * 4;
    int br = tid >> 5, bc = (tid & 31) * 4;

    u64 acc[8][4];
    #pragma unroll
    for (int i = 0; i < 8; i++)
        #pragma unroll
        for (int j = 0; j < 4; j++) acc[i][j] = 0ull;

    for (int k0 = 0; k0 < 128; k0 += 8) {
        float4 a4 = *(const float4*)&g_xn[(size_t)(m0 + ar)*128 + k0 + ac];
        float4 b4 = *(const float4*)&Bsrc[(size_t)(k0 + br)*256 + nb + bc];
        As[ac+0][ar] = a4.x; As[ac+1][ar] = a4.y;
        As[ac+2][ar] = a4.z; As[ac+3][ar] = a4.w;
        *(float4*)&Bs[br][bc] = b4;
        __syncthreads();
        #pragma unroll
        for (int k = 0; k < 8; k++) {
            float4 aA = *(const float4*)&As[k][ty*8];
            float4 aB = *(const float4*)&As[k][ty*8 + 4];
            const ulonglong2* bp = (const ulonglong2*)&Bs[k][tx*8];
            ulonglong2 b01 = bp[0], b23 = bp[1];
            u64 ad[8];
            ad[0]=pk2(aA.x,aA.x); ad[1]=pk2(aA.y,aA.y);
            ad[2]=pk2(aA.z,aA.z); ad[3]=pk2(aA.w,aA.w);
            ad[4]=pk2(aB.x,aB.x); ad[5]=pk2(aB.y,aB.y);
            ad[6]=pk2(aB.z,aB.z); ad[7]=pk2(aB.w,aB.w);
            #pragma unroll
            for (int i = 0; i < 8; i++) {
                acc[i][0] = f2fma(ad[i], b01.x, acc[i][0]);
                acc[i][1] = f2fma(ad[i], b01.y, acc[i][1]);
                acc[i][2] = f2fma(ad[i], b23.x, acc[i][2]);
                acc[i][3] = f2fma(ad[i], b23.y, acc[i][3]);
            }
        }
        __syncthreads();
    }
    #pragma unroll
    for (int i = 0; i < 8; i++) {
        float c[8];
        up2(acc[i][0], c[0], c[1]); up2(acc[i][1], c[2], c[3]);
        up2(acc[i][2], c[4], c[5]); up2(acc[i][3], c[6], c[7]);
        size_t base = (size_t)(m0 + ty*8 + i)*768 + n0 + tx*8;
        *(float4*)&g_y[base]     = make_float4(c[0], c[1], c[2], c[3]);
        *(float4*)&g_y[base + 4] = make_float4(c[4], c[5], c[6], c[7]);
    }
}

// ---------------- stage 3: banded differential attention ----------------
// No softmax max-tracking (scores bounded; out-of-band bias underflows exp to 0).
// Matrix1 (sigma_signal) has a narrower band than matrix2 -> skip its score +
// PV work on chunks outside the m1 window (warp-uniform branch).
__global__ void __launch_bounds__(256, 1)
attn_kernel(const float* __restrict__ lq1, const float* __restrict__ lk1,
            const float* __restrict__ lq2, const float* __restrict__ lk2,
            const float* __restrict__ sigS, const float* __restrict__ sigN,
            const float* __restrict__ hnw,  const float* __restrict__ hnb) {
    extern __shared__ float sm[];
    float* Ksm = sm;                       // KROWS * KLD
    float* Vsm = Ksm + KROWS*KLD;          // KROWS * 64 (interleaved (d,d+32) pairs)
    float* Qsm = Vsm + KROWS*64;           // QT * 64
    u64*   Pb  = (u64*)(Qsm + QT*64);      // NW * 256 u64 (per warp: 128 p1 + 128 p2)
    __shared__ float s_lam;

    int tid = threadIdx.x;
    int bh  = blockIdx.y;
    int b   = bh >> 2;
    int h   = bh & 3;
    int q0  = blockIdx.x * QT;

    float ss = fmaxf(sigS[0], 1.0f), sn = fmaxf(sigN[0], 1.0f);
    float c1 = -0.5f / (ss*ss);
    float c2 = -0.5f / (sn*sn);
    int Wn = (int)ceilf(8.0f * fmaxf(ss, sn)); if (Wn > W_MAX) Wn = W_MAX;
    int W1 = (int)ceilf(8.0f * ss);            if (W1 > W_MAX) W1 = W_MAX;

    int blo = q0 - Wn;          if (blo < 0) blo = 0;
    int bhi = q0 + QT - 1 + Wn; if (bhi > TT-1) bhi = TT-1;
    int nrows = bhi - blo + 1;

    const float* ybase = g_y + (size_t)(b*TT) * 768;

    // cooperative K/V band load
    for (int idx = tid; idx < nrows*64; idx += 256) {
        int r = idx >> 6, d = idx & 63;
        const float* row = ybase + (size_t)(blo + r)*768 + h*64;
        Ksm[r*KLD + d] = row[256 + d];
        float v = row[512 + d];
        int dd = (d < 32) ? (2*d) : (2*(d-32) + 1);
        Vsm[r*64 + dd] = v;
    }
    // Q tile
    for (int idx = tid; idx < QT*64; idx += 256) {
        int r = idx >> 6, d = idx & 63;
        Qsm[idx] = ybase[(size_t)(q0 + r)*768 + h*64 + d];
    }
    if (tid == 0) {
        float d1 = 0.0f, d2 = 0.0f;
        #pragma unroll
        for (int i = 0; i < 32; i++) { d1 += lq1[i]*lk1[i]; d2 += lq2[i]*lk2[i]; }
        s_lam = __expf(d1) - __expf(d2) + LAMBDA_INIT;
    }
    __syncthreads();
    float lam = s_lam;

    int w = tid >> 5, lane = tid & 31;
    int i0 = q0 + w*QW;                          // queries i0 .. i0+7
    int jlo = i0 - Wn;           if (jlo < blo) jlo = blo;
    int jhi = i0 + QW - 1 + Wn;  if (jhi > bhi) jhi = bhi;
    int m1lo = i0 - W1, m1hi = i0 + QW - 1 + W1;

    u64* p1w = Pb + w*256;     // 128 u64
    u64* p2w = p1w + 128;

    u64 o1x[4], o1y[4], o2x[4], o2y[4];
    float l1[QW], l2[QW];
    #pragma unroll
    for (int i = 0; i < 4; i++) { o1x[i]=0ull; o1y[i]=0ull; o2x[i]=0ull; o2y[i]=0ull; }
    #pragma unroll
    for (int q = 0; q < QW; q++) { l1[q] = 0.0f; l2[q] = 0.0f; }

    for (int jc = jlo; jc <= jhi; jc += 32) {
        bool doM1 = (jc <= m1hi) && (jc + 31 >= m1lo);
        int j = jc + lane;
        bool valid = (j <= jhi);
        int r = (valid ? j : jhi) - blo;
        const ulonglong2* kr = (const ulonglong2*)(Ksm + r*KLD);
        float relb = (float)(j - i0);

        // --- scores2 (always) ---
        u64 a2[QW];
        #pragma unroll
        for (int q = 0; q < QW; q++) a2[q] = 0ull;
        #pragma unroll
        for (int dc = 8; dc < 16; dc++) {
            ulonglong2 k2 = kr[dc];
            #pragma unroll
            for (int q = 0; q < QW; q++) {
                ulonglong2 q2 = *(const ulonglong2*)(Qsm + (w*QW + q)*64 + dc*4);
                a2[q] = f2fma(k2.x, q2.x, a2[q]);
                a2[q] = f2fma(k2.y, q2.y, a2[q]);
            }
        }
        float e2[QW];
        #pragma unroll
        for (int q = 0; q < QW; q++) {
            float rel = relb - (float)q, rr = rel*rel;
            float lo, hi; up2(a2[q], lo, hi);
            float s = (lo + hi)*SCALE + rr*c2;
            e2[q] = valid ? __expf(s) : 0.0f;
            l2[q] += e2[q];
        }
        ((ulonglong2*)p2w)[lane*2]     = make_ulonglong2(pk2(e2[0],e2[1]), pk2(e2[2],e2[3]));
        ((ulonglong2*)p2w)[lane*2 + 1] = make_ulonglong2(pk2(e2[4],e2[5]), pk2(e2[6],e2[7]));

        // --- scores1 (narrow band only) ---
        if (doM1) {
            u64 a1[QW];
            #pragma unroll
            for (int q = 0; q < QW; q++) a1[q] = 0ull;
            #pragma unroll
            for (int dc = 0; dc < 8; dc++) {
                ulonglong2 k2 = kr[dc];
                #pragma unroll
                for (int q = 0; q < QW; q++) {
                    ulonglong2 q2 = *(const ulonglong2*)(Qsm + (w*QW + q)*64 + dc*4);
                    a1[q] = f2fma(k2.x, q2.x, a1[q]);
                    a1[q] = f2fma(k2.y, q2.y, a1[q]);
                }
            }
            float e1[QW];
            #pragma unroll
            for (int q = 0; q < QW; q++) {
                float rel = relb - (float)q, rr = rel*rel;
                float lo, hi; up2(a1[q], lo, hi);
                float s = (lo + hi)*SCALE + rr*c1;
                e1[q] = valid ? __expf(s) : 0.0f;
                l1[q] += e1[q];
            }
            ((ulonglong2*)p1w)[lane*2]     = make_ulonglong2(pk2(e1[0],e1[1]), pk2(e1[2],e1[3]));
            ((ulonglong2*)p1w)[lane*2 + 1] = make_ulonglong2(pk2(e1[4],e1[5]), pk2(e1[6],e1[7]));
        }
        __syncwarp();

        // --- P.V accumulation ---
        int cnt = jhi - jc + 1; if (cnt > 32) cnt = 32;
        const float2* vb = (const float2*)(Vsm + (jc - blo)*64);
        const ulonglong2* P1 = (const ulonglong2*)p1w;
        const ulonglong2* P2 = (const ulonglong2*)p2w;
        if (doM1) {
            for (int jj = 0; jj < cnt; jj++) {
                float2 v = vb[jj*32 + lane];
                u64 vx = pk2(v.x, v.x), vy = pk2(v.y, v.y);
                ulonglong2 pa = P1[jj*2], pb = P1[jj*2 + 1];
                ulonglong2 qa = P2[jj*2], qb = P2[jj*2 + 1];
                o1x[0] = f2fma(pa.x, vx, o1x[0]);  o1y[0] = f2fma(pa.x, vy, o1y[0]);
                o1x[1] = f2fma(pa.y, vx, o1x[1]);  o1y[1] = f2fma(pa.y, vy, o1y[1]);
                o1x[2] = f2fma(pb.x, vx, o1x[2]);  o1y[2] = f2fma(pb.x, vy, o1y[2]);
                o1x[3] = f2fma(pb.y, vx, o1x[3]);  o1y[3] = f2fma(pb.y, vy, o1y[3]);
                o2x[0] = f2fma(qa.x, vx, o2x[0]);  o2y[0] = f2fma(qa.x, vy, o2y[0]);
                o2x[1] = f2fma(qa.y, vx, o2x[1]);  o2y[1] = f2fma(qa.y, vy, o2y[1]);
                o2x[2] = f2fma(qb.x, vx, o2x[2]);  o2y[2] = f2fma(qb.x, vy, o2y[2]);
                o2x[3] = f2fma(qb.y, vx, o2x[3]);  o2y[3] = f2fma(qb.y, vy, o2y[3]);
            }
        } else {
            for (int jj = 0; jj < cnt; jj++) {
                float2 v = vb[jj*32 + lane];
                u64 vx = pk2(v.x, v.x), vy = pk2(v.y, v.y);
                ulonglong2 qa = P2[jj*2], qb = P2[jj*2 + 1];
                o2x[0] = f2fma(qa.x, vx, o2x[0]);  o2y[0] = f2fma(qa.x, vy, o2y[0]);
                o2x[1] = f2fma(qa.y, vx, o2x[1]);  o2y[1] = f2fma(qa.y, vy, o2y[1]);
                o2x[2] = f2fma(qb.x, vx, o2x[2]);  o2y[2] = f2fma(qb.x, vy, o2y[2]);
                o2x[3] = f2fma(qb.y, vx, o2x[3]);  o2y[3] = f2fma(qb.y, vy, o2y[3]);
            }
        }
        __syncwarp();
    }

    // epilogue: combine, per-head layernorm(64), *(1-lambda_init)
    float hw0 = hnw[lane], hw1 = hnw[lane+32];
    float hb0 = hnb[lane], hb1 = hnb[lane+32];
    float post = 1.0f - LAMBDA_INIT;
    #pragma unroll
    for (int qp = 0; qp < 4; qp++) {
        float x1a, x1b, y1a, y1b, x2a, x2b, y2a, y2b;
        up2(o1x[qp], x1a, x1b);  up2(o1y[qp], y1a, y1b);
        up2(o2x[qp], x2a, x2b);  up2(o2y[qp], y2a, y2b);
        #pragma unroll
        for (int sub = 0; sub < 2; sub++) {
            int q = qp*2 + sub;
            float x1 = sub ? x1b : x1a, y1 = sub ? y1b : y1a;
            float x2 = sub ? x2b : x2a, y2 = sub ? y2b : y2a;
            float L1 = warpsum(l1[q]);
            float L2 = warpsum(l2[q]);
            float il1 = 1.0f / L1;
            float il2 = lam  / L2;
            float ox = x1*il1 - x2*il2;
            float oy = y1*il1 - y2*il2;
            float s  = warpsum(ox + oy);
            float sq = warpsum(ox*ox + oy*oy);
            float mu  = s * (1.0f/64.0f);
            float var = sq * (1.0f/64.0f) - mu*mu;
            float rs  = rsqrtf(var + LN_EPS);
            float y0 = ((ox - mu)*rs*hw0 + hb0) * post;
            float y1o = ((oy - mu)*rs*hw1 + hb1) * post;
            int i = i0 + q;
            float* dst = g_ho + (size_t)(b*TT + i)*256 + h*64;
            dst[lane]      = y0;
            dst[lane + 32] = y1o;
        }
    }
}

// ---------------- stage 4: output gemm 16384x256 @ 256x128 + residual ----------------
__global__ void __launch_bounds__(256, 2)
gemm_out(const float* __restrict__ wo,
         const float* __restrict__ tok,
         float* __restrict__ out) {
    __shared__ __align__(16) float As[8][132];
    __shared__ __align__(16) float Bs[8][128];
    int tid = threadIdx.x;
    int tx = tid & 15, ty = tid >> 4;
    int m0 = blockIdx.x * 128;

    int ar = tid >> 1, ac = (tid & 1) * 4;
    int br = tid >> 5, bc = (tid & 31) * 4;

    u64 acc[8][4];
    #pragma unroll
    for (int i = 0; i < 8; i++)
        #pragma unroll
        for (int j = 0; j < 4; j++) acc[i][j] = 0ull;

    for (int k0 = 0; k0 < 256; k0 += 8) {
        float4 a4 = *(const float4*)&g_ho[(size_t)(m0 + ar)*256 + k0 + ac];
        float4 b4 = *(const float4*)&wo[(size_t)(k0 + br)*128 + bc];
        As[ac+0][ar] = a4.x; As[ac+1][ar] = a4.y;
        As[ac+2][ar] = a4.z; As[ac+3][ar] = a4.w;
        *(float4*)&Bs[br][bc] = b4;
        __syncthreads();
        #pragma unroll
        for (int k = 0; k < 8; k++) {
            float4 aA = *(const float4*)&As[k][ty*8];
            float4 aB = *(const float4*)&As[k][ty*8 + 4];
            const ulonglong2* bp = (const ulonglong2*)&Bs[k][tx*8];
            ulonglong2 b01 = bp[0], b23 = bp[1];
            u64 ad[8];
            ad[0]=pk2(aA.x,aA.x); ad[1]=pk2(aA.y,aA.y);
            ad[2]=pk2(aA.z,aA.z); ad[3]=pk2(aA.w,aA.w);
            ad[4]=pk2(aB.x,aB.x); ad[5]=pk2(aB.y,aB.y);
            ad[6]=pk2(aB.z,aB.z); ad[7]=pk2(aB.w,aB.w);
            #pragma unroll
            for (int i = 0; i < 8; i++) {
                acc[i][0] = f2fma(ad[i], b01.x, acc[i][0]);
                acc[i][1] = f2fma(ad[i], b01.y, acc[i][1]);
                acc[i][2] = f2fma(ad[i], b23.x, acc[i][2]);
                acc[i][3] = f2fma(ad[i], b23.y, acc[i][3]);
            }
        }
        __syncthreads();
    }
    #pragma unroll
    for (int i = 0; i < 8; i++) {
        float c[8];
        up2(acc[i][0], c[0], c[1]); up2(acc[i][1], c[2], c[3]);
        up2(acc[i][2], c[4], c[5]); up2(acc[i][3], c[6], c[7]);
        size_t base = (size_t)(m0 + ty*8 + i)*128 + tx*8;
        float4 t0 = *(const float4*)&tok[base];
        float4 t1 = *(const float4*)&tok[base + 4];
        *(float4*)&out[base]     = make_float4(c[0]+t0.x, c[1]+t0.y, c[2]+t0.z, c[3]+t0.w);
        *(float4*)&out[base + 4] = make_float4(c[4]+t1.x, c[5]+t1.y, c[6]+t1.z, c[7]+t1.w);
    }
}

// ---------------- launch ----------------
extern "C" void kernel_launch(void* const* d_in, const int* in_sizes, int n_in,
                              void* d_out, int out_size) {
    const float* tokens = (const float*)d_in[0];
    const float* ln_w   = (const float*)d_in[1];
    const float* ln_b   = (const float*)d_in[2];
    const float* wq     = (const float*)d_in[3];
    const float* wk     = (const float*)d_in[4];
    const float* wv     = (const float*)d_in[5];
    const float* wo     = (const float*)d_in[6];
    const float* lq1    = (const float*)d_in[7];
    const float* lk1    = (const float*)d_in[8];
    const float* lq2    = (const float*)d_in[9];
    const float* lk2    = (const float*)d_in[10];
    const float* sigS   = (const float*)d_in[11];
    const float* sigN   = (const float*)d_in[12];
    const float* hnw    = (const float*)d_in[13];
    const float* hnb    = (const float*)d_in[14];
    float* out = (float*)d_out;

    const size_t attn_smem = (size_t)(KROWS*KLD + KROWS*64 + QT*64) * sizeof(float)
                           + (size_t)NW * 256 * sizeof(u64);
    cudaFuncSetAttribute(attn_kernel, cudaFuncAttributeMaxDynamicSharedMemorySize, (int)attn_smem);

    ln_kernel<<<NTOK/8, 256>>>(tokens, ln_w, ln_b);
    gemm_qkv<<<dim3(NTOK/128, 6), 256>>>(wq, wk, wv);
    attn_kernel<<<dim3(TT/QT, BB*HH), 256, attn_smem>>>(lq1, lk1, lq2, lk2, sigS, sigN, hnw, hnb);
    gemm_out<<<dim3(NTOK/128, 1), 256>>>(wo, tokens, out);
}

// round 6
// speedup vs baseline: 1.5451x; 1.1651x over previous
#include <cuda_runtime.h>
#include <math.h>

// ---------------- problem constants ----------------
#define TT 2048
#define BB 8
#define DD 128
#define HH 4
#define NTOK (BB*TT)          // 16384
#define SCALE 0.17677669529663687f   // 1/sqrt(32)
#define LAMBDA_INIT 0.8f
#define LN_EPS 1e-5f

// banded attention config
#define W_MAX 80
#define QT 64
#define QW 8
#define NW 8
#define KROWS (QT + 2*W_MAX + 1)   // 225
#define KLD 68

typedef unsigned long long u64;
typedef unsigned int u32;

// ---------------- scratch ----------------
__device__ float g_xn[NTOK*DD];
__device__ float g_y [NTOK*768];
__device__ float g_ho[NTOK*256];

// ---------------- helpers ----------------
__device__ __forceinline__ u64 pk2(float x, float y) {
    u64 r; asm("mov.b64 %0, {%1, %2};" : "=l"(r) : "f"(x), "f"(y)); return r;
}
__device__ __forceinline__ void up2(u64 v, float& x, float& y) {
    asm("mov.b64 {%0, %1}, %2;" : "=f"(x), "=f"(y) : "l"(v));
}
__device__ __forceinline__ u64 f2fma(u64 a, u64 b, u64 c) {
    u64 d; asm("fma.rn.f32x2 %0, %1, %2, %3;" : "=l"(d) : "l"(a), "l"(b), "l"(c));
    return d;
}
__device__ __forceinline__ float warpsum(float v) {
    #pragma unroll
    for (int o = 16; o; o >>= 1) v += __shfl_xor_sync(0xffffffffu, v, o);
    return v;
}
__device__ __forceinline__ u32 tf32_rnd(float x) {
    u32 r; asm("cvt.rna.tf32.f32 %0, %1;" : "=r"(r) : "f"(x)); return r;
}
__device__ __forceinline__ void tf32_split(float x, u32& hi, u32& lo) {
    hi = tf32_rnd(x);
    lo = tf32_rnd(x - __uint_as_float(hi));
}
__device__ __forceinline__ void mma_tf32(float* c, u32 a0, u32 a1, u32 a2, u32 a3,
                                         u32 b0, u32 b1) {
    asm volatile(
        "mma.sync.aligned.m16n8k8.row.col.f32.tf32.tf32.f32 "
        "{%0,%1,%2,%3}, {%4,%5,%6,%7}, {%8,%9}, {%0,%1,%2,%3};"
        : "+f"(c[0]), "+f"(c[1]), "+f"(c[2]), "+f"(c[3])
        : "r"(a0), "r"(a1), "r"(a2), "r"(a3), "r"(b0), "r"(b1));
}

// ---------------- stage 1: layernorm ----------------
__global__ void ln_kernel(const float* __restrict__ tok,
                          const float* __restrict__ w,
                          const float* __restrict__ b) {
    int t = blockIdx.x * 8 + (threadIdx.x >> 5);
    int lane = threadIdx.x & 31;
    const float4* src = (const float4*)(tok + (size_t)t * DD);
    float4 x = src[lane];
    float s  = x.x + x.y + x.z + x.w;
    float sq = x.x*x.x + x.y*x.y + x.z*x.z + x.w*x.w;
    s  = warpsum(s);
    sq = warpsum(sq);
    float mu  = s * (1.0f/128.0f);
    float var = sq * (1.0f/128.0f) - mu*mu;
    float rs  = rsqrtf(var + LN_EPS);
    float4 w4 = ((const float4*)w)[lane];
    float4 b4 = ((const float4*)b)[lane];
    float4 o;
    o.x = (x.x - mu) * rs * w4.x + b4.x;
    o.y = (x.y - mu) * rs * w4.y + b4.y;
    o.z = (x.z - mu) * rs * w4.z + b4.z;
    o.w = (x.w - mu) * rs * w4.w + b4.w;
    ((float4*)(g_xn + (size_t)t * DD))[lane] = o;
}

// ---------------- 3xTF32 tensor-core GEMM core ----------------
// Block tile 128x128, 256 threads = 8 warps (2x4), warp tile 64x32.
// A in smem [128][36] (row, k) pad 36; B in smem [32][136] (k, n) pad 136.
// Fragment loads: A banks 4g+t (unique), B banks 8t+g (unique).
template<int KTOT, int LDA_G, int LDB_G, bool RESID>
__device__ __forceinline__ void gemm_tc_body(
    const float* __restrict__ Ag,   // [M][LDA_G] at row m0
    const float* __restrict__ Bg,   // [KTOT][LDB_G] at col offset nb
    float* __restrict__ Cg,         // [M][LDC] at (m0, n0c)
    const float* __restrict__ Rg,   // residual (same layout as Cg) or null
    int ldc)
{
    __shared__ __align__(16) float As[128][36];
    __shared__ __align__(16) float Bs[32][136];

    int tid = threadIdx.x;
    int lane = tid & 31, wid = tid >> 5;
    int g = lane >> 2, t = lane & 3;
    int warp_m = (wid >> 2) * 64;
    int warp_n = (wid & 3) * 32;

    float acc[4][4][4];
    #pragma unroll
    for (int i = 0; i < 4; i++)
        #pragma unroll
        for (int j = 0; j < 4; j++)
            #pragma unroll
            for (int r = 0; r < 4; r++) acc[i][j][r] = 0.0f;

    int a_row = tid >> 1;
    int a_c4  = (tid & 1) * 4;
    int b_row = tid >> 3;
    int b_c4  = tid & 7;

    for (int k0 = 0; k0 < KTOT; k0 += 32) {
        #pragma unroll
        for (int i = 0; i < 4; i++) {
            float4 a4 = *(const float4*)&Ag[(size_t)a_row*LDA_G + k0 + (a_c4 + i)*4];
            *(float4*)&As[a_row][(a_c4 + i)*4] = a4;
        }
        #pragma unroll
        for (int i = 0; i < 4; i++) {
            float4 b4 = *(const float4*)&Bg[(size_t)(k0 + b_row)*LDB_G + (b_c4 + i*8)*4];
            *(float4*)&Bs[b_row][(b_c4 + i*8)*4] = b4;
        }
        __syncthreads();

        #pragma unroll
        for (int kk = 0; kk < 4; kk++) {
            int kb = kk*8;
            u32 bhi[4][2], blo[4][2];
            #pragma unroll
            for (int nt = 0; nt < 4; nt++) {
                int n = warp_n + nt*8 + g;
                tf32_split(Bs[kb + t][n],     bhi[nt][0], blo[nt][0]);
                tf32_split(Bs[kb + t + 4][n], bhi[nt][1], blo[nt][1]);
            }
            #pragma unroll
            for (int mt = 0; mt < 4; mt++) {
                int m = warp_m + mt*16;
                u32 ah[4], al[4];
                tf32_split(As[m + g][kb + t],         ah[0], al[0]);
                tf32_split(As[m + g + 8][kb + t],     ah[1], al[1]);
                tf32_split(As[m + g][kb + t + 4],     ah[2], al[2]);
                tf32_split(As[m + g + 8][kb + t + 4], ah[3], al[3]);
                #pragma unroll
                for (int nt = 0; nt < 4; nt++) {
                    mma_tf32(acc[mt][nt], ah[0], ah[1], ah[2], ah[3], bhi[nt][0], bhi[nt][1]);
                    mma_tf32(acc[mt][nt], ah[0], ah[1], ah[2], ah[3], blo[nt][0], blo[nt][1]);
                    mma_tf32(acc[mt][nt], al[0], al[1], al[2], al[3], bhi[nt][0], bhi[nt][1]);
                }
            }
        }
        __syncthreads();
    }

    #pragma unroll
    for (int mt = 0; mt < 4; mt++) {
        #pragma unroll
        for (int nt = 0; nt < 4; nt++) {
            int r0 = warp_m + mt*16 + g;
            int col = warp_n + nt*8 + 2*t;
            float* d0 = Cg + (size_t)r0*ldc + col;
            float* d1 = d0 + 8*ldc;
            float c0 = acc[mt][nt][0], c1 = acc[mt][nt][1];
            float c2 = acc[mt][nt][2], c3 = acc[mt][nt][3];
            if (RESID) {
                const float* s0 = Rg + (size_t)r0*ldc + col;
                const float* s1 = s0 + 8*ldc;
                float2 t0 = *(const float2*)s0;
                float2 t1 = *(const float2*)s1;
                c0 += t0.x; c1 += t0.y; c2 += t1.x; c3 += t1.y;
            }
            *(float2*)d0 = make_float2(c0, c1);
            *(float2*)d1 = make_float2(c2, c3);
        }
    }
}

// ---------------- stage 2: QKV gemm (16384x128 @ 128x768) ----------------
__global__ void __launch_bounds__(256)
gemm_qkv(const float* __restrict__ wq,
         const float* __restrict__ wk,
         const float* __restrict__ wv) {
    int m0 = blockIdx.x * 128;
    int n0 = blockIdx.y * 128;
    const float* Bsrc; int nb;
    if (n0 < 256)      { Bsrc = wq; nb = n0; }
    else if (n0 < 512) { Bsrc = wk; nb = n0 - 256; }
    else               { Bsrc = wv; nb = n0 - 512; }
    gemm_tc_body<128, 128, 256, false>(
        g_xn + (size_t)m0*128, Bsrc + nb,
        g_y + (size_t)m0*768 + n0, nullptr, 768);
}

// ---------------- stage 4: output gemm (16384x256 @ 256x128) + residual ----------------
__global__ void __launch_bounds__(256)
gemm_out(const float* __restrict__ wo,
         const float* __restrict__ tok,
         float* __restrict__ out) {
    int m0 = blockIdx.x * 128;
    gemm_tc_body<256, 256, 128, true>(
        g_ho + (size_t)m0*256, wo,
        out + (size_t)m0*128, tok + (size_t)m0*128, 128);
}

// ---------------- stage 3: banded differential attention (unchanged R5) ----------------
__global__ void __launch_bounds__(256, 1)
attn_kernel(const float* __restrict__ lq1, const float* __restrict__ lk1,
            const float* __restrict__ lq2, const float* __restrict__ lk2,
            const float* __restrict__ sigS, const float* __restrict__ sigN,
            const float* __restrict__ hnw,  const float* __restrict__ hnb) {
    extern __shared__ float sm[];
    float* Ksm = sm;
    float* Vsm = Ksm + KROWS*KLD;
    float* Qsm = Vsm + KROWS*64;
    u64*   Pb  = (u64*)(Qsm + QT*64);
    __shared__ float s_lam;

    int tid = threadIdx.x;
    int bh  = blockIdx.y;
    int b   = bh >> 2;
    int h   = bh & 3;
    int q0  = blockIdx.x * QT;

    float ss = fmaxf(sigS[0], 1.0f), sn = fmaxf(sigN[0], 1.0f);
    float c1 = -0.5f / (ss*ss);
    float c2 = -0.5f / (sn*sn);
    int Wn = (int)ceilf(8.0f * fmaxf(ss, sn)); if (Wn > W_MAX) Wn = W_MAX;
    int W1 = (int)ceilf(8.0f * ss);            if (W1 > W_MAX) W1 = W_MAX;

    int blo = q0 - Wn;          if (blo < 0) blo = 0;
    int bhi = q0 + QT - 1 + Wn; if (bhi > TT-1) bhi = TT-1;
    int nrows = bhi - blo + 1;

    const float* ybase = g_y + (size_t)(b*TT) * 768;

    for (int idx = tid; idx < nrows*64; idx += 256) {
        int r = idx >> 6, d = idx & 63;
        const float* row = ybase + (size_t)(blo + r)*768 + h*64;
        Ksm[r*KLD + d] = row[256 + d];
        float v = row[512 + d];
        int dd = (d < 32) ? (2*d) : (2*(d-32) + 1);
        Vsm[r*64 + dd] = v;
    }
    for (int idx = tid; idx < QT*64; idx += 256) {
        int r = idx >> 6, d = idx & 63;
        Qsm[idx] = ybase[(size_t)(q0 + r)*768 + h*64 + d];
    }
    if (tid == 0) {
        float d1 = 0.0f, d2 = 0.0f;
        #pragma unroll
        for (int i = 0; i < 32; i++) { d1 += lq1[i]*lk1[i]; d2 += lq2[i]*lk2[i]; }
        s_lam = __expf(d1) - __expf(d2) + LAMBDA_INIT;
    }
    __syncthreads();
    float lam = s_lam;

    int w = tid >> 5, lane = tid & 31;
    int i0 = q0 + w*QW;
    int jlo = i0 - Wn;           if (jlo < blo) jlo = blo;
    int jhi = i0 + QW - 1 + Wn;  if (jhi > bhi) jhi = bhi;
    int m1lo = i0 - W1, m1hi = i0 + QW - 1 + W1;

    u64* p1w = Pb + w*256;
    u64* p2w = p1w + 128;

    u64 o1x[4], o1y[4], o2x[4], o2y[4];
    float l1[QW], l2[QW];
    #pragma unroll
    for (int i = 0; i < 4; i++) { o1x[i]=0ull; o1y[i]=0ull; o2x[i]=0ull; o2y[i]=0ull; }
    #pragma unroll
    for (int q = 0; q < QW; q++) { l1[q] = 0.0f; l2[q] = 0.0f; }

    for (int jc = jlo; jc <= jhi; jc += 32) {
        bool doM1 = (jc <= m1hi) && (jc + 31 >= m1lo);
        int j = jc + lane;
        bool valid = (j <= jhi);
        int r = (valid ? j : jhi) - blo;
        const ulonglong2* kr = (const ulonglong2*)(Ksm + r*KLD);
        float relb = (float)(j - i0);

        u64 a2[QW];
        #pragma unroll
        for (int q = 0; q < QW; q++) a2[q] = 0ull;
        #pragma unroll
        for (int dc = 8; dc < 16; dc++) {
            ulonglong2 k2 = kr[dc];
            #pragma unroll
            for (int q = 0; q < QW; q++) {
                ulonglong2 q2 = *(const ulonglong2*)(Qsm + (w*QW + q)*64 + dc*4);
                a2[q] = f2fma(k2.x, q2.x, a2[q]);
                a2[q] = f2fma(k2.y, q2.y, a2[q]);
            }
        }
        float e2[QW];
        #pragma unroll
        for (int q = 0; q < QW; q++) {
            float rel = relb - (float)q, rr = rel*rel;
            float lo, hi; up2(a2[q], lo, hi);
            float s = (lo + hi)*SCALE + rr*c2;
            e2[q] = valid ? __expf(s) : 0.0f;
            l2[q] += e2[q];
        }
        ((ulonglong2*)p2w)[lane*2]     = make_ulonglong2(pk2(e2[0],e2[1]), pk2(e2[2],e2[3]));
        ((ulonglong2*)p2w)[lane*2 + 1] = make_ulonglong2(pk2(e2[4],e2[5]), pk2(e2[6],e2[7]));

        if (doM1) {
            u64 a1[QW];
            #pragma unroll
            for (int q = 0; q < QW; q++) a1[q] = 0ull;
            #pragma unroll
            for (int dc = 0; dc < 8; dc++) {
                ulonglong2 k2 = kr[dc];
                #pragma unroll
                for (int q = 0; q < QW; q++) {
                    ulonglong2 q2 = *(const ulonglong2*)(Qsm + (w*QW + q)*64 + dc*4);
                    a1[q] = f2fma(k2.x, q2.x, a1[q]);
                    a1[q] = f2fma(k2.y, q2.y, a1[q]);
                }
            }
            float e1[QW];
            #pragma unroll
            for (int q = 0; q < QW; q++) {
                float rel = relb - (float)q, rr = rel*rel;
                float lo, hi; up2(a1[q], lo, hi);
                float s = (lo + hi)*SCALE + rr*c1;
                e1[q] = valid ? __expf(s) : 0.0f;
                l1[q] += e1[q];
            }
            ((ulonglong2*)p1w)[lane*2]     = make_ulonglong2(pk2(e1[0],e1[1]), pk2(e1[2],e1[3]));
            ((ulonglong2*)p1w)[lane*2 + 1] = make_ulonglong2(pk2(e1[4],e1[5]), pk2(e1[6],e1[7]));
        }
        __syncwarp();

        int cnt = jhi - jc + 1; if (cnt > 32) cnt = 32;
        const float2* vb = (const float2*)(Vsm + (jc - blo)*64);
        const ulonglong2* P1 = (const ulonglong2*)p1w;
        const ulonglong2* P2 = (const ulonglong2*)p2w;
        if (doM1) {
            for (int jj = 0; jj < cnt; jj++) {
                float2 v = vb[jj*32 + lane];
                u64 vx = pk2(v.x, v.x), vy = pk2(v.y, v.y);
                ulonglong2 pa = P1[jj*2], pb = P1[jj*2 + 1];
                ulonglong2 qa = P2[jj*2], qb = P2[jj*2 + 1];
                o1x[0] = f2fma(pa.x, vx, o1x[0]);  o1y[0] = f2fma(pa.x, vy, o1y[0]);
                o1x[1] = f2fma(pa.y, vx, o1x[1]);  o1y[1] = f2fma(pa.y, vy, o1y[1]);
                o1x[2] = f2fma(pb.x, vx, o1x[2]);  o1y[2] = f2fma(pb.x, vy, o1y[2]);
                o1x[3] = f2fma(pb.y, vx, o1x[3]);  o1y[3] = f2fma(pb.y, vy, o1y[3]);
                o2x[0] = f2fma(qa.x, vx, o2x[0]);  o2y[0] = f2fma(qa.x, vy, o2y[0]);
                o2x[1] = f2fma(qa.y, vx, o2x[1]);  o2y[1] = f2fma(qa.y, vy, o2y[1]);
                o2x[2] = f2fma(qb.x, vx, o2x[2]);  o2y[2] = f2fma(qb.x, vy, o2y[2]);
                o2x[3] = f2fma(qb.y, vx, o2x[3]);  o2y[3] = f2fma(qb.y, vy, o2y[3]);
            }
        } else {
            for (int jj = 0; jj < cnt; jj++) {
                float2 v = vb[jj*32 + lane];
                u64 vx = pk2(v.x, v.x), vy = pk2(v.y, v.y);
                ulonglong2 qa = P2[jj*2], qb = P2[jj*2 + 1];
                o2x[0] = f2fma(qa.x, vx, o2x[0]);  o2y[0] = f2fma(qa.x, vy, o2y[0]);
                o2x[1] = f2fma(qa.y, vx, o2x[1]);  o2y[1] = f2fma(qa.y, vy, o2y[1]);
                o2x[2] = f2fma(qb.x, vx, o2x[2]);  o2y[2] = f2fma(qb.x, vy, o2y[2]);
                o2x[3] = f2fma(qb.y, vx, o2x[3]);  o2y[3] = f2fma(qb.y, vy, o2y[3]);
            }
        }
        __syncwarp();
    }

    float hw0 = hnw[lane], hw1 = hnw[lane+32];
    float hb0 = hnb[lane], hb1 = hnb[lane+32];
    float post = 1.0f - LAMBDA_INIT;
    #pragma unroll
    for (int qp = 0; qp < 4; qp++) {
        float x1a, x1b, y1a, y1b, x2a, x2b, y2a, y2b;
        up2(o1x[qp], x1a, x1b);  up2(o1y[qp], y1a, y1b);
        up2(o2x[qp], x2a, x2b);  up2(o2y[qp], y2a, y2b);
        #pragma unroll
        for (int sub = 0; sub < 2; sub++) {
            int q = qp*2 + sub;
            float x1 = sub ? x1b : x1a, y1 = sub ? y1b : y1a;
            float x2 = sub ? x2b : x2a, y2 = sub ? y2b : y2a;
            float L1 = warpsum(l1[q]);
            float L2 = warpsum(l2[q]);
            float il1 = 1.0f / L1;
            float il2 = lam  / L2;
            float ox = x1*il1 - x2*il2;
            float oy = y1*il1 - y2*il2;
            float s  = warpsum(ox + oy);
            float sq = warpsum(ox*ox + oy*oy);
            float mu  = s * (1.0f/64.0f);
            float var = sq * (1.0f/64.0f) - mu*mu;
            float rs  = rsqrtf(var + LN_EPS);
            float y0 = ((ox - mu)*rs*hw0 + hb0) * post;
            float y1o = ((oy - mu)*rs*hw1 + hb1) * post;
            int i = i0 + q;
            float* dst = g_ho + (size_t)(b*TT + i)*256 + h*64;
            dst[lane]      = y0;
            dst[lane + 32] = y1o;
        }
    }
}

// ---------------- launch ----------------
extern "C" void kernel_launch(void* const* d_in, const int* in_sizes, int n_in,
                              void* d_out, int out_size) {
    const float* tokens = (const float*)d_in[0];
    const float* ln_w   = (const float*)d_in[1];
    const float* ln_b   = (const float*)d_in[2];
    const float* wq     = (const float*)d_in[3];
    const float* wk     = (const float*)d_in[4];
    const float* wv     = (const float*)d_in[5];
    const float* wo     = (const float*)d_in[6];
    const float* lq1    = (const float*)d_in[7];
    const float* lk1    = (const float*)d_in[8];
    const float* lq2    = (const float*)d_in[9];
    const float* lk2    = (const float*)d_in[10];
    const float* sigS   = (const float*)d_in[11];
    const float* sigN   = (const float*)d_in[12];
    const float* hnw    = (const float*)d_in[13];
    const float* hnb    = (const float*)d_in[14];
    float* out = (float*)d_out;

    const size_t attn_smem = (size_t)(KROWS*KLD + KROWS*64 + QT*64) * sizeof(float)
                           + (size_t)NW * 256 * sizeof(u64);
    cudaFuncSetAttribute(attn_kernel, cudaFuncAttributeMaxDynamicSharedMemorySize, (int)attn_smem);

    ln_kernel<<<NTOK/8, 256>>>(tokens, ln_w, ln_b);
    gemm_qkv<<<dim3(NTOK/128, 6), 256>>>(wq, wk, wv);
    attn_kernel<<<dim3(TT/QT, BB*HH), 256, attn_smem>>>(lq1, lk1, lq2, lk2, sigS, sigN, hnw, hnb);
    gemm_out<<<dim3(NTOK/128, 1), 256>>>(wo, tokens, out);
}

// round 7
// speedup vs baseline: 1.5853x; 1.0260x over previous
#include <cuda_runtime.h>
#include <math.h>

// ---------------- problem constants ----------------
#define TT 2048
#define BB 8
#define DD 128
#define HH 4
#define NTOK (BB*TT)          // 16384
#define SCALE 0.17677669529663687f   // 1/sqrt(32)
#define LAMBDA_INIT 0.8f
#define LN_EPS 1e-5f

// banded attention config
#define W_MAX 80
#define QT 64
#define QW 8
#define NW 8
#define KROWS (QT + 2*W_MAX + 1)   // 225
#define KLD 68

typedef unsigned long long u64;
typedef unsigned int u32;

// ---------------- scratch ----------------
__device__ float g_xn[NTOK*DD];
__device__ float g_y [NTOK*768];
__device__ float g_ho[NTOK*256];

// ---------------- helpers ----------------
__device__ __forceinline__ u64 pk2(float x, float y) {
    u64 r; asm("mov.b64 %0, {%1, %2};" : "=l"(r) : "f"(x), "f"(y)); return r;
}
__device__ __forceinline__ void up2(u64 v, float& x, float& y) {
    asm("mov.b64 {%0, %1}, %2;" : "=f"(x), "=f"(y) : "l"(v));
}
__device__ __forceinline__ u64 f2fma(u64 a, u64 b, u64 c) {
    u64 d; asm("fma.rn.f32x2 %0, %1, %2, %3;" : "=l"(d) : "l"(a), "l"(b), "l"(c));
    return d;
}
__device__ __forceinline__ float warpsum(float v) {
    #pragma unroll
    for (int o = 16; o; o >>= 1) v += __shfl_xor_sync(0xffffffffu, v, o);
    return v;
}
__device__ __forceinline__ u32 tf32_rnd(float x) {
    u32 r; asm("cvt.rna.tf32.f32 %0, %1;" : "=r"(r) : "f"(x)); return r;
}
__device__ __forceinline__ void mma_tf32(float* c, u32 a0, u32 a1, u32 a2, u32 a3,
                                         u32 b0, u32 b1) {
    asm volatile(
        "mma.sync.aligned.m16n8k8.row.col.f32.tf32.tf32.f32 "
        "{%0,%1,%2,%3}, {%4,%5,%6,%7}, {%8,%9}, {%0,%1,%2,%3};"
        : "+f"(c[0]), "+f"(c[1]), "+f"(c[2]), "+f"(c[3])
        : "r"(a0), "r"(a1), "r"(a2), "r"(a3), "r"(b0), "r"(b1));
}

// ---------------- stage 1: layernorm ----------------
__global__ void ln_kernel(const float* __restrict__ tok,
                          const float* __restrict__ w,
                          const float* __restrict__ b) {
    int t = blockIdx.x * 8 + (threadIdx.x >> 5);
    int lane = threadIdx.x & 31;
    const float4* src = (const float4*)(tok + (size_t)t * DD);
    float4 x = src[lane];
    float s  = x.x + x.y + x.z + x.w;
    float sq = x.x*x.x + x.y*x.y + x.z*x.z + x.w*x.w;
    s  = warpsum(s);
    sq = warpsum(sq);
    float mu  = s * (1.0f/128.0f);
    float var = sq * (1.0f/128.0f) - mu*mu;
    float rs  = rsqrtf(var + LN_EPS);
    float4 w4 = ((const float4*)w)[lane];
    float4 b4 = ((const float4*)b)[lane];
    float4 o;
    o.x = (x.x - mu) * rs * w4.x + b4.x;
    o.y = (x.y - mu) * rs * w4.y + b4.y;
    o.z = (x.z - mu) * rs * w4.z + b4.z;
    o.w = (x.w - mu) * rs * w4.w + b4.w;
    ((float4*)(g_xn + (size_t)t * DD))[lane] = o;
}

// ---------------- 3xTF32 tensor-core GEMM core (hi/lo pre-split in smem) ----------------
// Block tile MT x 128, 256 threads = 8 warps (2x4 for MT=128, warp tile MT/2 x 32).
// A smem [MT][36] hi+lo; B smem [32][136] hi+lo. Loader converts each element once.
// Fragment banks: A 4g+t (unique), B 8t+g (unique) -> conflict-free.
template<int MT, int KTOT, int LDA_G, int LDB_G, bool RESID>
__device__ __forceinline__ void gemm_tc_body(
    const float* __restrict__ Ag,   // [..][LDA_G] at row m0
    const float* __restrict__ Bg,   // [KTOT][LDB_G] at col offset nb
    float* __restrict__ Cg,         // [..][ldc] at (m0, n0)
    const float* __restrict__ Rg,   // residual or null
    int ldc)
{
    constexpr int MTILES = MT / 32;          // m16 tiles per warp
    extern __shared__ __align__(16) float smg[];
    float* AsH = smg;                        // MT*36
    float* AsL = AsH + MT*36;
    float* BsH = AsL + MT*36;                // 32*136
    float* BsL = BsH + 32*136;

    int tid = threadIdx.x;
    int lane = tid & 31, wid = tid >> 5;
    int g = lane >> 2, t = lane & 3;
    int warp_m = (wid >> 2) * (MT/2);
    int warp_n = (wid & 3) * 32;

    float acc[MTILES][4][4];
    #pragma unroll
    for (int i = 0; i < MTILES; i++)
        #pragma unroll
        for (int j = 0; j < 4; j++)
            #pragma unroll
            for (int r = 0; r < 4; r++) acc[i][j][r] = 0.0f;

    constexpr int TPR  = 256 / MT;           // loader threads per A row
    constexpr int AC4  = 32 / TPR / 4;       // float4s per thread per A row
    int a_row = tid / TPR;
    int a_c0  = (tid % TPR) * (32 / TPR);
    int b_row = tid >> 3, b_c4 = tid & 7;

    for (int k0 = 0; k0 < KTOT; k0 += 32) {
        #pragma unroll
        for (int i = 0; i < AC4; i++) {
            int c = a_c0 + i*4;
            float4 a4 = *(const float4*)&Ag[(size_t)a_row*LDA_G + k0 + c];
            u32 h0 = tf32_rnd(a4.x), h1 = tf32_rnd(a4.y);
            u32 h2 = tf32_rnd(a4.z), h3 = tf32_rnd(a4.w);
            float4 hi = make_float4(__uint_as_float(h0), __uint_as_float(h1),
                                    __uint_as_float(h2), __uint_as_float(h3));
            float4 lo = make_float4(a4.x - hi.x, a4.y - hi.y,
                                    a4.z - hi.z, a4.w - hi.w);
            *(float4*)&AsH[a_row*36 + c] = hi;
            *(float4*)&AsL[a_row*36 + c] = lo;
        }
        #pragma unroll
        for (int i = 0; i < 4; i++) {
            int c = (b_c4 + i*8) * 4;
            float4 b4 = *(const float4*)&Bg[(size_t)(k0 + b_row)*LDB_G + c];
            u32 h0 = tf32_rnd(b4.x), h1 = tf32_rnd(b4.y);
            u32 h2 = tf32_rnd(b4.z), h3 = tf32_rnd(b4.w);
            float4 hi = make_float4(__uint_as_float(h0), __uint_as_float(h1),
                                    __uint_as_float(h2), __uint_as_float(h3));
            float4 lo = make_float4(b4.x - hi.x, b4.y - hi.y,
                                    b4.z - hi.z, b4.w - hi.w);
            *(float4*)&BsH[b_row*136 + c] = hi;
            *(float4*)&BsL[b_row*136 + c] = lo;
        }
        __syncthreads();

        #pragma unroll
        for (int kk = 0; kk < 4; kk++) {
            int kb = kk*8;
            u32 bh[4][2], bl[4][2];
            #pragma unroll
            for (int nt = 0; nt < 4; nt++) {
                int n = warp_n + nt*8 + g;
                bh[nt][0] = __float_as_uint(BsH[(kb + t)*136 + n]);
                bh[nt][1] = __float_as_uint(BsH[(kb + t + 4)*136 + n]);
                bl[nt][0] = __float_as_uint(BsL[(kb + t)*136 + n]);
                bl[nt][1] = __float_as_uint(BsL[(kb + t + 4)*136 + n]);
            }
            #pragma unroll
            for (int mt = 0; mt < MTILES; mt++) {
                int m = warp_m + mt*16;
                u32 ah[4], al[4];
                ah[0] = __float_as_uint(AsH[(m + g)*36 + kb + t]);
                ah[1] = __float_as_uint(AsH[(m + g + 8)*36 + kb + t]);
                ah[2] = __float_as_uint(AsH[(m + g)*36 + kb + t + 4]);
                ah[3] = __float_as_uint(AsH[(m + g + 8)*36 + kb + t + 4]);
                al[0] = __float_as_uint(AsL[(m + g)*36 + kb + t]);
                al[1] = __float_as_uint(AsL[(m + g + 8)*36 + kb + t]);
                al[2] = __float_as_uint(AsL[(m + g)*36 + kb + t + 4]);
                al[3] = __float_as_uint(AsL[(m + g + 8)*36 + kb + t + 4]);
                #pragma unroll
                for (int nt = 0; nt < 4; nt++) {
                    mma_tf32(acc[mt][nt], ah[0], ah[1], ah[2], ah[3], bh[nt][0], bh[nt][1]);
                    mma_tf32(acc[mt][nt], ah[0], ah[1], ah[2], ah[3], bl[nt][0], bl[nt][1]);
                    mma_tf32(acc[mt][nt], al[0], al[1], al[2], al[3], bh[nt][0], bh[nt][1]);
                }
            }
        }
        __syncthreads();
    }

    #pragma unroll
    for (int mt = 0; mt < MTILES; mt++) {
        #pragma unroll
        for (int nt = 0; nt < 4; nt++) {
            int r0 = warp_m + mt*16 + g;
            int col = warp_n + nt*8 + 2*t;
            float* d0 = Cg + (size_t)r0*ldc + col;
            float* d1 = d0 + 8*ldc;
            float c0 = acc[mt][nt][0], c1 = acc[mt][nt][1];
            float c2 = acc[mt][nt][2], c3 = acc[mt][nt][3];
            if (RESID) {
                const float* s0 = Rg + (size_t)r0*ldc + col;
                const float* s1 = s0 + 8*ldc;
                float2 t0 = *(const float2*)s0;
                float2 t1 = *(const float2*)s1;
                c0 += t0.x; c1 += t0.y; c2 += t1.x; c3 += t1.y;
            }
            *(float2*)d0 = make_float2(c0, c1);
            *(float2*)d1 = make_float2(c2, c3);
        }
    }
}

#define QKV_SMEM ((128*36*2 + 32*136*2) * 4)   // 71680 B
#define OUT_SMEM ((64*36*2 + 32*136*2) * 4)    // 53248 B

// ---------------- stage 2: QKV gemm (16384x128 @ 128x768) ----------------
__global__ void __launch_bounds__(256, 2)
gemm_qkv(const float* __restrict__ wq,
         const float* __restrict__ wk,
         const float* __restrict__ wv) {
    int m0 = blockIdx.x * 128;
    int n0 = blockIdx.y * 128;
    const float* Bsrc; int nb;
    if (n0 < 256)      { Bsrc = wq; nb = n0; }
    else if (n0 < 512) { Bsrc = wk; nb = n0 - 256; }
    else               { Bsrc = wv; nb = n0 - 512; }
    gemm_tc_body<128, 128, 128, 256, false>(
        g_xn + (size_t)m0*128, Bsrc + nb,
        g_y + (size_t)m0*768 + n0, nullptr, 768);
}

// ---------------- stage 4: output gemm (16384x256 @ 256x128) + residual ----------------
__global__ void __launch_bounds__(256, 2)
gemm_out(const float* __restrict__ wo,
         const float* __restrict__ tok,
         float* __restrict__ out) {
    int m0 = blockIdx.x * 64;
    gemm_tc_body<64, 256, 256, 128, true>(
        g_ho + (size_t)m0*256, wo,
        out + (size_t)m0*128, tok + (size_t)m0*128, 128);
}

// ---------------- stage 3: banded differential attention (unchanged R6) ----------------
__global__ void __launch_bounds__(256, 1)
attn_kernel(const float* __restrict__ lq1, const float* __restrict__ lk1,
            const float* __restrict__ lq2, const float* __restrict__ lk2,
            const float* __restrict__ sigS, const float* __restrict__ sigN,
            const float* __restrict__ hnw,  const float* __restrict__ hnb) {
    extern __shared__ float sm[];
    float* Ksm = sm;
    float* Vsm = Ksm + KROWS*KLD;
    float* Qsm = Vsm + KROWS*64;
    u64*   Pb  = (u64*)(Qsm + QT*64);
    __shared__ float s_lam;

    int tid = threadIdx.x;
    int bh  = blockIdx.y;
    int b   = bh >> 2;
    int h   = bh & 3;
    int q0  = blockIdx.x * QT;

    float ss = fmaxf(sigS[0], 1.0f), sn = fmaxf(sigN[0], 1.0f);
    float c1 = -0.5f / (ss*ss);
    float c2 = -0.5f / (sn*sn);
    int Wn = (int)ceilf(8.0f * fmaxf(ss, sn)); if (Wn > W_MAX) Wn = W_MAX;
    int W1 = (int)ceilf(8.0f * ss);            if (W1 > W_MAX) W1 = W_MAX;

    int blo = q0 - Wn;          if (blo < 0) blo = 0;
    int bhi = q0 + QT - 1 + Wn; if (bhi > TT-1) bhi = TT-1;
    int nrows = bhi - blo + 1;

    const float* ybase = g_y + (size_t)(b*TT) * 768;

    for (int idx = tid; idx < nrows*64; idx += 256) {
        int r = idx >> 6, d = idx & 63;
        const float* row = ybase + (size_t)(blo + r)*768 + h*64;
        Ksm[r*KLD + d] = row[256 + d];
        float v = row[512 + d];
        int dd = (d < 32) ? (2*d) : (2*(d-32) + 1);
        Vsm[r*64 + dd] = v;
    }
    for (int idx = tid; idx < QT*64; idx += 256) {
        int r = idx >> 6, d = idx & 63;
        Qsm[idx] = ybase[(size_t)(q0 + r)*768 + h*64 + d];
    }
    if (tid == 0) {
        float d1 = 0.0f, d2 = 0.0f;
        #pragma unroll
        for (int i = 0; i < 32; i++) { d1 += lq1[i]*lk1[i]; d2 += lq2[i]*lk2[i]; }
        s_lam = __expf(d1) - __expf(d2) + LAMBDA_INIT;
    }
    __syncthreads();
    float lam = s_lam;

    int w = tid >> 5, lane = tid & 31;
    int i0 = q0 + w*QW;
    int jlo = i0 - Wn;           if (jlo < blo) jlo = blo;
    int jhi = i0 + QW - 1 + Wn;  if (jhi > bhi) jhi = bhi;
    int m1lo = i0 - W1, m1hi = i0 + QW - 1 + W1;

    u64* p1w = Pb + w*256;
    u64* p2w = p1w + 128;

    u64 o1x[4], o1y[4], o2x[4], o2y[4];
    float l1[QW], l2[QW];
    #pragma unroll
    for (int i = 0; i < 4; i++) { o1x[i]=0ull; o1y[i]=0ull; o2x[i]=0ull; o2y[i]=0ull; }
    #pragma unroll
    for (int q = 0; q < QW; q++) { l1[q] = 0.0f; l2[q] = 0.0f; }

    for (int jc = jlo; jc <= jhi; jc += 32) {
        bool doM1 = (jc <= m1hi) && (jc + 31 >= m1lo);
        int j = jc + lane;
        bool valid = (j <= jhi);
        int r = (valid ? j : jhi) - blo;
        const ulonglong2* kr = (const ulonglong2*)(Ksm + r*KLD);
        float relb = (float)(j - i0);

        u64 a2[QW];
        #pragma unroll
        for (int q = 0; q < QW; q++) a2[q] = 0ull;
        #pragma unroll
        for (int dc = 8; dc < 16; dc++) {
            ulonglong2 k2 = kr[dc];
            #pragma unroll
            for (int q = 0; q < QW; q++) {
                ulonglong2 q2 = *(const ulonglong2*)(Qsm + (w*QW + q)*64 + dc*4);
                a2[q] = f2fma(k2.x, q2.x, a2[q]);
                a2[q] = f2fma(k2.y, q2.y, a2[q]);
            }
        }
        float e2[QW];
        #pragma unroll
        for (int q = 0; q < QW; q++) {
            float rel = relb - (float)q, rr = rel*rel;
            float lo, hi; up2(a2[q], lo, hi);
            float s = (lo + hi)*SCALE + rr*c2;
            e2[q] = valid ? __expf(s) : 0.0f;
            l2[q] += e2[q];
        }
        ((ulonglong2*)p2w)[lane*2]     = make_ulonglong2(pk2(e2[0],e2[1]), pk2(e2[2],e2[3]));
        ((ulonglong2*)p2w)[lane*2 + 1] = make_ulonglong2(pk2(e2[4],e2[5]), pk2(e2[6],e2[7]));

        if (doM1) {
            u64 a1[QW];
            #pragma unroll
            for (int q = 0; q < QW; q++) a1[q] = 0ull;
            #pragma unroll
            for (int dc = 0; dc < 8; dc++) {
                ulonglong2 k2 = kr[dc];
                #pragma unroll
                for (int q = 0; q < QW; q++) {
                    ulonglong2 q2 = *(const ulonglong2*)(Qsm + (w*QW + q)*64 + dc*4);
                    a1[q] = f2fma(k2.x, q2.x, a1[q]);
                    a1[q] = f2fma(k2.y, q2.y, a1[q]);
                }
            }
            float e1[QW];
            #pragma unroll
            for (int q = 0; q < QW; q++) {
                float rel = relb - (float)q, rr = rel*rel;
                float lo, hi; up2(a1[q], lo, hi);
                float s = (lo + hi)*SCALE + rr*c1;
                e1[q] = valid ? __expf(s) : 0.0f;
                l1[q] += e1[q];
            }
            ((ulonglong2*)p1w)[lane*2]     = make_ulonglong2(pk2(e1[0],e1[1]), pk2(e1[2],e1[3]));
            ((ulonglong2*)p1w)[lane*2 + 1] = make_ulonglong2(pk2(e1[4],e1[5]), pk2(e1[6],e1[7]));
        }
        __syncwarp();

        int cnt = jhi - jc + 1; if (cnt > 32) cnt = 32;
        const float2* vb = (const float2*)(Vsm + (jc - blo)*64);
        const ulonglong2* P1 = (const ulonglong2*)p1w;
        const ulonglong2* P2 = (const ulonglong2*)p2w;
        if (doM1) {
            for (int jj = 0; jj < cnt; jj++) {
                float2 v = vb[jj*32 + lane];
                u64 vx = pk2(v.x, v.x), vy = pk2(v.y, v.y);
                ulonglong2 pa = P1[jj*2], pb = P1[jj*2 + 1];
                ulonglong2 qa = P2[jj*2], qb = P2[jj*2 + 1];
                o1x[0] = f2fma(pa.x, vx, o1x[0]);  o1y[0] = f2fma(pa.x, vy, o1y[0]);
                o1x[1] = f2fma(pa.y, vx, o1x[1]);  o1y[1] = f2fma(pa.y, vy, o1y[1]);
                o1x[2] = f2fma(pb.x, vx, o1x[2]);  o1y[2] = f2fma(pb.x, vy, o1y[2]);
                o1x[3] = f2fma(pb.y, vx, o1x[3]);  o1y[3] = f2fma(pb.y, vy, o1y[3]);
                o2x[0] = f2fma(qa.x, vx, o2x[0]);  o2y[0] = f2fma(qa.x, vy, o2y[0]);
                o2x[1] = f2fma(qa.y, vx, o2x[1]);  o2y[1] = f2fma(qa.y, vy, o2y[1]);
                o2x[2] = f2fma(qb.x, vx, o2x[2]);  o2y[2] = f2fma(qb.x, vy, o2y[2]);
                o2x[3] = f2fma(qb.y, vx, o2x[3]);  o2y[3] = f2fma(qb.y, vy, o2y[3]);
            }
        } else {
            for (int jj = 0; jj < cnt; jj++) {
                float2 v = vb[jj*32 + lane];
                u64 vx = pk2(v.x, v.x), vy = pk2(v.y, v.y);
                ulonglong2 qa = P2[jj*2], qb = P2[jj*2 + 1];
                o2x[0] = f2fma(qa.x, vx, o2x[0]);  o2y[0] = f2fma(qa.x, vy, o2y[0]);
                o2x[1] = f2fma(qa.y, vx, o2x[1]);  o2y[1] = f2fma(qa.y, vy, o2y[1]);
                o2x[2] = f2fma(qb.x, vx, o2x[2]);  o2y[2] = f2fma(qb.x, vy, o2y[2]);
                o2x[3] = f2fma(qb.y, vx, o2x[3]);  o2y[3] = f2fma(qb.y, vy, o2y[3]);
            }
        }
        __syncwarp();
    }

    float hw0 = hnw[lane], hw1 = hnw[lane+32];
    float hb0 = hnb[lane], hb1 = hnb[lane+32];
    float post = 1.0f - LAMBDA_INIT;
    #pragma unroll
    for (int qp = 0; qp < 4; qp++) {
        float x1a, x1b, y1a, y1b, x2a, x2b, y2a, y2b;
        up2(o1x[qp], x1a, x1b);  up2(o1y[qp], y1a, y1b);
        up2(o2x[qp], x2a, x2b);  up2(o2y[qp], y2a, y2b);
        #pragma unroll
        for (int sub = 0; sub < 2; sub++) {
            int q = qp*2 + sub;
            float x1 = sub ? x1b : x1a, y1 = sub ? y1b : y1a;
            float x2 = sub ? x2b : x2a, y2 = sub ? y2b : y2a;
            float L1 = warpsum(l1[q]);
            float L2 = warpsum(l2[q]);
            float il1 = 1.0f / L1;
            float il2 = lam  / L2;
            float ox = x1*il1 - x2*il2;
            float oy = y1*il1 - y2*il2;
            float s  = warpsum(ox + oy);
            float sq = warpsum(ox*ox + oy*oy);
            float mu  = s * (1.0f/64.0f);
            float var = sq * (1.0f/64.0f) - mu*mu;
            float rs  = rsqrtf(var + LN_EPS);
            float y0 = ((ox - mu)*rs*hw0 + hb0) * post;
            float y1o = ((oy - mu)*rs*hw1 + hb1) * post;
            int i = i0 + q;
            float* dst = g_ho + (size_t)(b*TT + i)*256 + h*64;
            dst[lane]      = y0;
            dst[lane + 32] = y1o;
        }
    }
}

// ---------------- launch ----------------
extern "C" void kernel_launch(void* const* d_in, const int* in_sizes, int n_in,
                              void* d_out, int out_size) {
    const float* tokens = (const float*)d_in[0];
    const float* ln_w   = (const float*)d_in[1];
    const float* ln_b   = (const float*)d_in[2];
    const float* wq     = (const float*)d_in[3];
    const float* wk     = (const float*)d_in[4];
    const float* wv     = (const float*)d_in[5];
    const float* wo     = (const float*)d_in[6];
    const float* lq1    = (const float*)d_in[7];
    const float* lk1    = (const float*)d_in[8];
    const float* lq2    = (const float*)d_in[9];
    const float* lk2    = (const float*)d_in[10];
    const float* sigS   = (const float*)d_in[11];
    const float* sigN   = (const float*)d_in[12];
    const float* hnw    = (const float*)d_in[13];
    const float* hnb    = (const float*)d_in[14];
    float* out = (float*)d_out;

    const size_t attn_smem = (size_t)(KROWS*KLD + KROWS*64 + QT*64) * sizeof(float)
                           + (size_t)NW * 256 * sizeof(u64);
    cudaFuncSetAttribute(attn_kernel, cudaFuncAttributeMaxDynamicSharedMemorySize, (int)attn_smem);
    cudaFuncSetAttribute(gemm_qkv, cudaFuncAttributeMaxDynamicSharedMemorySize, QKV_SMEM);
    cudaFuncSetAttribute(gemm_out, cudaFuncAttributeMaxDynamicSharedMemorySize, OUT_SMEM);

    ln_kernel<<<NTOK/8, 256>>>(tokens, ln_w, ln_b);
    gemm_qkv<<<dim3(NTOK/128, 6), 256, QKV_SMEM>>>(wq, wk, wv);
    attn_kernel<<<dim3(TT/QT, BB*HH), 256, attn_smem>>>(lq1, lk1, lq2, lk2, sigS, sigN, hnw, hnb);
    gemm_out<<<NTOK/64, 256, OUT_SMEM>>>(wo, tokens, out);
}

// round 8
// speedup vs baseline: 1.6707x; 1.0539x over previous
#include <cuda_runtime.h>
#include <math.h>

// ---------------- problem constants ----------------
#define TT 2048
#define BB 8
#define DD 128
#define HH 4
#define NTOK (BB*TT)          // 16384
#define SCALE 0.17677669529663687f   // 1/sqrt(32)
#define LAMBDA_INIT 0.8f
#define LN_EPS 1e-5f

// banded attention config
#define W_MAX 80
#define QT 128                // queries per block
#define QW 8                  // queries per warp
#define NW 16                 // warps per block
#define KROWS (QT + 2*W_MAX + 1)   // 289 (sized for cap case)
#define KLD 68

typedef unsigned long long u64;
typedef unsigned int u32;

// ---------------- scratch ----------------
__device__ float g_xn[NTOK*DD];
__device__ float g_y [NTOK*768];
__device__ float g_ho[NTOK*256];

// ---------------- helpers ----------------
__device__ __forceinline__ u64 pk2(float x, float y) {
    u64 r; asm("mov.b64 %0, {%1, %2};" : "=l"(r) : "f"(x), "f"(y)); return r;
}
__device__ __forceinline__ void up2(u64 v, float& x, float& y) {
    asm("mov.b64 {%0, %1}, %2;" : "=f"(x), "=f"(y) : "l"(v));
}
__device__ __forceinline__ u64 f2fma(u64 a, u64 b, u64 c) {
    u64 d; asm("fma.rn.f32x2 %0, %1, %2, %3;" : "=l"(d) : "l"(a), "l"(b), "l"(c));
    return d;
}
__device__ __forceinline__ float warpsum(float v) {
    #pragma unroll
    for (int o = 16; o; o >>= 1) v += __shfl_xor_sync(0xffffffffu, v, o);
    return v;
}
__device__ __forceinline__ u32 tf32_rnd(float x) {
    u32 r; asm("cvt.rna.tf32.f32 %0, %1;" : "=r"(r) : "f"(x)); return r;
}
__device__ __forceinline__ void mma_tf32(float* c, u32 a0, u32 a1, u32 a2, u32 a3,
                                         u32 b0, u32 b1) {
    asm volatile(
        "mma.sync.aligned.m16n8k8.row.col.f32.tf32.tf32.f32 "
        "{%0,%1,%2,%3}, {%4,%5,%6,%7}, {%8,%9}, {%0,%1,%2,%3};"
        : "+f"(c[0]), "+f"(c[1]), "+f"(c[2]), "+f"(c[3])
        : "r"(a0), "r"(a1), "r"(a2), "r"(a3), "r"(b0), "r"(b1));
}

// ---------------- stage 1: layernorm ----------------
__global__ void ln_kernel(const float* __restrict__ tok,
                          const float* __restrict__ w,
                          const float* __restrict__ b) {
    int t = blockIdx.x * 8 + (threadIdx.x >> 5);
    int lane = threadIdx.x & 31;
    const float4* src = (const float4*)(tok + (size_t)t * DD);
    float4 x = src[lane];
    float s  = x.x + x.y + x.z + x.w;
    float sq = x.x*x.x + x.y*x.y + x.z*x.z + x.w*x.w;
    s  = warpsum(s);
    sq = warpsum(sq);
    float mu  = s * (1.0f/128.0f);
    float var = sq * (1.0f/128.0f) - mu*mu;
    float rs  = rsqrtf(var + LN_EPS);
    float4 w4 = ((const float4*)w)[lane];
    float4 b4 = ((const float4*)b)[lane];
    float4 o;
    o.x = (x.x - mu) * rs * w4.x + b4.x;
    o.y = (x.y - mu) * rs * w4.y + b4.y;
    o.z = (x.z - mu) * rs * w4.z + b4.z;
    o.w = (x.w - mu) * rs * w4.w + b4.w;
    ((float4*)(g_xn + (size_t)t * DD))[lane] = o;
}

// ---------------- 3xTF32 TC GEMM, hi/lo interleaved float2 smem ----------------
// A smem: float2 [MT][36]   (cols 0..31 = k)  -> LDS.64 gives (hi,lo) pair
// B smem: float2 [32][140]  (cols = n)        -> conflict-free phases
template<int MT, int KTOT, int LDA_G, int LDB_G, bool RESID>
__device__ __forceinline__ void gemm_tc_body(
    const float* __restrict__ Ag,
    const float* __restrict__ Bg,
    float* __restrict__ Cg,
    const float* __restrict__ Rg,
    int ldc)
{
    constexpr int MTILES = MT / 32;
    extern __shared__ __align__(16) float smg[];
    float2* As2 = (float2*)smg;              // MT*36 float2
    float2* Bs2 = As2 + MT*36;               // 32*140 float2

    int tid = threadIdx.x;
    int lane = tid & 31, wid = tid >> 5;
    int g = lane >> 2, t = lane & 3;
    int warp_m = (wid >> 2) * (MT/2);
    int warp_n = (wid & 3) * 32;

    float acc[MTILES][4][4];
    #pragma unroll
    for (int i = 0; i < MTILES; i++)
        #pragma unroll
        for (int j = 0; j < 4; j++)
            #pragma unroll
            for (int r = 0; r < 4; r++) acc[i][j][r] = 0.0f;

    constexpr int TPR = 256 / MT;
    constexpr int AC4 = 32 / TPR / 4;
    int a_row = tid / TPR;
    int a_c0  = (tid % TPR) * (32 / TPR);
    int b_row = tid >> 3, b_c4 = tid & 7;

    for (int k0 = 0; k0 < KTOT; k0 += 32) {
        #pragma unroll
        for (int i = 0; i < AC4; i++) {
            int c = a_c0 + i*4;
            float4 a4 = *(const float4*)&Ag[(size_t)a_row*LDA_G + k0 + c];
            float h0 = __uint_as_float(tf32_rnd(a4.x));
            float h1 = __uint_as_float(tf32_rnd(a4.y));
            float h2 = __uint_as_float(tf32_rnd(a4.z));
            float h3 = __uint_as_float(tf32_rnd(a4.w));
            *(float4*)&As2[a_row*36 + c]     = make_float4(h0, a4.x - h0, h1, a4.y - h1);
            *(float4*)&As2[a_row*36 + c + 2] = make_float4(h2, a4.z - h2, h3, a4.w - h3);
        }
        #pragma unroll
        for (int i = 0; i < 4; i++) {
            int c = (b_c4 + i*8) * 4;
            float4 b4 = *(const float4*)&Bg[(size_t)(k0 + b_row)*LDB_G + c];
            float h0 = __uint_as_float(tf32_rnd(b4.x));
            float h1 = __uint_as_float(tf32_rnd(b4.y));
            float h2 = __uint_as_float(tf32_rnd(b4.z));
            float h3 = __uint_as_float(tf32_rnd(b4.w));
            *(float4*)&Bs2[b_row*140 + c]     = make_float4(h0, b4.x - h0, h1, b4.y - h1);
            *(float4*)&Bs2[b_row*140 + c + 2] = make_float4(h2, b4.z - h2, h3, b4.w - h3);
        }
        __syncthreads();

        #pragma unroll
        for (int kk = 0; kk < 4; kk++) {
            int kb = kk*8;
            u32 bh[4][2], bl[4][2];
            #pragma unroll
            for (int nt = 0; nt < 4; nt++) {
                int n = warp_n + nt*8 + g;
                float2 p0 = Bs2[(kb + t)*140 + n];
                float2 p1 = Bs2[(kb + t + 4)*140 + n];
                bh[nt][0] = __float_as_uint(p0.x); bl[nt][0] = __float_as_uint(p0.y);
                bh[nt][1] = __float_as_uint(p1.x); bl[nt][1] = __float_as_uint(p1.y);
            }
            #pragma unroll
            for (int mt = 0; mt < MTILES; mt++) {
                int m = warp_m + mt*16;
                float2 q0 = As2[(m + g)*36 + kb + t];
                float2 q1 = As2[(m + g + 8)*36 + kb + t];
                float2 q2 = As2[(m + g)*36 + kb + t + 4];
                float2 q3 = As2[(m + g + 8)*36 + kb + t + 4];
                u32 ah[4] = { __float_as_uint(q0.x), __float_as_uint(q1.x),
                              __float_as_uint(q2.x), __float_as_uint(q3.x) };
                u32 al[4] = { __float_as_uint(q0.y), __float_as_uint(q1.y),
                              __float_as_uint(q2.y), __float_as_uint(q3.y) };
                #pragma unroll
                for (int nt = 0; nt < 4; nt++) {
                    mma_tf32(acc[mt][nt], ah[0], ah[1], ah[2], ah[3], bh[nt][0], bh[nt][1]);
                    mma_tf32(acc[mt][nt], ah[0], ah[1], ah[2], ah[3], bl[nt][0], bl[nt][1]);
                    mma_tf32(acc[mt][nt], al[0], al[1], al[2], al[3], bh[nt][0], bh[nt][1]);
                }
            }
        }
        __syncthreads();
    }

    #pragma unroll
    for (int mt = 0; mt < MTILES; mt++) {
        #pragma unroll
        for (int nt = 0; nt < 4; nt++) {
            int r0 = warp_m + mt*16 + g;
            int col = warp_n + nt*8 + 2*t;
            float* d0 = Cg + (size_t)r0*ldc + col;
            float* d1 = d0 + 8*ldc;
            float c0 = acc[mt][nt][0], c1 = acc[mt][nt][1];
            float c2 = acc[mt][nt][2], c3 = acc[mt][nt][3];
            if (RESID) {
                const float* s0 = Rg + (size_t)r0*ldc + col;
                const float* s1 = s0 + 8*ldc;
                float2 t0 = *(const float2*)s0;
                float2 t1 = *(const float2*)s1;
                c0 += t0.x; c1 += t0.y; c2 += t1.x; c3 += t1.y;
            }
            *(float2*)d0 = make_float2(c0, c1);
            *(float2*)d1 = make_float2(c2, c3);
        }
    }
}

#define QKV_SMEM ((128*36 + 32*140) * 8)   // 72704 B
#define OUT_SMEM ((64*36 + 32*140) * 8)    // 54272 B

// ---------------- stage 2: QKV gemm ----------------
__global__ void __launch_bounds__(256, 2)
gemm_qkv(const float* __restrict__ wq,
         const float* __restrict__ wk,
         const float* __restrict__ wv) {
    int m0 = blockIdx.x * 128;
    int n0 = blockIdx.y * 128;
    const float* Bsrc; int nb;
    if (n0 < 256)      { Bsrc = wq; nb = n0; }
    else if (n0 < 512) { Bsrc = wk; nb = n0 - 256; }
    else               { Bsrc = wv; nb = n0 - 512; }
    gemm_tc_body<128, 128, 128, 256, false>(
        g_xn + (size_t)m0*128, Bsrc + nb,
        g_y + (size_t)m0*768 + n0, nullptr, 768);
}

// ---------------- stage 4: output gemm + residual ----------------
__global__ void __launch_bounds__(256, 2)
gemm_out(const float* __restrict__ wo,
         const float* __restrict__ tok,
         float* __restrict__ out) {
    int m0 = blockIdx.x * 64;
    gemm_tc_body<64, 256, 256, 128, true>(
        g_ho + (size_t)m0*256, wo,
        out + (size_t)m0*128, tok + (size_t)m0*128, 128);
}

// ---------------- stage 3: banded differential attention ----------------
// 7-sigma band (dropped softmax mass <= ~1e-6 worst case). No max-tracking.
__global__ void __launch_bounds__(512, 1)
attn_kernel(const float* __restrict__ lq1, const float* __restrict__ lk1,
            const float* __restrict__ lq2, const float* __restrict__ lk2,
            const float* __restrict__ sigS, const float* __restrict__ sigN,
            const float* __restrict__ hnw,  const float* __restrict__ hnb) {
    extern __shared__ float sm[];
    float* Ksm = sm;
    float* Vsm = Ksm + KROWS*KLD;
    float* Qsm = Vsm + KROWS*64;
    u64*   Pb  = (u64*)(Qsm + QT*64);
    __shared__ float s_lam;

    int tid = threadIdx.x;
    int bh  = blockIdx.y;
    int b   = bh >> 2;
    int h   = bh & 3;
    int q0  = blockIdx.x * QT;

    float ss = fmaxf(sigS[0], 1.0f), sn = fmaxf(sigN[0], 1.0f);
    float c1 = -0.5f / (ss*ss);
    float c2 = -0.5f / (sn*sn);
    int Wn = (int)ceilf(7.0f * fmaxf(ss, sn)); if (Wn > W_MAX) Wn = W_MAX;
    int W1 = (int)ceilf(7.0f * ss);            if (W1 > W_MAX) W1 = W_MAX;

    int blo = q0 - Wn;          if (blo < 0) blo = 0;
    int bhi = q0 + QT - 1 + Wn; if (bhi > TT-1) bhi = TT-1;
    int nrows = bhi - blo + 1;

    const float* ybase = g_y + (size_t)(b*TT) * 768;

    for (int idx = tid; idx < nrows*64; idx += 512) {
        int r = idx >> 6, d = idx & 63;
        const float* row = ybase + (size_t)(blo + r)*768 + h*64;
        Ksm[r*KLD + d] = row[256 + d];
        float v = row[512 + d];
        int dd = (d < 32) ? (2*d) : (2*(d-32) + 1);
        Vsm[r*64 + dd] = v;
    }
    for (int idx = tid; idx < QT*64; idx += 512) {
        int r = idx >> 6, d = idx & 63;
        Qsm[idx] = ybase[(size_t)(q0 + r)*768 + h*64 + d];
    }
    if (tid == 0) {
        float d1 = 0.0f, d2 = 0.0f;
        #pragma unroll
        for (int i = 0; i < 32; i++) { d1 += lq1[i]*lk1[i]; d2 += lq2[i]*lk2[i]; }
        s_lam = __expf(d1) - __expf(d2) + LAMBDA_INIT;
    }
    __syncthreads();
    float lam = s_lam;

    int w = tid >> 5, lane = tid & 31;
    int i0 = q0 + w*QW;
    int jlo = i0 - Wn;           if (jlo < blo) jlo = blo;
    int jhi = i0 + QW - 1 + Wn;  if (jhi > bhi) jhi = bhi;
    int m1lo = i0 - W1, m1hi = i0 + QW - 1 + W1;

    u64* p1w = Pb + w*256;
    u64* p2w = p1w + 128;

    u64 o1x[4], o1y[4], o2x[4], o2y[4];
    float l1[QW], l2[QW];
    #pragma unroll
    for (int i = 0; i < 4; i++) { o1x[i]=0ull; o1y[i]=0ull; o2x[i]=0ull; o2y[i]=0ull; }
    #pragma unroll
    for (int q = 0; q < QW; q++) { l1[q] = 0.0f; l2[q] = 0.0f; }

    for (int jc = jlo; jc <= jhi; jc += 32) {
        bool doM1 = (jc <= m1hi) && (jc + 31 >= m1lo);
        int j = jc + lane;
        bool valid = (j <= jhi);
        int r = (valid ? j : jhi) - blo;
        const ulonglong2* kr = (const ulonglong2*)(Ksm + r*KLD);
        float relb = (float)(j - i0);

        u64 a2[QW];
        #pragma unroll
        for (int q = 0; q < QW; q++) a2[q] = 0ull;
        #pragma unroll
        for (int dc = 8; dc < 16; dc++) {
            ulonglong2 k2 = kr[dc];
            #pragma unroll
            for (int q = 0; q < QW; q++) {
                ulonglong2 q2 = *(const ulonglong2*)(Qsm + (w*QW + q)*64 + dc*4);
                a2[q] = f2fma(k2.x, q2.x, a2[q]);
                a2[q] = f2fma(k2.y, q2.y, a2[q]);
            }
        }
        float e2[QW];
        #pragma unroll
        for (int q = 0; q < QW; q++) {
            float rel = relb - (float)q, rr = rel*rel;
            float lo, hi; up2(a2[q], lo, hi);
            float s = (lo + hi)*SCALE + rr*c2;
            e2[q] = valid ? __expf(s) : 0.0f;
            l2[q] += e2[q];
        }
        ((ulonglong2*)p2w)[lane*2]     = make_ulonglong2(pk2(e2[0],e2[1]), pk2(e2[2],e2[3]));
        ((ulonglong2*)p2w)[lane*2 + 1] = make_ulonglong2(pk2(e2[4],e2[5]), pk2(e2[6],e2[7]));

        if (doM1) {
            u64 a1[QW];
            #pragma unroll
            for (int q = 0; q < QW; q++) a1[q] = 0ull;
            #pragma unroll
            for (int dc = 0; dc < 8; dc++) {
                ulonglong2 k2 = kr[dc];
                #pragma unroll
                for (int q = 0; q < QW; q++) {
                    ulonglong2 q2 = *(const ulonglong2*)(Qsm + (w*QW + q)*64 + dc*4);
                    a1[q] = f2fma(k2.x, q2.x, a1[q]);
                    a1[q] = f2fma(k2.y, q2.y, a1[q]);
                }
            }
            float e1[QW];
            #pragma unroll
            for (int q = 0; q < QW; q++) {
                float rel = relb - (float)q, rr = rel*rel;
                float lo, hi; up2(a1[q], lo, hi);
                float s = (lo + hi)*SCALE + rr*c1;
                e1[q] = valid ? __expf(s) : 0.0f;
                l1[q] += e1[q];
            }
            ((ulonglong2*)p1w)[lane*2]     = make_ulonglong2(pk2(e1[0],e1[1]), pk2(e1[2],e1[3]));
            ((ulonglong2*)p1w)[lane*2 + 1] = make_ulonglong2(pk2(e1[4],e1[5]), pk2(e1[6],e1[7]));
        }
        __syncwarp();

        int cnt = jhi - jc + 1; if (cnt > 32) cnt = 32;
        const float2* vb = (const float2*)(Vsm + (jc - blo)*64);
        const ulonglong2* P1 = (const ulonglong2*)p1w;
        const ulonglong2* P2 = (const ulonglong2*)p2w;
        if (doM1) {
            for (int jj = 0; jj < cnt; jj++) {
                float2 v = vb[jj*32 + lane];
                u64 vx = pk2(v.x, v.x), vy = pk2(v.y, v.y);
                ulonglong2 pa = P1[jj*2], pb = P1[jj*2 + 1];
                ulonglong2 qa = P2[jj*2], qb = P2[jj*2 + 1];
                o1x[0] = f2fma(pa.x, vx, o1x[0]);  o1y[0] = f2fma(pa.x, vy, o1y[0]);
                o1x[1] = f2fma(pa.y, vx, o1x[1]);  o1y[1] = f2fma(pa.y, vy, o1y[1]);
                o1x[2] = f2fma(pb.x, vx, o1x[2]);  o1y[2] = f2fma(pb.x, vy, o1y[2]);
                o1x[3] = f2fma(pb.y, vx, o1x[3]);  o1y[3] = f2fma(pb.y, vy, o1y[3]);
                o2x[0] = f2fma(qa.x, vx, o2x[0]);  o2y[0] = f2fma(qa.x, vy, o2y[0]);
                o2x[1] = f2fma(qa.y, vx, o2x[1]);  o2y[1] = f2fma(qa.y, vy, o2y[1]);
                o2x[2] = f2fma(qb.x, vx, o2x[2]);  o2y[2] = f2fma(qb.x, vy, o2y[2]);
                o2x[3] = f2fma(qb.y, vx, o2x[3]);  o2y[3] = f2fma(qb.y, vy, o2y[3]);
            }
        } else {
            for (int jj = 0; jj < cnt; jj++) {
                float2 v = vb[jj*32 + lane];
                u64 vx = pk2(v.x, v.x), vy = pk2(v.y, v.y);
                ulonglong2 qa = P2[jj*2], qb = P2[jj*2 + 1];
                o2x[0] = f2fma(qa.x, vx, o2x[0]);  o2y[0] = f2fma(qa.x, vy, o2y[0]);
                o2x[1] = f2fma(qa.y, vx, o2x[1]);  o2y[1] = f2fma(qa.y, vy, o2y[1]);
                o2x[2] = f2fma(qb.x, vx, o2x[2]);  o2y[2] = f2fma(qb.x, vy, o2y[2]);
                o2x[3] = f2fma(qb.y, vx, o2x[3]);  o2y[3] = f2fma(qb.y, vy, o2y[3]);
            }
        }
        __syncwarp();
    }

    float hw0 = hnw[lane], hw1 = hnw[lane+32];
    float hb0 = hnb[lane], hb1 = hnb[lane+32];
    float post = 1.0f - LAMBDA_INIT;
    #pragma unroll
    for (int qp = 0; qp < 4; qp++) {
        float x1a, x1b, y1a, y1b, x2a, x2b, y2a, y2b;
        up2(o1x[qp], x1a, x1b);  up2(o1y[qp], y1a, y1b);
        up2(o2x[qp], x2a, x2b);  up2(o2y[qp], y2a, y2b);
        #pragma unroll
        for (int sub = 0; sub < 2; sub++) {
            int q = qp*2 + sub;
            float x1 = sub ? x1b : x1a, y1 = sub ? y1b : y1a;
            float x2 = sub ? x2b : x2a, y2 = sub ? y2b : y2a;
            float L1 = warpsum(l1[q]);
            float L2 = warpsum(l2[q]);
            float il1 = 1.0f / L1;
            float il2 = lam  / L2;
            float ox = x1*il1 - x2*il2;
            float oy = y1*il1 - y2*il2;
            float s  = warpsum(ox + oy);
            float sq = warpsum(ox*ox + oy*oy);
            float mu  = s * (1.0f/64.0f);
            float var = sq * (1.0f/64.0f) - mu*mu;
            float rs  = rsqrtf(var + LN_EPS);
            float y0 = ((ox - mu)*rs*hw0 + hb0) * post;
            float y1o = ((oy - mu)*rs*hw1 + hb1) * post;
            int i = i0 + q;
            float* dst = g_ho + (size_t)(b*TT + i)*256 + h*64;
            dst[lane]      = y0;
            dst[lane + 32] = y1o;
        }
    }
}

// ---------------- launch ----------------
extern "C" void kernel_launch(void* const* d_in, const int* in_sizes, int n_in,
                              void* d_out, int out_size) {
    const float* tokens = (const float*)d_in[0];
    const float* ln_w   = (const float*)d_in[1];
    const float* ln_b   = (const float*)d_in[2];
    const float* wq     = (const float*)d_in[3];
    const float* wk     = (const float*)d_in[4];
    const float* wv     = (const float*)d_in[5];
    const float* wo     = (const float*)d_in[6];
    const float* lq1    = (const float*)d_in[7];
    const float* lk1    = (const float*)d_in[8];
    const float* lq2    = (const float*)d_in[9];
    const float* lk2    = (const float*)d_in[10];
    const float* sigS   = (const float*)d_in[11];
    const float* sigN   = (const float*)d_in[12];
    const float* hnw    = (const float*)d_in[13];
    const float* hnb    = (const float*)d_in[14];
    float* out = (float*)d_out;

    const size_t attn_smem = (size_t)(KROWS*KLD + KROWS*64 + QT*64) * sizeof(float)
                           + (size_t)NW * 256 * sizeof(u64);   // 218128 B
    cudaFuncSetAttribute(attn_kernel, cudaFuncAttributeMaxDynamicSharedMemorySize, (int)attn_smem);
    cudaFuncSetAttribute(gemm_qkv, cudaFuncAttributeMaxDynamicSharedMemorySize, QKV_SMEM);
    cudaFuncSetAttribute(gemm_out, cudaFuncAttributeMaxDynamicSharedMemorySize, OUT_SMEM);

    ln_kernel<<<NTOK/8, 256>>>(tokens, ln_w, ln_b);
    gemm_qkv<<<dim3(NTOK/128, 6), 256, QKV_SMEM>>>(wq, wk, wv);
    attn_kernel<<<dim3(TT/QT, BB*HH), 512, attn_smem>>>(lq1, lk1, lq2, lk2, sigS, sigN, hnw, hnb);
    gemm_out<<<NTOK/64, 256, OUT_SMEM>>>(wo, tokens, out);
}

// round 9
// speedup vs baseline: 1.7936x; 1.0736x over previous
#include <cuda_runtime.h>
#include <math.h>

// ---------------- problem constants ----------------
#define TT 2048
#define BB 8
#define DD 128
#define HH 4
#define NTOK (BB*TT)          // 16384
#define SCALE 0.17677669529663687f   // 1/sqrt(32)
#define LAMBDA_INIT 0.8f
#define LN_EPS 1e-5f

// banded attention config
#define W_MAX 80
#define QT 128
#define QW 8
#define NW 16
#define KROWS (QT + 2*W_MAX + 1)   // 289
#define KLD 68

typedef unsigned long long u64;
typedef unsigned int u32;

// ---------------- scratch ----------------
__device__ float g_mu[NTOK];           // layernorm mean
__device__ float g_rs[NTOK];           // layernorm rsqrt(var+eps)
__device__ float g_y [NTOK*768];       // qkv projections
__device__ float g_ho[NTOK*256];       // per-head outputs

// ---------------- helpers ----------------
__device__ __forceinline__ u64 pk2(float x, float y) {
    u64 r; asm("mov.b64 %0, {%1, %2};" : "=l"(r) : "f"(x), "f"(y)); return r;
}
__device__ __forceinline__ void up2(u64 v, float& x, float& y) {
    asm("mov.b64 {%0, %1}, %2;" : "=f"(x), "=f"(y) : "l"(v));
}
__device__ __forceinline__ u64 f2fma(u64 a, u64 b, u64 c) {
    u64 d; asm("fma.rn.f32x2 %0, %1, %2, %3;" : "=l"(d) : "l"(a), "l"(b), "l"(c));
    return d;
}
__device__ __forceinline__ float warpsum(float v) {
    #pragma unroll
    for (int o = 16; o; o >>= 1) v += __shfl_xor_sync(0xffffffffu, v, o);
    return v;
}
__device__ __forceinline__ u32 tf32_rnd(float x) {
    u32 r; asm("cvt.rna.tf32.f32 %0, %1;" : "=r"(r) : "f"(x)); return r;
}
__device__ __forceinline__ void mma_tf32(float* c, u32 a0, u32 a1, u32 a2, u32 a3,
                                         u32 b0, u32 b1) {
    asm volatile(
        "mma.sync.aligned.m16n8k8.row.col.f32.tf32.tf32.f32 "
        "{%0,%1,%2,%3}, {%4,%5,%6,%7}, {%8,%9}, {%0,%1,%2,%3};"
        : "+f"(c[0]), "+f"(c[1]), "+f"(c[2]), "+f"(c[3])
        : "r"(a0), "r"(a1), "r"(a2), "r"(a3), "r"(b0), "r"(b1));
}

// ---------------- stage 1: layernorm stats only ----------------
__global__ void ln_stats(const float* __restrict__ tok) {
    int t = blockIdx.x * 8 + (threadIdx.x >> 5);
    int lane = threadIdx.x & 31;
    const float4* src = (const float4*)(tok + (size_t)t * DD);
    float4 x = src[lane];
    float s  = x.x + x.y + x.z + x.w;
    float sq = x.x*x.x + x.y*x.y + x.z*x.z + x.w*x.w;
    s  = warpsum(s);
    sq = warpsum(sq);
    float mu  = s * (1.0f/128.0f);
    float var = sq * (1.0f/128.0f) - mu*mu;
    if (lane == 0) {
        g_mu[t] = mu;
        g_rs[t] = rsqrtf(var + LN_EPS);
    }
}

// ---------------- 3xTF32 TC GEMM (R7 separate hi/lo planes) ----------------
// A smem [MT][36] hi + lo planes; B smem [32][136] hi + lo planes.
// LNA: apply layernorm (mu/rs per row, w/b per column) on A load.
template<int MT, int KTOT, int LDA_G, int LDB_G, bool RESID, bool LNA>
__device__ __forceinline__ void gemm_tc_body(
    const float* __restrict__ Ag,
    const float* __restrict__ Bg,
    float* __restrict__ Cg,
    const float* __restrict__ Rg,
    int ldc,
    const float* __restrict__ mu_p,   // per-row mean (offset to m0) or null
    const float* __restrict__ rs_p,   // per-row rstd or null
    const float* __restrict__ lnw,
    const float* __restrict__ lnb)
{
    constexpr int MTILES = MT / 32;
    extern __shared__ __align__(16) float smg[];
    float* AsH = smg;
    float* AsL = AsH + MT*36;
    float* BsH = AsL + MT*36;
    float* BsL = BsH + 32*136;

    int tid = threadIdx.x;
    int lane = tid & 31, wid = tid >> 5;
    int g = lane >> 2, t = lane & 3;
    int warp_m = (wid >> 2) * (MT/2);
    int warp_n = (wid & 3) * 32;

    float acc[MTILES][4][4];
    #pragma unroll
    for (int i = 0; i < MTILES; i++)
        #pragma unroll
        for (int j = 0; j < 4; j++)
            #pragma unroll
            for (int r = 0; r < 4; r++) acc[i][j][r] = 0.0f;

    constexpr int TPR = 256 / MT;
    constexpr int AC4 = 32 / TPR / 4;
    int a_row = tid / TPR;
    int a_c0  = (tid % TPR) * (32 / TPR);
    int b_row = tid >> 3, b_c4 = tid & 7;

    float a_mu = 0.0f, a_rs = 1.0f;
    if (LNA) { a_mu = mu_p[a_row]; a_rs = rs_p[a_row]; }

    for (int k0 = 0; k0 < KTOT; k0 += 32) {
        #pragma unroll
        for (int i = 0; i < AC4; i++) {
            int c = a_c0 + i*4;
            float4 a4 = *(const float4*)&Ag[(size_t)a_row*LDA_G + k0 + c];
            if (LNA) {
                float4 w4 = *(const float4*)&lnw[k0 + c];
                float4 b4 = *(const float4*)&lnb[k0 + c];
                a4.x = (a4.x - a_mu) * a_rs * w4.x + b4.x;
                a4.y = (a4.y - a_mu) * a_rs * w4.y + b4.y;
                a4.z = (a4.z - a_mu) * a_rs * w4.z + b4.z;
                a4.w = (a4.w - a_mu) * a_rs * w4.w + b4.w;
            }
            u32 h0 = tf32_rnd(a4.x), h1 = tf32_rnd(a4.y);
            u32 h2 = tf32_rnd(a4.z), h3 = tf32_rnd(a4.w);
            float4 hi = make_float4(__uint_as_float(h0), __uint_as_float(h1),
                                    __uint_as_float(h2), __uint_as_float(h3));
            float4 lo = make_float4(a4.x - hi.x, a4.y - hi.y,
                                    a4.z - hi.z, a4.w - hi.w);
            *(float4*)&AsH[a_row*36 + c] = hi;
            *(float4*)&AsL[a_row*36 + c] = lo;
        }
        #pragma unroll
        for (int i = 0; i < 4; i++) {
            int c = (b_c4 + i*8) * 4;
            float4 b4 = *(const float4*)&Bg[(size_t)(k0 + b_row)*LDB_G + c];
            u32 h0 = tf32_rnd(b4.x), h1 = tf32_rnd(b4.y);
            u32 h2 = tf32_rnd(b4.z), h3 = tf32_rnd(b4.w);
            float4 hi = make_float4(__uint_as_float(h0), __uint_as_float(h1),
                                    __uint_as_float(h2), __uint_as_float(h3));
            float4 lo = make_float4(b4.x - hi.x, b4.y - hi.y,
                                    b4.z - hi.z, b4.w - hi.w);
            *(float4*)&BsH[b_row*136 + c] = hi;
            *(float4*)&BsL[b_row*136 + c] = lo;
        }
        __syncthreads();

        #pragma unroll
        for (int kk = 0; kk < 4; kk++) {
            int kb = kk*8;
            u32 bh[4][2], bl[4][2];
            #pragma unroll
            for (int nt = 0; nt < 4; nt++) {
                int n = warp_n + nt*8 + g;
                bh[nt][0] = __float_as_uint(BsH[(kb + t)*136 + n]);
                bh[nt][1] = __float_as_uint(BsH[(kb + t + 4)*136 + n]);
                bl[nt][0] = __float_as_uint(BsL[(kb + t)*136 + n]);
                bl[nt][1] = __float_as_uint(BsL[(kb + t + 4)*136 + n]);
            }
            #pragma unroll
            for (int mt = 0; mt < MTILES; mt++) {
                int m = warp_m + mt*16;
                u32 ah[4], al[4];
                ah[0] = __float_as_uint(AsH[(m + g)*36 + kb + t]);
                ah[1] = __float_as_uint(AsH[(m + g + 8)*36 + kb + t]);
                ah[2] = __float_as_uint(AsH[(m + g)*36 + kb + t + 4]);
                ah[3] = __float_as_uint(AsH[(m + g + 8)*36 + kb + t + 4]);
                al[0] = __float_as_uint(AsL[(m + g)*36 + kb + t]);
                al[1] = __float_as_uint(AsL[(m + g + 8)*36 + kb + t]);
                al[2] = __float_as_uint(AsL[(m + g)*36 + kb + t + 4]);
                al[3] = __float_as_uint(AsL[(m + g + 8)*36 + kb + t + 4]);
                #pragma unroll
                for (int nt = 0; nt < 4; nt++) {
                    mma_tf32(acc[mt][nt], ah[0], ah[1], ah[2], ah[3], bh[nt][0], bh[nt][1]);
                    mma_tf32(acc[mt][nt], ah[0], ah[1], ah[2], ah[3], bl[nt][0], bl[nt][1]);
                    mma_tf32(acc[mt][nt], al[0], al[1], al[2], al[3], bh[nt][0], bh[nt][1]);
                }
            }
        }
        __syncthreads();
    }

    #pragma unroll
    for (int mt = 0; mt < MTILES; mt++) {
        #pragma unroll
        for (int nt = 0; nt < 4; nt++) {
            int r0 = warp_m + mt*16 + g;
            int col = warp_n + nt*8 + 2*t;
            float* d0 = Cg + (size_t)r0*ldc + col;
            float* d1 = d0 + 8*ldc;
            float c0 = acc[mt][nt][0], c1 = acc[mt][nt][1];
            float c2 = acc[mt][nt][2], c3 = acc[mt][nt][3];
            if (RESID) {
                const float* s0 = Rg + (size_t)r0*ldc + col;
                const float* s1 = s0 + 8*ldc;
                float2 t0 = *(const float2*)s0;
                float2 t1 = *(const float2*)s1;
                c0 += t0.x; c1 += t0.y; c2 += t1.x; c3 += t1.y;
            }
            *(float2*)d0 = make_float2(c0, c1);
            *(float2*)d1 = make_float2(c2, c3);
        }
    }
}

#define QKV_SMEM ((128*36*2 + 32*136*2) * 4)   // 71680 B
#define OUT_SMEM ((64*36*2 + 32*136*2) * 4)    // 53248 B

// ---------------- stage 2: QKV gemm (LN fused into A load) ----------------
__global__ void __launch_bounds__(256, 2)
gemm_qkv(const float* __restrict__ tok,
         const float* __restrict__ lnw, const float* __restrict__ lnb,
         const float* __restrict__ wq,
         const float* __restrict__ wk,
         const float* __restrict__ wv) {
    int m0 = blockIdx.x * 128;
    int n0 = blockIdx.y * 128;
    const float* Bsrc; int nb;
    if (n0 < 256)      { Bsrc = wq; nb = n0; }
    else if (n0 < 512) { Bsrc = wk; nb = n0 - 256; }
    else               { Bsrc = wv; nb = n0 - 512; }
    gemm_tc_body<128, 128, 128, 256, false, true>(
        tok + (size_t)m0*128, Bsrc + nb,
        g_y + (size_t)m0*768 + n0, nullptr, 768,
        g_mu + m0, g_rs + m0, lnw, lnb);
}

// ---------------- stage 4: output gemm + residual ----------------
__global__ void __launch_bounds__(256, 2)
gemm_out(const float* __restrict__ wo,
         const float* __restrict__ tok,
         float* __restrict__ out) {
    int m0 = blockIdx.x * 64;
    gemm_tc_body<64, 256, 256, 128, true, false>(
        g_ho + (size_t)m0*256, wo,
        out + (size_t)m0*128, tok + (size_t)m0*128, 128,
        nullptr, nullptr, nullptr, nullptr);
}

// ---------------- stage 3: banded differential attention (unchanged R8) ----------------
__global__ void __launch_bounds__(512, 1)
attn_kernel(const float* __restrict__ lq1, const float* __restrict__ lk1,
            const float* __restrict__ lq2, const float* __restrict__ lk2,
            const float* __restrict__ sigS, const float* __restrict__ sigN,
            const float* __restrict__ hnw,  const float* __restrict__ hnb) {
    extern __shared__ float sm[];
    float* Ksm = sm;
    float* Vsm = Ksm + KROWS*KLD;
    float* Qsm = Vsm + KROWS*64;
    u64*   Pb  = (u64*)(Qsm + QT*64);
    __shared__ float s_lam;

    int tid = threadIdx.x;
    int bh  = blockIdx.y;
    int b   = bh >> 2;
    int h   = bh & 3;
    int q0  = blockIdx.x * QT;

    float ss = fmaxf(sigS[0], 1.0f), sn = fmaxf(sigN[0], 1.0f);
    float c1 = -0.5f / (ss*ss);
    float c2 = -0.5f / (sn*sn);
    int Wn = (int)ceilf(7.0f * fmaxf(ss, sn)); if (Wn > W_MAX) Wn = W_MAX;
    int W1 = (int)ceilf(7.0f * ss);            if (W1 > W_MAX) W1 = W_MAX;

    int blo = q0 - Wn;          if (blo < 0) blo = 0;
    int bhi = q0 + QT - 1 + Wn; if (bhi > TT-1) bhi = TT-1;
    int nrows = bhi - blo + 1;

    const float* ybase = g_y + (size_t)(b*TT) * 768;

    for (int idx = tid; idx < nrows*64; idx += 512) {
        int r = idx >> 6, d = idx & 63;
        const float* row = ybase + (size_t)(blo + r)*768 + h*64;
        Ksm[r*KLD + d] = row[256 + d];
        float v = row[512 + d];
        int dd = (d < 32) ? (2*d) : (2*(d-32) + 1);
        Vsm[r*64 + dd] = v;
    }
    for (int idx = tid; idx < QT*64; idx += 512) {
        int r = idx >> 6, d = idx & 63;
        Qsm[idx] = ybase[(size_t)(q0 + r)*768 + h*64 + d];
    }
    if (tid == 0) {
        float d1 = 0.0f, d2 = 0.0f;
        #pragma unroll
        for (int i = 0; i < 32; i++) { d1 += lq1[i]*lk1[i]; d2 += lq2[i]*lk2[i]; }
        s_lam = __expf(d1) - __expf(d2) + LAMBDA_INIT;
    }
    __syncthreads();
    float lam = s_lam;

    int w = tid >> 5, lane = tid & 31;
    int i0 = q0 + w*QW;
    int jlo = i0 - Wn;           if (jlo < blo) jlo = blo;
    int jhi = i0 + QW - 1 + Wn;  if (jhi > bhi) jhi = bhi;
    int m1lo = i0 - W1, m1hi = i0 + QW - 1 + W1;

    u64* p1w = Pb + w*256;
    u64* p2w = p1w + 128;

    u64 o1x[4], o1y[4], o2x[4], o2y[4];
    float l1[QW], l2[QW];
    #pragma unroll
    for (int i = 0; i < 4; i++) { o1x[i]=0ull; o1y[i]=0ull; o2x[i]=0ull; o2y[i]=0ull; }
    #pragma unroll
    for (int q = 0; q < QW; q++) { l1[q] = 0.0f; l2[q] = 0.0f; }

    for (int jc = jlo; jc <= jhi; jc += 32) {
        bool doM1 = (jc <= m1hi) && (jc + 31 >= m1lo);
        int j = jc + lane;
        bool valid = (j <= jhi);
        int r = (valid ? j : jhi) - blo;
        const ulonglong2* kr = (const ulonglong2*)(Ksm + r*KLD);
        float relb = (float)(j - i0);

        u64 a2[QW];
        #pragma unroll
        for (int q = 0; q < QW; q++) a2[q] = 0ull;
        #pragma unroll
        for (int dc = 8; dc < 16; dc++) {
            ulonglong2 k2 = kr[dc];
            #pragma unroll
            for (int q = 0; q < QW; q++) {
                ulonglong2 q2 = *(const ulonglong2*)(Qsm + (w*QW + q)*64 + dc*4);
                a2[q] = f2fma(k2.x, q2.x, a2[q]);
                a2[q] = f2fma(k2.y, q2.y, a2[q]);
            }
        }
        float e2[QW];
        #pragma unroll
        for (int q = 0; q < QW; q++) {
            float rel = relb - (float)q, rr = rel*rel;
            float lo, hi; up2(a2[q], lo, hi);
            float s = (lo + hi)*SCALE + rr*c2;
            e2[q] = valid ? __expf(s) : 0.0f;
            l2[q] += e2[q];
        }
        ((ulonglong2*)p2w)[lane*2]     = make_ulonglong2(pk2(e2[0],e2[1]), pk2(e2[2],e2[3]));
        ((ulonglong2*)p2w)[lane*2 + 1] = make_ulonglong2(pk2(e2[4],e2[5]), pk2(e2[6],e2[7]));

        if (doM1) {
            u64 a1[QW];
            #pragma unroll
            for (int q = 0; q < QW; q++) a1[q] = 0ull;
            #pragma unroll
            for (int dc = 0; dc < 8; dc++) {
                ulonglong2 k2 = kr[dc];
                #pragma unroll
                for (int q = 0; q < QW; q++) {
                    ulonglong2 q2 = *(const ulonglong2*)(Qsm + (w*QW + q)*64 + dc*4);
                    a1[q] = f2fma(k2.x, q2.x, a1[q]);
                    a1[q] = f2fma(k2.y, q2.y, a1[q]);
                }
            }
            float e1[QW];
            #pragma unroll
            for (int q = 0; q < QW; q++) {
                float rel = relb - (float)q, rr = rel*rel;
                float lo, hi; up2(a1[q], lo, hi);
                float s = (lo + hi)*SCALE + rr*c1;
                e1[q] = valid ? __expf(s) : 0.0f;
                l1[q] += e1[q];
            }
            ((ulonglong2*)p1w)[lane*2]     = make_ulonglong2(pk2(e1[0],e1[1]), pk2(e1[2],e1[3]));
            ((ulonglong2*)p1w)[lane*2 + 1] = make_ulonglong2(pk2(e1[4],e1[5]), pk2(e1[6],e1[7]));
        }
        __syncwarp();

        int cnt = jhi - jc + 1; if (cnt > 32) cnt = 32;
        const float2* vb = (const float2*)(Vsm + (jc - blo)*64);
        const ulonglong2* P1 = (const ulonglong2*)p1w;
        const ulonglong2* P2 = (const ulonglong2*)p2w;
        if (doM1) {
            for (int jj = 0; jj < cnt; jj++) {
                float2 v = vb[jj*32 + lane];
                u64 vx = pk2(v.x, v.x), vy = pk2(v.y, v.y);
                ulonglong2 pa = P1[jj*2], pb = P1[jj*2 + 1];
                ulonglong2 qa = P2[jj*2], qb = P2[jj*2 + 1];
                o1x[0] = f2fma(pa.x, vx, o1x[0]);  o1y[0] = f2fma(pa.x, vy, o1y[0]);
                o1x[1] = f2fma(pa.y, vx, o1x[1]);  o1y[1] = f2fma(pa.y, vy, o1y[1]);
                o1x[2] = f2fma(pb.x, vx, o1x[2]);  o1y[2] = f2fma(pb.x, vy, o1y[2]);
                o1x[3] = f2fma(pb.y, vx, o1x[3]);  o1y[3] = f2fma(pb.y, vy, o1y[3]);
                o2x[0] = f2fma(qa.x, vx, o2x[0]);  o2y[0] = f2fma(qa.x, vy, o2y[0]);
                o2x[1] = f2fma(qa.y, vx, o2x[1]);  o2y[1] = f2fma(qa.y, vy, o2y[1]);
                o2x[2] = f2fma(qb.x, vx, o2x[2]);  o2y[2] = f2fma(qb.x, vy, o2y[2]);
                o2x[3] = f2fma(qb.y, vx, o2x[3]);  o2y[3] = f2fma(qb.y, vy, o2y[3]);
            }
        } else {
            for (int jj = 0; jj < cnt; jj++) {
                float2 v = vb[jj*32 + lane];
                u64 vx = pk2(v.x, v.x), vy = pk2(v.y, v.y);
                ulonglong2 qa = P2[jj*2], qb = P2[jj*2 + 1];
                o2x[0] = f2fma(qa.x, vx, o2x[0]);  o2y[0] = f2fma(qa.x, vy, o2y[0]);
                o2x[1] = f2fma(qa.y, vx, o2x[1]);  o2y[1] = f2fma(qa.y, vy, o2y[1]);
                o2x[2] = f2fma(qb.x, vx, o2x[2]);  o2y[2] = f2fma(qb.x, vy, o2y[2]);
                o2x[3] = f2fma(qb.y, vx, o2x[3]);  o2y[3] = f2fma(qb.y, vy, o2y[3]);
            }
        }
        __syncwarp();
    }

    float hw0 = hnw[lane], hw1 = hnw[lane+32];
    float hb0 = hnb[lane], hb1 = hnb[lane+32];
    float post = 1.0f - LAMBDA_INIT;
    #pragma unroll
    for (int qp = 0; qp < 4; qp++) {
        float x1a, x1b, y1a, y1b, x2a, x2b, y2a, y2b;
        up2(o1x[qp], x1a, x1b);  up2(o1y[qp], y1a, y1b);
        up2(o2x[qp], x2a, x2b);  up2(o2y[qp], y2a, y2b);
        #pragma unroll
        for (int sub = 0; sub < 2; sub++) {
            int q = qp*2 + sub;
            float x1 = sub ? x1b : x1a, y1 = sub ? y1b : y1a;
            float x2 = sub ? x2b : x2a, y2 = sub ? y2b : y2a;
            float L1 = warpsum(l1[q]);
            float L2 = warpsum(l2[q]);
            float il1 = 1.0f / L1;
            float il2 = lam  / L2;
            float ox = x1*il1 - x2*il2;
            float oy = y1*il1 - y2*il2;
            float s  = warpsum(ox + oy);
            float sq = warpsum(ox*ox + oy*oy);
            float mu  = s * (1.0f/64.0f);
            float var = sq * (1.0f/64.0f) - mu*mu;
            float rs  = rsqrtf(var + LN_EPS);
            float y0 = ((ox - mu)*rs*hw0 + hb0) * post;
            float y1o = ((oy - mu)*rs*hw1 + hb1) * post;
            int i = i0 + q;
            float* dst = g_ho + (size_t)(b*TT + i)*256 + h*64;
            dst[lane]      = y0;
            dst[lane + 32] = y1o;
        }
    }
}

// ---------------- launch ----------------
extern "C" void kernel_launch(void* const* d_in, const int* in_sizes, int n_in,
                              void* d_out, int out_size) {
    const float* tokens = (const float*)d_in[0];
    const float* ln_w   = (const float*)d_in[1];
    const float* ln_b   = (const float*)d_in[2];
    const float* wq     = (const float*)d_in[3];
    const float* wk     = (const float*)d_in[4];
    const float* wv     = (const float*)d_in[5];
    const float* wo     = (const float*)d_in[6];
    const float* lq1    = (const float*)d_in[7];
    const float* lk1    = (const float*)d_in[8];
    const float* lq2    = (const float*)d_in[9];
    const float* lk2    = (const float*)d_in[10];
    const float* sigS   = (const float*)d_in[11];
    const float* sigN   = (const float*)d_in[12];
    const float* hnw    = (const float*)d_in[13];
    const float* hnb    = (const float*)d_in[14];
    float* out = (float*)d_out;

    const size_t attn_smem = (size_t)(KROWS*KLD + KROWS*64 + QT*64) * sizeof(float)
                           + (size_t)NW * 256 * sizeof(u64);
    cudaFuncSetAttribute(attn_kernel, cudaFuncAttributeMaxDynamicSharedMemorySize, (int)attn_smem);
    cudaFuncSetAttribute(gemm_qkv, cudaFuncAttributeMaxDynamicSharedMemorySize, QKV_SMEM);
    cudaFuncSetAttribute(gemm_out, cudaFuncAttributeMaxDynamicSharedMemorySize, OUT_SMEM);

    ln_stats<<<NTOK/8, 256>>>(tokens);
    gemm_qkv<<<dim3(NTOK/128, 6), 256, QKV_SMEM>>>(tokens, ln_w, ln_b, wq, wk, wv);
    attn_kernel<<<dim3(TT/QT, BB*HH), 512, attn_smem>>>(lq1, lk1, lq2, lk2, sigS, sigN, hnw, hnb);
    gemm_out<<<NTOK/64, 256, OUT_SMEM>>>(wo, tokens, out);
}

// round 10
// speedup vs baseline: 1.9861x; 1.1073x over previous
#include <cuda_runtime.h>
#include <math.h>

// ---------------- problem constants ----------------
#define TT 2048
#define BB 8
#define DD 128
#define HH 4
#define NTOK (BB*TT)          // 16384
#define SCALE 0.17677669529663687f   // 1/sqrt(32)
#define LAMBDA_INIT 0.8f
#define LN_EPS 1e-5f

// banded attention config
#define W_MAX 80
#define QT 128
#define QW 8
#define NW 16
#define KROWS (QT + 2*W_MAX + 1)   // 289 (cap case)
#define KLD 68

typedef unsigned long long u64;
typedef unsigned int u32;

// ---------------- scratch ----------------
__device__ float g_mu[NTOK];
__device__ float g_rs[NTOK];
__device__ float g_y [NTOK*768];
__device__ float g_ho[NTOK*256];

// ---------------- helpers ----------------
__device__ __forceinline__ u64 pk2(float x, float y) {
    u64 r; asm("mov.b64 %0, {%1, %2};" : "=l"(r) : "f"(x), "f"(y)); return r;
}
__device__ __forceinline__ void up2(u64 v, float& x, float& y) {
    asm("mov.b64 {%0, %1}, %2;" : "=f"(x), "=f"(y) : "l"(v));
}
__device__ __forceinline__ u64 f2fma(u64 a, u64 b, u64 c) {
    u64 d; asm("fma.rn.f32x2 %0, %1, %2, %3;" : "=l"(d) : "l"(a), "l"(b), "l"(c));
    return d;
}
__device__ __forceinline__ float warpsum(float v) {
    #pragma unroll
    for (int o = 16; o; o >>= 1) v += __shfl_xor_sync(0xffffffffu, v, o);
    return v;
}
__device__ __forceinline__ u32 tf32_rnd(float x) {
    u32 r; asm("cvt.rna.tf32.f32 %0, %1;" : "=r"(r) : "f"(x)); return r;
}
__device__ __forceinline__ void mma_tf32(float* c, u32 a0, u32 a1, u32 a2, u32 a3,
                                         u32 b0, u32 b1) {
    asm volatile(
        "mma.sync.aligned.m16n8k8.row.col.f32.tf32.tf32.f32 "
        "{%0,%1,%2,%3}, {%4,%5,%6,%7}, {%8,%9}, {%0,%1,%2,%3};"
        : "+f"(c[0]), "+f"(c[1]), "+f"(c[2]), "+f"(c[3])
        : "r"(a0), "r"(a1), "r"(a2), "r"(a3), "r"(b0), "r"(b1));
}

// ---------------- stage 1: layernorm stats only ----------------
__global__ void ln_stats(const float* __restrict__ tok) {
    int t = blockIdx.x * 8 + (threadIdx.x >> 5);
    int lane = threadIdx.x & 31;
    const float4* src = (const float4*)(tok + (size_t)t * DD);
    float4 x = src[lane];
    float s  = x.x + x.y + x.z + x.w;
    float sq = x.x*x.x + x.y*x.y + x.z*x.z + x.w*x.w;
    s  = warpsum(s);
    sq = warpsum(sq);
    float mu  = s * (1.0f/128.0f);
    float var = sq * (1.0f/128.0f) - mu*mu;
    if (lane == 0) {
        g_mu[t] = mu;
        g_rs[t] = rsqrtf(var + LN_EPS);
    }
}

// ---------------- 3xTF32 TC GEMM (hi/lo planes, A-panel prefetch) ----------------
template<int MT, int KTOT, int LDA_G, int LDB_G, bool RESID, bool LNA>
__device__ __forceinline__ void gemm_tc_body(
    const float* __restrict__ Ag,
    const float* __restrict__ Bg,
    float* __restrict__ Cg,
    const float* __restrict__ Rg,
    int ldc,
    const float* __restrict__ mu_p,
    const float* __restrict__ rs_p,
    const float* __restrict__ lnw,
    const float* __restrict__ lnb)
{
    constexpr int MTILES = MT / 32;
    extern __shared__ __align__(16) float smg[];
    float* AsH = smg;
    float* AsL = AsH + MT*36;
    float* BsH = AsL + MT*36;
    float* BsL = BsH + 32*136;

    int tid = threadIdx.x;
    int lane = tid & 31, wid = tid >> 5;
    int g = lane >> 2, t = lane & 3;
    int warp_m = (wid >> 2) * (MT/2);
    int warp_n = (wid & 3) * 32;

    float acc[MTILES][4][4];
    #pragma unroll
    for (int i = 0; i < MTILES; i++)
        #pragma unroll
        for (int j = 0; j < 4; j++)
            #pragma unroll
            for (int r = 0; r < 4; r++) acc[i][j][r] = 0.0f;

    constexpr int TPR = 256 / MT;
    constexpr int AC4 = 32 / TPR / 4;
    int a_row = tid / TPR;
    int a_c0  = (tid % TPR) * (32 / TPR);
    int b_row = tid >> 3, b_c4 = tid & 7;

    float a_mu = 0.0f, a_rs = 1.0f;
    if (LNA) { a_mu = mu_p[a_row]; a_rs = rs_p[a_row]; }

    // prefetch chunk 0 of A into registers
    float4 aNext[AC4];
    #pragma unroll
    for (int i = 0; i < AC4; i++)
        aNext[i] = *(const float4*)&Ag[(size_t)a_row*LDA_G + a_c0 + i*4];

    for (int k0 = 0; k0 < KTOT; k0 += 32) {
        // convert + store A chunk (from prefetched regs)
        #pragma unroll
        for (int i = 0; i < AC4; i++) {
            int c = a_c0 + i*4;
            float4 a4 = aNext[i];
            if (LNA) {
                float4 w4 = *(const float4*)&lnw[k0 + c];
                float4 b4 = *(const float4*)&lnb[k0 + c];
                a4.x = (a4.x - a_mu) * a_rs * w4.x + b4.x;
                a4.y = (a4.y - a_mu) * a_rs * w4.y + b4.y;
                a4.z = (a4.z - a_mu) * a_rs * w4.z + b4.z;
                a4.w = (a4.w - a_mu) * a_rs * w4.w + b4.w;
            }
            u32 h0 = tf32_rnd(a4.x), h1 = tf32_rnd(a4.y);
            u32 h2 = tf32_rnd(a4.z), h3 = tf32_rnd(a4.w);
            float4 hi = make_float4(__uint_as_float(h0), __uint_as_float(h1),
                                    __uint_as_float(h2), __uint_as_float(h3));
            float4 lo = make_float4(a4.x - hi.x, a4.y - hi.y,
                                    a4.z - hi.z, a4.w - hi.w);
            *(float4*)&AsH[a_row*36 + c] = hi;
            *(float4*)&AsL[a_row*36 + c] = lo;
        }
        // B chunk load + convert + store
        #pragma unroll
        for (int i = 0; i < 4; i++) {
            int c = (b_c4 + i*8) * 4;
            float4 b4 = *(const float4*)&Bg[(size_t)(k0 + b_row)*LDB_G + c];
            u32 h0 = tf32_rnd(b4.x), h1 = tf32_rnd(b4.y);
            u32 h2 = tf32_rnd(b4.z), h3 = tf32_rnd(b4.w);
            float4 hi = make_float4(__uint_as_float(h0), __uint_as_float(h1),
                                    __uint_as_float(h2), __uint_as_float(h3));
            float4 lo = make_float4(b4.x - hi.x, b4.y - hi.y,
                                    b4.z - hi.z, b4.w - hi.w);
            *(float4*)&BsH[b_row*136 + c] = hi;
            *(float4*)&BsL[b_row*136 + c] = lo;
        }
        __syncthreads();

        // issue next A chunk's global loads; latency hidden under compute
        if (k0 + 32 < KTOT) {
            #pragma unroll
            for (int i = 0; i < AC4; i++)
                aNext[i] = *(const float4*)&Ag[(size_t)a_row*LDA_G + k0 + 32 + a_c0 + i*4];
        }

        #pragma unroll
        for (int kk = 0; kk < 4; kk++) {
            int kb = kk*8;
            u32 bh[4][2], bl[4][2];
            #pragma unroll
            for (int nt = 0; nt < 4; nt++) {
                int n = warp_n + nt*8 + g;
                bh[nt][0] = __float_as_uint(BsH[(kb + t)*136 + n]);
                bh[nt][1] = __float_as_uint(BsH[(kb + t + 4)*136 + n]);
                bl[nt][0] = __float_as_uint(BsL[(kb + t)*136 + n]);
                bl[nt][1] = __float_as_uint(BsL[(kb + t + 4)*136 + n]);
            }
            #pragma unroll
            for (int mt = 0; mt < MTILES; mt++) {
                int m = warp_m + mt*16;
                u32 ah[4], al[4];
                ah[0] = __float_as_uint(AsH[(m + g)*36 + kb + t]);
                ah[1] = __float_as_uint(AsH[(m + g + 8)*36 + kb + t]);
                ah[2] = __float_as_uint(AsH[(m + g)*36 + kb + t + 4]);
                ah[3] = __float_as_uint(AsH[(m + g + 8)*36 + kb + t + 4]);
                al[0] = __float_as_uint(AsL[(m + g)*36 + kb + t]);
                al[1] = __float_as_uint(AsL[(m + g + 8)*36 + kb + t]);
                al[2] = __float_as_uint(AsL[(m + g)*36 + kb + t + 4]);
                al[3] = __float_as_uint(AsL[(m + g + 8)*36 + kb + t + 4]);
                #pragma unroll
                for (int nt = 0; nt < 4; nt++) {
                    mma_tf32(acc[mt][nt], ah[0], ah[1], ah[2], ah[3], bh[nt][0], bh[nt][1]);
                    mma_tf32(acc[mt][nt], ah[0], ah[1], ah[2], ah[3], bl[nt][0], bl[nt][1]);
                    mma_tf32(acc[mt][nt], al[0], al[1], al[2], al[3], bh[nt][0], bh[nt][1]);
                }
            }
        }
        __syncthreads();
    }

    #pragma unroll
    for (int mt = 0; mt < MTILES; mt++) {
        #pragma unroll
        for (int nt = 0; nt < 4; nt++) {
            int r0 = warp_m + mt*16 + g;
            int col = warp_n + nt*8 + 2*t;
            float* d0 = Cg + (size_t)r0*ldc + col;
            float* d1 = d0 + 8*ldc;
            float c0 = acc[mt][nt][0], c1 = acc[mt][nt][1];
            float c2 = acc[mt][nt][2], c3 = acc[mt][nt][3];
            if (RESID) {
                const float* s0 = Rg + (size_t)r0*ldc + col;
                const float* s1 = s0 + 8*ldc;
                float2 t0 = *(const float2*)s0;
                float2 t1 = *(const float2*)s1;
                c0 += t0.x; c1 += t0.y; c2 += t1.x; c3 += t1.y;
            }
            *(float2*)d0 = make_float2(c0, c1);
            *(float2*)d1 = make_float2(c2, c3);
        }
    }
}

#define QKV_SMEM ((128*36*2 + 32*136*2) * 4)   // 71680 B
#define OUT_SMEM ((64*36*2 + 32*136*2) * 4)    // 53248 B

// ---------------- stage 2: QKV gemm (LN fused into A load) ----------------
__global__ void __launch_bounds__(256, 2)
gemm_qkv(const float* __restrict__ tok,
         const float* __restrict__ lnw, const float* __restrict__ lnb,
         const float* __restrict__ wq,
         const float* __restrict__ wk,
         const float* __restrict__ wv) {
    int m0 = blockIdx.x * 128;
    int n0 = blockIdx.y * 128;
    const float* Bsrc; int nb;
    if (n0 < 256)      { Bsrc = wq; nb = n0; }
    else if (n0 < 512) { Bsrc = wk; nb = n0 - 256; }
    else               { Bsrc = wv; nb = n0 - 512; }
    gemm_tc_body<128, 128, 128, 256, false, true>(
        tok + (size_t)m0*128, Bsrc + nb,
        g_y + (size_t)m0*768 + n0, nullptr, 768,
        g_mu + m0, g_rs + m0, lnw, lnb);
}

// ---------------- stage 4: output gemm + residual ----------------
__global__ void __launch_bounds__(256, 2)
gemm_out(const float* __restrict__ wo,
         const float* __restrict__ tok,
         float* __restrict__ out) {
    int m0 = blockIdx.x * 64;
    gemm_tc_body<64, 256, 256, 128, true, false>(
        g_ho + (size_t)m0*256, wo,
        out + (size_t)m0*128, tok + (size_t)m0*128, 128,
        nullptr, nullptr, nullptr, nullptr);
}

// ---------------- stage 3: banded differential attention (6-sigma band) ----------------
__global__ void __launch_bounds__(512, 1)
attn_kernel(const float* __restrict__ lq1, const float* __restrict__ lk1,
            const float* __restrict__ lq2, const float* __restrict__ lk2,
            const float* __restrict__ sigS, const float* __restrict__ sigN,
            const float* __restrict__ hnw,  const float* __restrict__ hnb) {
    extern __shared__ float sm[];
    float* Ksm = sm;
    float* Vsm = Ksm + KROWS*KLD;
    float* Qsm = Vsm + KROWS*64;
    u64*   Pb  = (u64*)(Qsm + QT*64);
    __shared__ float s_lam;

    int tid = threadIdx.x;
    int bh  = blockIdx.y;
    int b   = bh >> 2;
    int h   = bh & 3;
    int q0  = blockIdx.x * QT;

    float ss = fmaxf(sigS[0], 1.0f), sn = fmaxf(sigN[0], 1.0f);
    float c1 = -0.5f / (ss*ss);
    float c2 = -0.5f / (sn*sn);
    int Wn = (int)ceilf(6.0f * fmaxf(ss, sn)); if (Wn > W_MAX) Wn = W_MAX;
    int W1 = (int)ceilf(6.0f * ss);            if (W1 > W_MAX) W1 = W_MAX;

    int blo = q0 - Wn;          if (blo < 0) blo = 0;
    int bhi = q0 + QT - 1 + Wn; if (bhi > TT-1) bhi = TT-1;
    int nrows = bhi - blo + 1;

    const float* ybase = g_y + (size_t)(b*TT) * 768;

    for (int idx = tid; idx < nrows*64; idx += 512) {
        int r = idx >> 6, d = idx & 63;
        const float* row = ybase + (size_t)(blo + r)*768 + h*64;
        Ksm[r*KLD + d] = row[256 + d];
        float v = row[512 + d];
        int dd = (d < 32) ? (2*d) : (2*(d-32) + 1);
        Vsm[r*64 + dd] = v;
    }
    for (int idx = tid; idx < QT*64; idx += 512) {
        int r = idx >> 6, d = idx & 63;
        Qsm[idx] = ybase[(size_t)(q0 + r)*768 + h*64 + d];
    }
    if (tid == 0) {
        float d1 = 0.0f, d2 = 0.0f;
        #pragma unroll
        for (int i = 0; i < 32; i++) { d1 += lq1[i]*lk1[i]; d2 += lq2[i]*lk2[i]; }
        s_lam = __expf(d1) - __expf(d2) + LAMBDA_INIT;
    }
    __syncthreads();
    float lam = s_lam;

    int w = tid >> 5, lane = tid & 31;
    int i0 = q0 + w*QW;
    int jlo = i0 - Wn;           if (jlo < blo) jlo = blo;
    int jhi = i0 + QW - 1 + Wn;  if (jhi > bhi) jhi = bhi;
    int m1lo = i0 - W1, m1hi = i0 + QW - 1 + W1;

    u64* p1w = Pb + w*256;
    u64* p2w = p1w + 128;

    u64 o1x[4], o1y[4], o2x[4], o2y[4];
    float l1[QW], l2[QW];
    #pragma unroll
    for (int i = 0; i < 4; i++) { o1x[i]=0ull; o1y[i]=0ull; o2x[i]=0ull; o2y[i]=0ull; }
    #pragma unroll
    for (int q = 0; q < QW; q++) { l1[q] = 0.0f; l2[q] = 0.0f; }

    for (int jc = jlo; jc <= jhi; jc += 32) {
        bool doM1 = (jc <= m1hi) && (jc + 31 >= m1lo);
        int j = jc + lane;
        bool valid = (j <= jhi);
        int r = (valid ? j : jhi) - blo;
        const ulonglong2* kr = (const ulonglong2*)(Ksm + r*KLD);
        float relb = (float)(j - i0);

        u64 a2[QW];
        #pragma unroll
        for (int q = 0; q < QW; q++) a2[q] = 0ull;
        #pragma unroll
        for (int dc = 8; dc < 16; dc++) {
            ulonglong2 k2 = kr[dc];
            #pragma unroll
            for (int q = 0; q < QW; q++) {
                ulonglong2 q2 = *(const ulonglong2*)(Qsm + (w*QW + q)*64 + dc*4);
                a2[q] = f2fma(k2.x, q2.x, a2[q]);
                a2[q] = f2fma(k2.y, q2.y, a2[q]);
            }
        }
        float e2[QW];
        #pragma unroll
        for (int q = 0; q < QW; q++) {
            float rel = relb - (float)q, rr = rel*rel;
            float lo, hi; up2(a2[q], lo, hi);
            float s = (lo + hi)*SCALE + rr*c2;
            e2[q] = valid ? __expf(s) : 0.0f;
            l2[q] += e2[q];
        }
        ((ulonglong2*)p2w)[lane*2]     = make_ulonglong2(pk2(e2[0],e2[1]), pk2(e2[2],e2[3]));
        ((ulonglong2*)p2w)[lane*2 + 1] = make_ulonglong2(pk2(e2[4],e2[5]), pk2(e2[6],e2[7]));

        if (doM1) {
            u64 a1[QW];
            #pragma unroll
            for (int q = 0; q < QW; q++) a1[q] = 0ull;
            #pragma unroll
            for (int dc = 0; dc < 8; dc++) {
                ulonglong2 k2 = kr[dc];
                #pragma unroll
                for (int q = 0; q < QW; q++) {
                    ulonglong2 q2 = *(const ulonglong2*)(Qsm + (w*QW + q)*64 + dc*4);
                    a1[q] = f2fma(k2.x, q2.x, a1[q]);
                    a1[q] = f2fma(k2.y, q2.y, a1[q]);
                }
            }
            float e1[QW];
            #pragma unroll
            for (int q = 0; q < QW; q++) {
                float rel = relb - (float)q, rr = rel*rel;
                float lo, hi; up2(a1[q], lo, hi);
                float s = (lo + hi)*SCALE + rr*c1;
                e1[q] = valid ? __expf(s) : 0.0f;
                l1[q] += e1[q];
            }
            ((ulonglong2*)p1w)[lane*2]     = make_ulonglong2(pk2(e1[0],e1[1]), pk2(e1[2],e1[3]));
            ((ulonglong2*)p1w)[lane*2 + 1] = make_ulonglong2(pk2(e1[4],e1[5]), pk2(e1[6],e1[7]));
        }
        __syncwarp();

        int cnt = jhi - jc + 1; if (cnt > 32) cnt = 32;
        const float2* vb = (const float2*)(Vsm + (jc - blo)*64);
        const ulonglong2* P1 = (const ulonglong2*)p1w;
        const ulonglong2* P2 = (const ulonglong2*)p2w;
        if (doM1) {
            for (int jj = 0; jj < cnt; jj++) {
                float2 v = vb[jj*32 + lane];
                u64 vx = pk2(v.x, v.x), vy = pk2(v.y, v.y);
                ulonglong2 pa = P1[jj*2], pb = P1[jj*2 + 1];
                ulonglong2 qa = P2[jj*2], qb = P2[jj*2 + 1];
                o1x[0] = f2fma(pa.x, vx, o1x[0]);  o1y[0] = f2fma(pa.x, vy, o1y[0]);
                o1x[1] = f2fma(pa.y, vx, o1x[1]);  o1y[1] = f2fma(pa.y, vy, o1y[1]);
                o1x[2] = f2fma(pb.x, vx, o1x[2]);  o1y[2] = f2fma(pb.x, vy, o1y[2]);
                o1x[3] = f2fma(pb.y, vx, o1x[3]);  o1y[3] = f2fma(pb.y, vy, o1y[3]);
                o2x[0] = f2fma(qa.x, vx, o2x[0]);  o2y[0] = f2fma(qa.x, vy, o2y[0]);
                o2x[1] = f2fma(qa.y, vx, o2x[1]);  o2y[1] = f2fma(qa.y, vy, o2y[1]);
                o2x[2] = f2fma(qb.x, vx, o2x[2]);  o2y[2] = f2fma(qb.x, vy, o2y[2]);
                o2x[3] = f2fma(qb.y, vx, o2x[3]);  o2y[3] = f2fma(qb.y, vy, o2y[3]);
            }
        } else {
            for (int jj = 0; jj < cnt; jj++) {
                float2 v = vb[jj*32 + lane];
                u64 vx = pk2(v.x, v.x), vy = pk2(v.y, v.y);
                ulonglong2 qa = P2[jj*2], qb = P2[jj*2 + 1];
                o2x[0] = f2fma(qa.x, vx, o2x[0]);  o2y[0] = f2fma(qa.x, vy, o2y[0]);
                o2x[1] = f2fma(qa.y, vx, o2x[1]);  o2y[1] = f2fma(qa.y, vy, o2y[1]);
                o2x[2] = f2fma(qb.x, vx, o2x[2]);  o2y[2] = f2fma(qb.x, vy, o2y[2]);
                o2x[3] = f2fma(qb.y, vx, o2x[3]);  o2y[3] = f2fma(qb.y, vy, o2y[3]);
            }
        }
        __syncwarp();
    }

    float hw0 = hnw[lane], hw1 = hnw[lane+32];
    float hb0 = hnb[lane], hb1 = hnb[lane+32];
    float post = 1.0f - LAMBDA_INIT;
    #pragma unroll
    for (int qp = 0; qp < 4; qp++) {
        float x1a, x1b, y1a, y1b, x2a, x2b, y2a, y2b;
        up2(o1x[qp], x1a, x1b);  up2(o1y[qp], y1a, y1b);
        up2(o2x[qp], x2a, x2b);  up2(o2y[qp], y2a, y2b);
        #pragma unroll
        for (int sub = 0; sub < 2; sub++) {
            int q = qp*2 + sub;
            float x1 = sub ? x1b : x1a, y1 = sub ? y1b : y1a;
            float x2 = sub ? x2b : x2a, y2 = sub ? y2b : y2a;
            float L1 = warpsum(l1[q]);
            float L2 = warpsum(l2[q]);
            float il1 = 1.0f / L1;
            float il2 = lam  / L2;
            float ox = x1*il1 - x2*il2;
            float oy = y1*il1 - y2*il2;
            float s  = warpsum(ox + oy);
            float sq = warpsum(ox*ox + oy*oy);
            float mu  = s * (1.0f/64.0f);
            float var = sq * (1.0f/64.0f) - mu*mu;
            float rs  = rsqrtf(var + LN_EPS);
            float y0 = ((ox - mu)*rs*hw0 + hb0) * post;
            float y1o = ((oy - mu)*rs*hw1 + hb1) * post;
            int i = i0 + q;
            float* dst = g_ho + (size_t)(b*TT + i)*256 + h*64;
            dst[lane]      = y0;
            dst[lane + 32] = y1o;
        }
    }
}

// ---------------- launch ----------------
extern "C" void kernel_launch(void* const* d_in, const int* in_sizes, int n_in,
                              void* d_out, int out_size) {
    const float* tokens = (const float*)d_in[0];
    const float* ln_w   = (const float*)d_in[1];
    const float* ln_b   = (const float*)d_in[2];
    const float* wq     = (const float*)d_in[3];
    const float* wk     = (const float*)d_in[4];
    const float* wv     = (const float*)d_in[5];
    const float* wo     = (const float*)d_in[6];
    const float* lq1    = (const float*)d_in[7];
    const float* lk1    = (const float*)d_in[8];
    const float* lq2    = (const float*)d_in[9];
    const float* lk2    = (const float*)d_in[10];
    const float* sigS   = (const float*)d_in[11];
    const float* sigN   = (const float*)d_in[12];
    const float* hnw    = (const float*)d_in[13];
    const float* hnb    = (const float*)d_in[14];
    float* out = (float*)d_out;

    const size_t attn_smem = (size_t)(KROWS*KLD + KROWS*64 + QT*64) * sizeof(float)
                           + (size_t)NW * 256 * sizeof(u64);
    cudaFuncSetAttribute(attn_kernel, cudaFuncAttributeMaxDynamicSharedMemorySize, (int)attn_smem);
    cudaFuncSetAttribute(gemm_qkv, cudaFuncAttributeMaxDynamicSharedMemorySize, QKV_SMEM);
    cudaFuncSetAttribute(gemm_out, cudaFuncAttributeMaxDynamicSharedMemorySize, OUT_SMEM);

    ln_stats<<<NTOK/8, 256>>>(tokens);
    gemm_qkv<<<dim3(NTOK/128, 6), 256, QKV_SMEM>>>(tokens, ln_w, ln_b, wq, wk, wv);
    attn_kernel<<<dim3(TT/QT, BB*HH), 512, attn_smem>>>(lq1, lk1, lq2, lk2, sigS, sigN, hnw, hnb);
    gemm_out<<<NTOK/64, 256, OUT_SMEM>>>(wo, tokens, out);
}

// round 11
// speedup vs baseline: 2.2713x; 1.1436x over previous
#include <cuda_runtime.h>
#include <math.h>

// ---------------- problem constants ----------------
#define TT 2048
#define BB 8
#define DD 128
#define HH 4
#define NTOK (BB*TT)          // 16384
#define SCALE 0.17677669529663687f   // 1/sqrt(32)
#define LAMBDA_INIT 0.8f
#define LN_EPS 1e-5f

// banded attention config
#define W_MAX 80
#define QT 128
#define QW 8
#define NW 16
#define KROWS (QT + 2*W_MAX + 1)   // 289 (cap case)
#define KLD 68

typedef unsigned long long u64;
typedef unsigned int u32;

// ---------------- scratch ----------------
__device__ float g_mu[NTOK];
__device__ float g_rs[NTOK];
__device__ float g_y [NTOK*768];
__device__ float g_ho[NTOK*256];

// ---------------- helpers ----------------
__device__ __forceinline__ u64 pk2(float x, float y) {
    u64 r; asm("mov.b64 %0, {%1, %2};" : "=l"(r) : "f"(x), "f"(y)); return r;
}
__device__ __forceinline__ void up2(u64 v, float& x, float& y) {
    asm("mov.b64 {%0, %1}, %2;" : "=f"(x), "=f"(y) : "l"(v));
}
__device__ __forceinline__ u64 f2fma(u64 a, u64 b, u64 c) {
    u64 d; asm("fma.rn.f32x2 %0, %1, %2, %3;" : "=l"(d) : "l"(a), "l"(b), "l"(c));
    return d;
}
__device__ __forceinline__ float warpsum(float v) {
    #pragma unroll
    for (int o = 16; o; o >>= 1) v += __shfl_xor_sync(0xffffffffu, v, o);
    return v;
}
// pack two floats to bf16x2: 'upper' -> high 16 bits, 'lower' -> low 16 bits
__device__ __forceinline__ u32 bfpack(float upper, float lower) {
    u32 r; asm("cvt.rn.bf16x2.f32 %0, %1, %2;" : "=r"(r) : "f"(upper), "f"(lower));
    return r;
}
// split (x0=k, x1=k+1) into hi bf16x2 + lo (residual) bf16x2
__device__ __forceinline__ void bfsplit(float x0, float x1, u32& h, u32& l) {
    h = bfpack(x1, x0);
    float f0 = __uint_as_float(h << 16);
    float f1 = __uint_as_float(h & 0xFFFF0000u);
    l = bfpack(x1 - f1, x0 - f0);
}
__device__ __forceinline__ void mma_bf16(float* c, u32 a0, u32 a1, u32 a2, u32 a3,
                                         u32 b0, u32 b1) {
    asm volatile(
        "mma.sync.aligned.m16n8k16.row.col.f32.bf16.bf16.f32 "
        "{%0,%1,%2,%3}, {%4,%5,%6,%7}, {%8,%9}, {%0,%1,%2,%3};"
        : "+f"(c[0]), "+f"(c[1]), "+f"(c[2]), "+f"(c[3])
        : "r"(a0), "r"(a1), "r"(a2), "r"(a3), "r"(b0), "r"(b1));
}

// ---------------- stage 1: layernorm stats only ----------------
__global__ void ln_stats(const float* __restrict__ tok) {
    int t = blockIdx.x * 8 + (threadIdx.x >> 5);
    int lane = threadIdx.x & 31;
    const float4* src = (const float4*)(tok + (size_t)t * DD);
    float4 x = src[lane];
    float s  = x.x + x.y + x.z + x.w;
    float sq = x.x*x.x + x.y*x.y + x.z*x.z + x.w*x.w;
    s  = warpsum(s);
    sq = warpsum(sq);
    float mu  = s * (1.0f/128.0f);
    float var = sq * (1.0f/128.0f) - mu*mu;
    if (lane == 0) {
        g_mu[t] = mu;
        g_rs[t] = rsqrtf(var + LN_EPS);
    }
}

// ---------------- 3xBF16 TC GEMM (m16n8k16, hi/lo planes, A prefetch) ----------------
// A smem: u32 [MT][20]  (16 used = 32 k packed in pairs) hi + lo planes
// B smem: u32 [16][136] (128 n cols) hi + lo planes (pairs packed along k)
// Fragment banks: A 20g+t unique; B 8t+g unique -> conflict-free.
template<int MT, int KTOT, int LDA_G, int LDB_G, bool RESID, bool LNA>
__device__ __forceinline__ void gemm_tc_body(
    const float* __restrict__ Ag,
    const float* __restrict__ Bg,
    float* __restrict__ Cg,
    const float* __restrict__ Rg,
    int ldc,
    const float* __restrict__ mu_p,
    const float* __restrict__ rs_p,
    const float* __restrict__ lnw,
    const float* __restrict__ lnb)
{
    constexpr int MTILES = MT / 32;
    extern __shared__ __align__(16) float smg[];
    u32* AsH = (u32*)smg;            // MT*20
    u32* AsL = AsH + MT*20;
    u32* BsH = AsL + MT*20;          // 16*136
    u32* BsL = BsH + 16*136;

    int tid = threadIdx.x;
    int lane = tid & 31, wid = tid >> 5;
    int g = lane >> 2, t = lane & 3;
    int warp_m = (wid >> 2) * (MT/2);
    int warp_n = (wid & 3) * 32;

    float acc[MTILES][4][4];
    #pragma unroll
    for (int i = 0; i < MTILES; i++)
        #pragma unroll
        for (int j = 0; j < 4; j++)
            #pragma unroll
            for (int r = 0; r < 4; r++) acc[i][j][r] = 0.0f;

    constexpr int TPR = 256 / MT;
    constexpr int AC4 = 32 / TPR / 4;
    int a_row = tid / TPR;
    int a_c0  = (tid % TPR) * (32 / TPR);
    int b_kp  = tid >> 4;              // 0..15 (k-pair row)
    int b_n0  = (tid & 15) * 8;        // 0..120

    float a_mu = 0.0f, a_rs = 1.0f;
    if (LNA) { a_mu = mu_p[a_row]; a_rs = rs_p[a_row]; }

    // prefetch chunk 0 of A
    float4 aNext[AC4];
    #pragma unroll
    for (int i = 0; i < AC4; i++)
        aNext[i] = *(const float4*)&Ag[(size_t)a_row*LDA_G + a_c0 + i*4];

    for (int k0 = 0; k0 < KTOT; k0 += 32) {
        // A chunk: LN + bf16 split -> smem
        #pragma unroll
        for (int i = 0; i < AC4; i++) {
            int c = a_c0 + i*4;
            float4 a4 = aNext[i];
            if (LNA) {
                float4 w4 = *(const float4*)&lnw[k0 + c];
                float4 b4 = *(const float4*)&lnb[k0 + c];
                a4.x = (a4.x - a_mu) * a_rs * w4.x + b4.x;
                a4.y = (a4.y - a_mu) * a_rs * w4.y + b4.y;
                a4.z = (a4.z - a_mu) * a_rs * w4.z + b4.z;
                a4.w = (a4.w - a_mu) * a_rs * w4.w + b4.w;
            }
            u32 h01, l01, h23, l23;
            bfsplit(a4.x, a4.y, h01, l01);
            bfsplit(a4.z, a4.w, h23, l23);
            int cu = c >> 1;
            *(uint2*)&AsH[a_row*20 + cu] = make_uint2(h01, h23);
            *(uint2*)&AsL[a_row*20 + cu] = make_uint2(l01, l23);
        }
        // B chunk: two k-rows, pack pairs along k
        {
            const float* B0 = &Bg[(size_t)(k0 + 2*b_kp)*LDB_G + b_n0];
            float4 x0a = *(const float4*)B0;
            float4 x0b = *(const float4*)(B0 + 4);
            float4 x1a = *(const float4*)(B0 + LDB_G);
            float4 x1b = *(const float4*)(B0 + LDB_G + 4);
            u32 h[8], l[8];
            bfsplit(x0a.x, x1a.x, h[0], l[0]);
            bfsplit(x0a.y, x1a.y, h[1], l[1]);
            bfsplit(x0a.z, x1a.z, h[2], l[2]);
            bfsplit(x0a.w, x1a.w, h[3], l[3]);
            bfsplit(x0b.x, x1b.x, h[4], l[4]);
            bfsplit(x0b.y, x1b.y, h[5], l[5]);
            bfsplit(x0b.z, x1b.z, h[6], l[6]);
            bfsplit(x0b.w, x1b.w, h[7], l[7]);
            u32* dh = &BsH[b_kp*136 + b_n0];
            u32* dl = &BsL[b_kp*136 + b_n0];
            *(uint4*)dh       = make_uint4(h[0], h[1], h[2], h[3]);
            *(uint4*)(dh + 4) = make_uint4(h[4], h[5], h[6], h[7]);
            *(uint4*)dl       = make_uint4(l[0], l[1], l[2], l[3]);
            *(uint4*)(dl + 4) = make_uint4(l[4], l[5], l[6], l[7]);
        }
        __syncthreads();

        // prefetch next A chunk
        if (k0 + 32 < KTOT) {
            #pragma unroll
            for (int i = 0; i < AC4; i++)
                aNext[i] = *(const float4*)&Ag[(size_t)a_row*LDA_G + k0 + 32 + a_c0 + i*4];
        }

        #pragma unroll
        for (int kk = 0; kk < 2; kk++) {
            int kp = kk*8;
            u32 bh[4][2], bl[4][2];
            #pragma unroll
            for (int nt = 0; nt < 4; nt++) {
                int n = warp_n + nt*8 + g;
                bh[nt][0] = BsH[(kp + t)*136 + n];
                bh[nt][1] = BsH[(kp + t + 4)*136 + n];
                bl[nt][0] = BsL[(kp + t)*136 + n];
                bl[nt][1] = BsL[(kp + t + 4)*136 + n];
            }
            #pragma unroll
            for (int mt = 0; mt < MTILES; mt++) {
                int m = warp_m + mt*16;
                u32 ah[4], al[4];
                ah[0] = AsH[(m + g)*20 + kp + t];
                ah[1] = AsH[(m + g + 8)*20 + kp + t];
                ah[2] = AsH[(m + g)*20 + kp + t + 4];
                ah[3] = AsH[(m + g + 8)*20 + kp + t + 4];
                al[0] = AsL[(m + g)*20 + kp + t];
                al[1] = AsL[(m + g + 8)*20 + kp + t];
                al[2] = AsL[(m + g)*20 + kp + t + 4];
                al[3] = AsL[(m + g + 8)*20 + kp + t + 4];
                #pragma unroll
                for (int nt = 0; nt < 4; nt++) {
                    mma_bf16(acc[mt][nt], ah[0], ah[1], ah[2], ah[3], bh[nt][0], bh[nt][1]);
                    mma_bf16(acc[mt][nt], ah[0], ah[1], ah[2], ah[3], bl[nt][0], bl[nt][1]);
                    mma_bf16(acc[mt][nt], al[0], al[1], al[2], al[3], bh[nt][0], bh[nt][1]);
                }
            }
        }
        __syncthreads();
    }

    #pragma unroll
    for (int mt = 0; mt < MTILES; mt++) {
        #pragma unroll
        for (int nt = 0; nt < 4; nt++) {
            int r0 = warp_m + mt*16 + g;
            int col = warp_n + nt*8 + 2*t;
            float* d0 = Cg + (size_t)r0*ldc + col;
            float* d1 = d0 + 8*ldc;
            float c0 = acc[mt][nt][0], c1 = acc[mt][nt][1];
            float c2 = acc[mt][nt][2], c3 = acc[mt][nt][3];
            if (RESID) {
                const float* s0 = Rg + (size_t)r0*ldc + col;
                const float* s1 = s0 + 8*ldc;
                float2 t0 = *(const float2*)s0;
                float2 t1 = *(const float2*)s1;
                c0 += t0.x; c1 += t0.y; c2 += t1.x; c3 += t1.y;
            }
            *(float2*)d0 = make_float2(c0, c1);
            *(float2*)d1 = make_float2(c2, c3);
        }
    }
}

#define QKV_SMEM ((128*20*2 + 16*136*2) * 4)   // 37888 B
#define OUT_SMEM ((64*20*2 + 16*136*2) * 4)    // 27648 B

// ---------------- stage 2: QKV gemm (LN fused into A load) ----------------
__global__ void __launch_bounds__(256, 2)
gemm_qkv(const float* __restrict__ tok,
         const float* __restrict__ lnw, const float* __restrict__ lnb,
         const float* __restrict__ wq,
         const float* __restrict__ wk,
         const float* __restrict__ wv) {
    int m0 = blockIdx.x * 128;
    int n0 = blockIdx.y * 128;
    const float* Bsrc; int nb;
    if (n0 < 256)      { Bsrc = wq; nb = n0; }
    else if (n0 < 512) { Bsrc = wk; nb = n0 - 256; }
    else               { Bsrc = wv; nb = n0 - 512; }
    gemm_tc_body<128, 128, 128, 256, false, true>(
        tok + (size_t)m0*128, Bsrc + nb,
        g_y + (size_t)m0*768 + n0, nullptr, 768,
        g_mu + m0, g_rs + m0, lnw, lnb);
}

// ---------------- stage 4: output gemm + residual ----------------
__global__ void __launch_bounds__(256, 2)
gemm_out(const float* __restrict__ wo,
         const float* __restrict__ tok,
         float* __restrict__ out) {
    int m0 = blockIdx.x * 64;
    gemm_tc_body<64, 256, 256, 128, true, false>(
        g_ho + (size_t)m0*256, wo,
        out + (size_t)m0*128, tok + (size_t)m0*128, 128,
        nullptr, nullptr, nullptr, nullptr);
}

// ---------------- stage 3: banded differential attention (6-sigma, unchanged R10) ----------------
__global__ void __launch_bounds__(512, 1)
attn_kernel(const float* __restrict__ lq1, const float* __restrict__ lk1,
            const float* __restrict__ lq2, const float* __restrict__ lk2,
            const float* __restrict__ sigS, const float* __restrict__ sigN,
            const float* __restrict__ hnw,  const float* __restrict__ hnb) {
    extern __shared__ float sm[];
    float* Ksm = sm;
    float* Vsm = Ksm + KROWS*KLD;
    float* Qsm = Vsm + KROWS*64;
    u64*   Pb  = (u64*)(Qsm + QT*64);
    __shared__ float s_lam;

    int tid = threadIdx.x;
    int bh  = blockIdx.y;
    int b   = bh >> 2;
    int h   = bh & 3;
    int q0  = blockIdx.x * QT;

    float ss = fmaxf(sigS[0], 1.0f), sn = fmaxf(sigN[0], 1.0f);
    float c1 = -0.5f / (ss*ss);
    float c2 = -0.5f / (sn*sn);
    int Wn = (int)ceilf(6.0f * fmaxf(ss, sn)); if (Wn > W_MAX) Wn = W_MAX;
    int W1 = (int)ceilf(6.0f * ss);            if (W1 > W_MAX) W1 = W_MAX;

    int blo = q0 - Wn;          if (blo < 0) blo = 0;
    int bhi = q0 + QT - 1 + Wn; if (bhi > TT-1) bhi = TT-1;
    int nrows = bhi - blo + 1;

    const float* ybase = g_y + (size_t)(b*TT) * 768;

    for (int idx = tid; idx < nrows*64; idx += 512) {
        int r = idx >> 6, d = idx & 63;
        const float* row = ybase + (size_t)(blo + r)*768 + h*64;
        Ksm[r*KLD + d] = row[256 + d];
        float v = row[512 + d];
        int dd = (d < 32) ? (2*d) : (2*(d-32) + 1);
        Vsm[r*64 + dd] = v;
    }
    for (int idx = tid; idx < QT*64; idx += 512) {
        int r = idx >> 6, d = idx & 63;
        Qsm[idx] = ybase[(size_t)(q0 + r)*768 + h*64 + d];
    }
    if (tid == 0) {
        float d1 = 0.0f, d2 = 0.0f;
        #pragma unroll
        for (int i = 0; i < 32; i++) { d1 += lq1[i]*lk1[i]; d2 += lq2[i]*lk2[i]; }
        s_lam = __expf(d1) - __expf(d2) + LAMBDA_INIT;
    }
    __syncthreads();
    float lam = s_lam;

    int w = tid >> 5, lane = tid & 31;
    int i0 = q0 + w*QW;
    int jlo = i0 - Wn;           if (jlo < blo) jlo = blo;
    int jhi = i0 + QW - 1 + Wn;  if (jhi > bhi) jhi = bhi;
    int m1lo = i0 - W1, m1hi = i0 + QW - 1 + W1;

    u64* p1w = Pb + w*256;
    u64* p2w = p1w + 128;

    u64 o1x[4], o1y[4], o2x[4], o2y[4];
    float l1[QW], l2[QW];
    #pragma unroll
    for (int i = 0; i < 4; i++) { o1x[i]=0ull; o1y[i]=0ull; o2x[i]=0ull; o2y[i]=0ull; }
    #pragma unroll
    for (int q = 0; q < QW; q++) { l1[q] = 0.0f; l2[q] = 0.0f; }

    for (int jc = jlo; jc <= jhi; jc += 32) {
        bool doM1 = (jc <= m1hi) && (jc + 31 >= m1lo);
        int j = jc + lane;
        bool valid = (j <= jhi);
        int r = (valid ? j : jhi) - blo;
        const ulonglong2* kr = (const ulonglong2*)(Ksm + r*KLD);
        float relb = (float)(j - i0);

        u64 a2[QW];
        #pragma unroll
        for (int q = 0; q < QW; q++) a2[q] = 0ull;
        #pragma unroll
        for (int dc = 8; dc < 16; dc++) {
            ulonglong2 k2 = kr[dc];
            #pragma unroll
            for (int q = 0; q < QW; q++) {
                ulonglong2 q2 = *(const ulonglong2*)(Qsm + (w*QW + q)*64 + dc*4);
                a2[q] = f2fma(k2.x, q2.x, a2[q]);
                a2[q] = f2fma(k2.y, q2.y, a2[q]);
            }
        }
        float e2[QW];
        #pragma unroll
        for (int q = 0; q < QW; q++) {
            float rel = relb - (float)q, rr = rel*rel;
            float lo, hi; up2(a2[q], lo, hi);
            float s = (lo + hi)*SCALE + rr*c2;
            e2[q] = valid ? __expf(s) : 0.0f;
            l2[q] += e2[q];
        }
        ((ulonglong2*)p2w)[lane*2]     = make_ulonglong2(pk2(e2[0],e2[1]), pk2(e2[2],e2[3]));
        ((ulonglong2*)p2w)[lane*2 + 1] = make_ulonglong2(pk2(e2[4],e2[5]), pk2(e2[6],e2[7]));

        if (doM1) {
            u64 a1[QW];
            #pragma unroll
            for (int q = 0; q < QW; q++) a1[q] = 0ull;
            #pragma unroll
            for (int dc = 0; dc < 8; dc++) {
                ulonglong2 k2 = kr[dc];
                #pragma unroll
                for (int q = 0; q < QW; q++) {
                    ulonglong2 q2 = *(const ulonglong2*)(Qsm + (w*QW + q)*64 + dc*4);
                    a1[q] = f2fma(k2.x, q2.x, a1[q]);
                    a1[q] = f2fma(k2.y, q2.y, a1[q]);
                }
            }
            float e1[QW];
            #pragma unroll
            for (int q = 0; q < QW; q++) {
                float rel = relb - (float)q, rr = rel*rel;
                float lo, hi; up2(a1[q], lo, hi);
                float s = (lo + hi)*SCALE + rr*c1;
                e1[q] = valid ? __expf(s) : 0.0f;
                l1[q] += e1[q];
            }
            ((ulonglong2*)p1w)[lane*2]     = make_ulonglong2(pk2(e1[0],e1[1]), pk2(e1[2],e1[3]));
            ((ulonglong2*)p1w)[lane*2 + 1] = make_ulonglong2(pk2(e1[4],e1[5]), pk2(e1[6],e1[7]));
        }
        __syncwarp();

        int cnt = jhi - jc + 1; if (cnt > 32) cnt = 32;
        const float2* vb = (const float2*)(Vsm + (jc - blo)*64);
        const ulonglong2* P1 = (const ulonglong2*)p1w;
        const ulonglong2* P2 = (const ulonglong2*)p2w;
        if (doM1) {
            for (int jj = 0; jj < cnt; jj++) {
                float2 v = vb[jj*32 + lane];
                u64 vx = pk2(v.x, v.x), vy = pk2(v.y, v.y);
                ulonglong2 pa = P1[jj*2], pb = P1[jj*2 + 1];
                ulonglong2 qa = P2[jj*2], qb = P2[jj*2 + 1];
                o1x[0] = f2fma(pa.x, vx, o1x[0]);  o1y[0] = f2fma(pa.x, vy, o1y[0]);
                o1x[1] = f2fma(pa.y, vx, o1x[1]);  o1y[1] = f2fma(pa.y, vy, o1y[1]);
                o1x[2] = f2fma(pb.x, vx, o1x[2]);  o1y[2] = f2fma(pb.x, vy, o1y[2]);
                o1x[3] = f2fma(pb.y, vx, o1x[3]);  o1y[3] = f2fma(pb.y, vy, o1y[3]);
                o2x[0] = f2fma(qa.x, vx, o2x[0]);  o2y[0] = f2fma(qa.x, vy, o2y[0]);
                o2x[1] = f2fma(qa.y, vx, o2x[1]);  o2y[1] = f2fma(qa.y, vy, o2y[1]);
                o2x[2] = f2fma(qb.x, vx, o2x[2]);  o2y[2] = f2fma(qb.x, vy, o2y[2]);
                o2x[3] = f2fma(qb.y, vx, o2x[3]);  o2y[3] = f2fma(qb.y, vy, o2y[3]);
            }
        } else {
            for (int jj = 0; jj < cnt; jj++) {
                float2 v = vb[jj*32 + lane];
                u64 vx = pk2(v.x, v.x), vy = pk2(v.y, v.y);
                ulonglong2 qa = P2[jj*2], qb = P2[jj*2 + 1];
                o2x[0] = f2fma(qa.x, vx, o2x[0]);  o2y[0] = f2fma(qa.x, vy, o2y[0]);
                o2x[1] = f2fma(qa.y, vx, o2x[1]);  o2y[1] = f2fma(qa.y, vy, o2y[1]);
                o2x[2] = f2fma(qb.x, vx, o2x[2]);  o2y[2] = f2fma(qb.x, vy, o2y[2]);
                o2x[3] = f2fma(qb.y, vx, o2x[3]);  o2y[3] = f2fma(qb.y, vy, o2y[3]);
            }
        }
        __syncwarp();
    }

    float hw0 = hnw[lane], hw1 = hnw[lane+32];
    float hb0 = hnb[lane], hb1 = hnb[lane+32];
    float post = 1.0f - LAMBDA_INIT;
    #pragma unroll
    for (int qp = 0; qp < 4; qp++) {
        float x1a, x1b, y1a, y1b, x2a, x2b, y2a, y2b;
        up2(o1x[qp], x1a, x1b);  up2(o1y[qp], y1a, y1b);
        up2(o2x[qp], x2a, x2b);  up2(o2y[qp], y2a, y2b);
        #pragma unroll
        for (int sub = 0; sub < 2; sub++) {
            int q = qp*2 + sub;
            float x1 = sub ? x1b : x1a, y1 = sub ? y1b : y1a;
            float x2 = sub ? x2b : x2a, y2 = sub ? y2b : y2a;
            float L1 = warpsum(l1[q]);
            float L2 = warpsum(l2[q]);
            float il1 = 1.0f / L1;
            float il2 = lam  / L2;
            float ox = x1*il1 - x2*il2;
            float oy = y1*il1 - y2*il2;
            float s  = warpsum(ox + oy);
            float sq = warpsum(ox*ox + oy*oy);
            float mu  = s * (1.0f/64.0f);
            float var = sq * (1.0f/64.0f) - mu*mu;
            float rs  = rsqrtf(var + LN_EPS);
            float y0 = ((ox - mu)*rs*hw0 + hb0) * post;
            float y1o = ((oy - mu)*rs*hw1 + hb1) * post;
            int i = i0 + q;
            float* dst = g_ho + (size_t)(b*TT + i)*256 + h*64;
            dst[lane]      = y0;
            dst[lane + 32] = y1o;
        }
    }
}

// ---------------- launch ----------------
extern "C" void kernel_launch(void* const* d_in, const int* in_sizes, int n_in,
                              void* d_out, int out_size) {
    const float* tokens = (const float*)d_in[0];
    const float* ln_w   = (const float*)d_in[1];
    const float* ln_b   = (const float*)d_in[2];
    const float* wq     = (const float*)d_in[3];
    const float* wk     = (const float*)d_in[4];
    const float* wv     = (const float*)d_in[5];
    const float* wo     = (const float*)d_in[6];
    const float* lq1    = (const float*)d_in[7];
    const float* lk1    = (const float*)d_in[8];
    const float* lq2    = (const float*)d_in[9];
    const float* lk2    = (const float*)d_in[10];
    const float* sigS   = (const float*)d_in[11];
    const float* sigN   = (const float*)d_in[12];
    const float* hnw    = (const float*)d_in[13];
    const float* hnb    = (const float*)d_in[14];
    float* out = (float*)d_out;

    const size_t attn_smem = (size_t)(KROWS*KLD + KROWS*64 + QT*64) * sizeof(float)
                           + (size_t)NW * 256 * sizeof(u64);
    cudaFuncSetAttribute(attn_kernel, cudaFuncAttributeMaxDynamicSharedMemorySize, (int)attn_smem);
    cudaFuncSetAttribute(gemm_qkv, cudaFuncAttributeMaxDynamicSharedMemorySize, QKV_SMEM);
    cudaFuncSetAttribute(gemm_out, cudaFuncAttributeMaxDynamicSharedMemorySize, OUT_SMEM);

    ln_stats<<<NTOK/8, 256>>>(tokens);
    gemm_qkv<<<dim3(NTOK/128, 6), 256, QKV_SMEM>>>(tokens, ln_w, ln_b, wq, wk, wv);
    attn_kernel<<<dim3(TT/QT, BB*HH), 512, attn_smem>>>(lq1, lk1, lq2, lk2, sigS, sigN, hnw, hnb);
    gemm_out<<<NTOK/64, 256, OUT_SMEM>>>(wo, tokens, out);
}